// round 2
// baseline (speedup 1.0000x reference)
#include <cuda_runtime.h>
#include <cuda_bf16.h>
#include <math.h>

// Problem constants
#define B_  8
#define T_  1024
#define D_  512
#define FF_ 2048
#define H_  8
#define DH_ 64
#define BT_ (B_*T_)          // 8192 rows

// ---------------- scratch (device globals; no allocation allowed) ----------
__device__ float  g_qkv [3*BT_*D_];     // qkv projections (current layer)
__device__ float  g_ctx [BT_*D_];       // attention context
__device__ float  g_tmp [BT_*D_];       // generic D-wide temp
__device__ float  g_h1  [BT_*D_];       // post-attn LN output
__device__ float  g_ffn [BT_*FF_];      // FFN hidden
__device__ float  g_outv[BT_*D_];       // layer1 output
__device__ float  g_outl[BT_*D_];       // layer2 output
__device__ float  g_part[B_*H_*32*T_];  // per-(b,h,qtile) prob column sums
__device__ double g_wsum[B_*T_];        // reduced column sums (fp64)
__device__ float  g_wl  [B_*T_];        // softmax weights for pooling
__device__ int    g_ids [B_*T_];        // window id per frame
__device__ int    g_ws  [B_*T_];        // window start
__device__ int    g_we  [B_*T_];        // window end

// ---------------- generic fp32 GEMM: C(MxN) = A(MxK) @ B(KxN) --------------
#define GBM 64
#define GBN 64
#define GBK 16
template<bool RELU>
__global__ void gemm_kernel(const float* __restrict__ A, const float* __restrict__ Bm,
                            float* __restrict__ C, int M, int N, int K)
{
    __shared__ float As[GBK][GBM];
    __shared__ float Bs[GBK][GBN];
    int tid = threadIdx.x;               // 256 threads
    int bm = blockIdx.y * GBM;
    int bn = blockIdx.x * GBN;
    int tr = tid >> 4;                   // 0..15
    int tc = tid & 15;                   // 0..15
    float acc[4][4] = {};
    for (int k0 = 0; k0 < K; k0 += GBK) {
        #pragma unroll
        for (int idx = tid; idx < GBM*GBK; idx += 256) {
            int m = idx >> 4, k = idx & 15;
            As[k][m] = A[(size_t)(bm + m) * K + k0 + k];
        }
        #pragma unroll
        for (int idx = tid; idx < GBK*GBN; idx += 256) {
            int k = idx >> 6, n = idx & 63;
            Bs[k][n] = Bm[(size_t)(k0 + k) * N + bn + n];
        }
        __syncthreads();
        #pragma unroll
        for (int k = 0; k < GBK; k++) {
            float ra[4], rb[4];
            #pragma unroll
            for (int i = 0; i < 4; i++) ra[i] = As[k][tr*4 + i];
            #pragma unroll
            for (int j = 0; j < 4; j++) rb[j] = Bs[k][tc*4 + j];
            #pragma unroll
            for (int i = 0; i < 4; i++)
                #pragma unroll
                for (int j = 0; j < 4; j++)
                    acc[i][j] += ra[i] * rb[j];
        }
        __syncthreads();
    }
    #pragma unroll
    for (int i = 0; i < 4; i++)
        #pragma unroll
        for (int j = 0; j < 4; j++) {
            float v = acc[i][j];
            if (RELU) v = fmaxf(v, 0.f);
            C[(size_t)(bm + tr*4 + i) * N + bn + tc*4 + j] = v;
        }
}

// ---------------- attention (two-pass, flash-style), emits ctx + colsums ---
#define QT 32
#define KT 32
template<bool MASKED>
__global__ void attn_kernel(const float* __restrict__ qkv, const int* __restrict__ ids,
                            float* __restrict__ ctx, float* __restrict__ part)
{
    __shared__ float Qs[QT][DH_+1];
    __shared__ float Ks[KT][DH_+1];
    __shared__ float Vs[KT][DH_+1];
    __shared__ float Ps[QT][KT+1];
    __shared__ float ms[QT], ls[QT];
    __shared__ int   qid[QT], kid[KT];

    int qt = blockIdx.x, h = blockIdx.y, b = blockIdx.z;
    int tid = threadIdx.x;  // 256
    int q0 = qt * QT;
    const float scale = 0.125f;   // 1/sqrt(64)

    const float* Qp = qkv;
    const float* Kp = qkv + (size_t)BT_*D_;
    const float* Vp = qkv + (size_t)2*BT_*D_;

    for (int idx = tid; idx < QT*DH_; idx += 256) {
        int i = idx >> 6, e = idx & 63;
        Qs[i][e] = Qp[(size_t)(b*T_ + q0 + i) * D_ + h*DH_ + e];
    }
    if (MASKED && tid < QT) qid[tid] = ids[b*T_ + q0 + tid];
    if (tid < QT) { ms[tid] = -1e30f; ls[tid] = 0.f; }
    __syncthreads();

    // ---- pass 1: row max + exp-sum ----
    for (int kt = 0; kt < T_/KT; kt++) {
        int k0 = kt * KT;
        for (int idx = tid; idx < KT*DH_; idx += 256) {
            int j = idx >> 6, e = idx & 63;
            Ks[j][e] = Kp[(size_t)(b*T_ + k0 + j) * D_ + h*DH_ + e];
        }
        if (MASKED && tid < KT) kid[tid] = ids[b*T_ + k0 + tid];
        __syncthreads();
        for (int idx = tid; idx < QT*KT; idx += 256) {
            int i = idx / KT, j = idx % KT;
            float s;
            if (MASKED && qid[i] != kid[j]) {
                s = -1e30f;
            } else {
                s = 0.f;
                #pragma unroll
                for (int e = 0; e < DH_; e++) s += Qs[i][e] * Ks[j][e];
                s *= scale;
            }
            Ps[i][j] = s;
        }
        __syncthreads();
        if (tid < QT) {
            float m = ms[tid], l = ls[tid];
            float tm = -1e30f;
            #pragma unroll
            for (int j = 0; j < KT; j++) tm = fmaxf(tm, Ps[tid][j]);
            float nm = fmaxf(m, tm);
            float acc = 0.f;
            #pragma unroll
            for (int j = 0; j < KT; j++) {
                float s = Ps[tid][j];
                acc += (s < -1e29f) ? 0.f : expf(s - nm);
            }
            l = l * expf(m - nm) + acc;
            ms[tid] = nm; ls[tid] = l;
        }
        __syncthreads();
    }

    // ---- pass 2: probs -> ctx + colsums ----
    int r  = tid & 31;          // output row in tile
    int c0 = (tid >> 5) * 8;    // output col base
    float acc[8];
    #pragma unroll
    for (int u = 0; u < 8; u++) acc[u] = 0.f;

    for (int kt = 0; kt < T_/KT; kt++) {
        int k0 = kt * KT;
        for (int idx = tid; idx < KT*DH_; idx += 256) {
            int j = idx >> 6, e = idx & 63;
            size_t off = (size_t)(b*T_ + k0 + j) * D_ + h*DH_ + e;
            Ks[j][e] = Kp[off];
            Vs[j][e] = Vp[off];
        }
        if (MASKED && tid < KT) kid[tid] = ids[b*T_ + k0 + tid];
        __syncthreads();
        for (int idx = tid; idx < QT*KT; idx += 256) {
            int i = idx / KT, j = idx % KT;
            float p;
            if (MASKED && qid[i] != kid[j]) {
                p = 0.f;
            } else {
                float s = 0.f;
                #pragma unroll
                for (int e = 0; e < DH_; e++) s += Qs[i][e] * Ks[j][e];
                s *= scale;
                p = expf(s - ms[i]) / ls[i];
            }
            Ps[i][j] = p;
        }
        __syncthreads();
        if (tid < KT) {
            double cs = 0.0;     // fp64 colsum: window decisions are threshold-sensitive
            #pragma unroll
            for (int i = 0; i < QT; i++) cs += (double)Ps[i][tid];
            part[((size_t)((b*H_ + h)*32 + qt)) * T_ + k0 + tid] = (float)cs;
        }
        #pragma unroll
        for (int j = 0; j < KT; j++) {
            float p = Ps[r][j];
            #pragma unroll
            for (int u = 0; u < 8; u++) acc[u] += p * Vs[j][c0 + u];
        }
        __syncthreads();
    }
    #pragma unroll
    for (int u = 0; u < 8; u++)
        ctx[(size_t)(b*T_ + q0 + r) * D_ + h*DH_ + c0 + u] = acc[u];
}

// ---------------- deterministic fp64 reduction of prob column sums ---------
__global__ void reduce_part_kernel(const float* __restrict__ part, double* __restrict__ wsum)
{
    int idx = blockIdx.x * 256 + threadIdx.x;    // 0..8191
    int b = idx >> 10, j = idx & 1023;
    double s = 0.0;
    for (int g = 0; g < H_*32; g++)
        s += (double)part[((size_t)(b*H_*32 + g)) * T_ + j];
    wsum[idx] = s;
}

// ---------------- y = LayerNorm(x + r), row = 512 ---------------------------
__global__ void add_ln_kernel(const float* __restrict__ x, const float* __restrict__ r,
                              float* __restrict__ y)
{
    __shared__ float sm[256];
    int row = blockIdx.x, tid = threadIdx.x;
    size_t base = (size_t)row * D_;
    float v0 = x[base + tid]        + r[base + tid];
    float v1 = x[base + 256 + tid]  + r[base + 256 + tid];
    sm[tid] = v0 + v1; __syncthreads();
    for (int s = 128; s > 0; s >>= 1) { if (tid < s) sm[tid] += sm[tid + s]; __syncthreads(); }
    float mean = sm[0] * (1.f / D_); __syncthreads();
    float d0 = v0 - mean, d1 = v1 - mean;
    sm[tid] = d0*d0 + d1*d1; __syncthreads();
    for (int s = 128; s > 0; s >>= 1) { if (tid < s) sm[tid] += sm[tid + s]; __syncthreads(); }
    float var = sm[0] * (1.f / D_);
    float inv = 1.f / sqrtf(var + 1e-5f);
    y[base + tid]       = d0 * inv;
    y[base + 256 + tid] = d1 * inv;
}

// ---------------- window-id scan (exact replica of reference scan, fp64) ----
__global__ void scan_kernel(const double* __restrict__ wsum, int* __restrict__ ids,
                            int* __restrict__ ws, int* __restrict__ we)
{
    __shared__ double smn[256], smx[256];
    int b = blockIdx.x, tid = threadIdx.x;
    double mn = 1e300, mx = -1e300;
    for (int t = tid; t < T_; t += 256) {
        double v = wsum[b*T_ + t] * (1.0 / H_);
        mn = fmin(mn, v); mx = fmax(mx, v);
    }
    smn[tid] = mn; smx[tid] = mx; __syncthreads();
    for (int s = 128; s > 0; s >>= 1) {
        if (tid < s) { smn[tid] = fmin(smn[tid], smn[tid+s]); smx[tid] = fmax(smx[tid], smx[tid+s]); }
        __syncthreads();
    }
    for (int t = tid; t < T_; t += 256) { ws[b*T_ + t] = 0; we[b*T_ + t] = 0; }
    __syncthreads();
    if (tid == 0) {
        double MN = smn[0], MX = smx[0];
        double denom = MX - MN + 1e-8;
        double thr = MN + 0.5 * denom;      // v >= thr  <=>  normalized >= 0.5
        int cur = (wsum[b*T_ + 0] * (1.0 / H_)) >= thr ? 1 : 0;
        int start = 0, wid = 0;
        ids[b*T_ + 0] = 0;
        for (int t = 1; t < T_; t++) {
            int wt = (wsum[b*T_ + t] * (1.0 / H_)) >= thr ? 1 : 0;
            if (wt == cur) {
                // same run
            } else if (start + 1 == t) {
                cur = wt;                      // absorb length-1 run
            } else {
                cur = wt; start = t; wid++;    // close window
            }
            ids[b*T_ + t] = wid;
        }
        int prev = -1;
        for (int t = 0; t < T_; t++) {
            int w = ids[b*T_ + t];
            if (w != prev) { ws[b*T_ + w] = t; prev = w; }
            we[b*T_ + w] = t + 1;
        }
    }
}

// ---------------- wl = softmax_j(wsum/H) ------------------------------------
__global__ void wl_softmax_kernel(const double* __restrict__ wsum, float* __restrict__ wl)
{
    __shared__ float sm[256];
    int b = blockIdx.x, tid = threadIdx.x;
    float vals[4];
    float mx = -1e30f;
    #pragma unroll
    for (int i = 0; i < 4; i++) {
        vals[i] = (float)(wsum[b*T_ + tid + i*256] * (1.0 / H_));
        mx = fmaxf(mx, vals[i]);
    }
    sm[tid] = mx; __syncthreads();
    for (int s = 128; s > 0; s >>= 1) { if (tid < s) sm[tid] = fmaxf(sm[tid], sm[tid+s]); __syncthreads(); }
    float M = sm[0]; __syncthreads();
    float e[4], acc = 0.f;
    #pragma unroll
    for (int i = 0; i < 4; i++) { e[i] = expf(vals[i] - M); acc += e[i]; }
    sm[tid] = acc; __syncthreads();
    for (int s = 128; s > 0; s >>= 1) { if (tid < s) sm[tid] += sm[tid+s]; __syncthreads(); }
    float inv = 1.f / sm[0];
    #pragma unroll
    for (int i = 0; i < 4; i++) wl[b*T_ + tid + i*256] = e[i] * inv;
}

// ---------------- window-weighted pooling (deterministic gather) ------------
__global__ void word_tokens_kernel(const float* __restrict__ outl, const float* __restrict__ wl,
                                   const int* __restrict__ ws, const int* __restrict__ we,
                                   float* __restrict__ out)
{
    int w = blockIdx.x, b = blockIdx.y, tid = threadIdx.x;   // 128 threads
    int s = ws[b*T_ + w], e = we[b*T_ + w];
    float acc[4] = {0.f, 0.f, 0.f, 0.f};
    for (int t = s; t < e; t++) {
        float g = wl[b*T_ + t];
        const float* row = outl + (size_t)(b*T_ + t) * D_;
        #pragma unroll
        for (int u = 0; u < 4; u++) acc[u] += g * row[tid + u*128];
    }
    float* dst = out + ((size_t)(b*2*T_ + w)) * D_;
    #pragma unroll
    for (int u = 0; u < 4; u++) dst[tid + u*128] = acc[u];
}

// ---------------- copy x into second half of concat output ------------------
__global__ void copy_x_kernel(const float* __restrict__ x, float* __restrict__ out)
{
    int idx = blockIdx.x * 256 + threadIdx.x;    // 0 .. 8*1024*512-1
    int b = idx / (T_*D_);
    out[(size_t)idx + (size_t)(b + 1) * T_ * D_] = x[idx];
}

// ---------------- window_mapping output -------------------------------------
__global__ void winmap_kernel(const int* __restrict__ ids, float* __restrict__ out2)
{
    int idx = blockIdx.x * 256 + threadIdx.x;    // 0 .. 8*1024*1024-1
    int b = idx >> 20;
    int k = (idx >> 10) & 1023;
    int j = idx & 1023;
    out2[idx] = (ids[b*T_ + j] == k) ? 1.f : 0.f;
}

// ---------------- host launcher ---------------------------------------------
extern "C" void kernel_launch(void* const* d_in, const int* in_sizes, int n_in,
                              void* d_out, int out_size)
{
    const float* x       = (const float*)d_in[0];
    const float* v_qkv_w = (const float*)d_in[1];
    const float* v_out_w = (const float*)d_in[2];
    const float* v_w1    = (const float*)d_in[3];
    const float* v_w2    = (const float*)d_in[4];
    const float* l_qkv_w = (const float*)d_in[5];
    const float* l_out_w = (const float*)d_in[6];
    const float* l_w1    = (const float*)d_in[7];
    const float* l_w2    = (const float*)d_in[8];
    float* out = (float*)d_out;

    float *qkv, *ctx, *tmp, *h1, *ffn, *outv, *outl, *part, *wl;
    double *wsum;
    int *ids, *ws, *we;
    cudaGetSymbolAddress((void**)&qkv,  g_qkv);
    cudaGetSymbolAddress((void**)&ctx,  g_ctx);
    cudaGetSymbolAddress((void**)&tmp,  g_tmp);
    cudaGetSymbolAddress((void**)&h1,   g_h1);
    cudaGetSymbolAddress((void**)&ffn,  g_ffn);
    cudaGetSymbolAddress((void**)&outv, g_outv);
    cudaGetSymbolAddress((void**)&outl, g_outl);
    cudaGetSymbolAddress((void**)&part, g_part);
    cudaGetSymbolAddress((void**)&wsum, g_wsum);
    cudaGetSymbolAddress((void**)&wl,   g_wl);
    cudaGetSymbolAddress((void**)&ids,  g_ids);
    cudaGetSymbolAddress((void**)&ws,   g_ws);
    cudaGetSymbolAddress((void**)&we,   g_we);

    dim3 gD(D_/GBN, BT_/GBM);     // N=512 grids
    dim3 gF1(FF_/GBN, BT_/GBM);   // N=2048
    dim3 gAttn(T_/QT, H_, B_);

    // ===== layer 1 (vanilla) =====
    for (int c = 0; c < 3; c++)
        gemm_kernel<false><<<gD, 256>>>(x, v_qkv_w + (size_t)c*D_*D_, qkv + (size_t)c*BT_*D_, BT_, D_, D_);
    attn_kernel<false><<<gAttn, 256>>>(qkv, nullptr, ctx, part);
    reduce_part_kernel<<<(B_*T_)/256, 256>>>(part, wsum);
    gemm_kernel<false><<<gD, 256>>>(ctx, v_out_w, tmp, BT_, D_, D_);
    add_ln_kernel<<<BT_, 256>>>(x, tmp, h1);
    gemm_kernel<true ><<<gF1, 256>>>(h1, v_w1, ffn, BT_, FF_, D_);
    gemm_kernel<false><<<gD, 256>>>(ffn, v_w2, tmp, BT_, D_, FF_);
    add_ln_kernel<<<BT_, 256>>>(h1, tmp, outv);

    // ===== dynamic window mask =====
    scan_kernel<<<B_, 256>>>(wsum, ids, ws, we);

    // ===== layer 2 (masked) =====
    for (int c = 0; c < 3; c++)
        gemm_kernel<false><<<gD, 256>>>(outv, l_qkv_w + (size_t)c*D_*D_, qkv + (size_t)c*BT_*D_, BT_, D_, D_);
    attn_kernel<true><<<gAttn, 256>>>(qkv, ids, ctx, part);
    reduce_part_kernel<<<(B_*T_)/256, 256>>>(part, wsum);
    gemm_kernel<false><<<gD, 256>>>(ctx, l_out_w, tmp, BT_, D_, D_);
    add_ln_kernel<<<BT_, 256>>>(outv, tmp, h1);
    gemm_kernel<true ><<<gF1, 256>>>(h1, l_w1, ffn, BT_, FF_, D_);
    gemm_kernel<false><<<gD, 256>>>(ffn, l_w2, tmp, BT_, D_, FF_);
    add_ln_kernel<<<BT_, 256>>>(h1, tmp, outl);

    // ===== outputs =====
    wl_softmax_kernel<<<B_, 256>>>(wsum, wl);
    word_tokens_kernel<<<dim3(T_, B_), 128>>>(outl, wl, ws, we, out);
    copy_x_kernel<<<(B_*T_*D_)/256, 256>>>(x, out);
    winmap_kernel<<<(B_*T_*T_)/256, 256>>>(ids, out + (size_t)B_*2*T_*D_);
}

// round 3
// speedup vs baseline: 1.7640x; 1.7640x over previous
#include <cuda_runtime.h>
#include <cuda_bf16.h>
#include <math.h>

// Problem constants
#define B_  8
#define T_  1024
#define D_  512
#define FF_ 2048
#define H_  8
#define DH_ 64
#define BT_ (B_*T_)          // 8192 rows

// ---------------- scratch (device globals; no allocation allowed) ----------
__device__ float  g_qkv [3*BT_*D_];
__device__ float  g_ctx [BT_*D_];
__device__ float  g_tmp [BT_*D_];
__device__ float  g_h1  [BT_*D_];
__device__ float  g_ffn [BT_*FF_];
__device__ float  g_outv[BT_*D_];
__device__ float  g_outl[BT_*D_];
__device__ float  g_part[B_*H_*16*T_];  // per-(b,h,qtile64) prob column sums
__device__ double g_wsum[B_*T_];
__device__ float  g_wl  [B_*T_];
__device__ int    g_ids [B_*T_];
__device__ int    g_ws  [B_*T_];
__device__ int    g_we  [B_*T_];

// ---------------- f32x2 helpers --------------------------------------------
__device__ __forceinline__ unsigned long long pack_dup(float a) {
    unsigned long long r;
    asm("mov.b64 %0, {%1, %1};" : "=l"(r) : "f"(a));
    return r;
}
__device__ __forceinline__ void fma2(unsigned long long& d, unsigned long long a, unsigned long long b) {
    asm("fma.rn.f32x2 %0, %1, %2, %0;" : "+l"(d) : "l"(a), "l"(b));
}
__device__ __forceinline__ float2 unpack2(unsigned long long v) {
    float2 r;
    asm("mov.b64 {%0, %1}, %2;" : "=f"(r.x), "=f"(r.y) : "l"(v));
    return r;
}

// ---------------- fp32 GEMM v2: 128x128x8, 8x8 microtile, f32x2 ------------
#define TM 128
#define TN 128
#define TK 8
template<bool RELU>
__global__ __launch_bounds__(256)
void gemm2_kernel(const float* __restrict__ A, const float* __restrict__ Bsrc,
                  float* __restrict__ Csrc, int M, int N, int K,
                  long long bz_stride, long long cz_stride)
{
    const float* Bm = Bsrc + (long long)blockIdx.z * bz_stride;
    float*       C  = Csrc + (long long)blockIdx.z * cz_stride;

    __shared__ float As[2][TK][TM];
    __shared__ float Bs[2][TK][TN];
    int tid = threadIdx.x;
    int bm = blockIdx.y * TM, bn = blockIdx.x * TN;
    int tr = tid >> 4, tc = tid & 15;            // 16x16 thread grid
    int arow = tid >> 1, ak = (tid & 1) * 4;     // A loader: row, k-quad
    int bk = tid >> 5, bn4 = (tid & 31) * 4;     // B loader: k, n-quad

    unsigned long long acc[8][4];
    #pragma unroll
    for (int i = 0; i < 8; i++)
        #pragma unroll
        for (int j = 0; j < 4; j++) acc[i][j] = 0ULL;

    // preload tile 0
    float4 av = *(const float4*)&A[(size_t)(bm + arow) * K + ak];
    float4 bv = *(const float4*)&Bm[(size_t)bk * N + bn + bn4];
    As[0][ak+0][arow] = av.x; As[0][ak+1][arow] = av.y;
    As[0][ak+2][arow] = av.z; As[0][ak+3][arow] = av.w;
    *(float4*)&Bs[0][bk][bn4] = bv;
    __syncthreads();

    int nkt = K / TK;
    int buf = 0;
    for (int kt = 0; kt < nkt; kt++) {
        if (kt + 1 < nkt) {
            int k0 = (kt + 1) * TK;
            av = *(const float4*)&A[(size_t)(bm + arow) * K + k0 + ak];
            bv = *(const float4*)&Bm[(size_t)(k0 + bk) * N + bn + bn4];
        }
        #pragma unroll
        for (int k = 0; k < TK; k++) {
            float a[8];
            *(float4*)&a[0] = *(float4*)&As[buf][k][tr*8];
            *(float4*)&a[4] = *(float4*)&As[buf][k][tr*8 + 4];
            unsigned long long bb[4];
            *(float4*)&bb[0] = *(float4*)&Bs[buf][k][tc*8];
            *(float4*)&bb[2] = *(float4*)&Bs[buf][k][tc*8 + 4];
            #pragma unroll
            for (int i = 0; i < 8; i++) {
                unsigned long long aa = pack_dup(a[i]);
                #pragma unroll
                for (int j = 0; j < 4; j++) fma2(acc[i][j], aa, bb[j]);
            }
        }
        if (kt + 1 < nkt) {
            int nb = buf ^ 1;
            As[nb][ak+0][arow] = av.x; As[nb][ak+1][arow] = av.y;
            As[nb][ak+2][arow] = av.z; As[nb][ak+3][arow] = av.w;
            *(float4*)&Bs[nb][bk][bn4] = bv;
        }
        __syncthreads();
        buf ^= 1;
    }
    #pragma unroll
    for (int i = 0; i < 8; i++) {
        float vals[8];
        #pragma unroll
        for (int j = 0; j < 4; j++) {
            float2 p = unpack2(acc[i][j]);
            vals[2*j] = p.x; vals[2*j+1] = p.y;
        }
        if (RELU) {
            #pragma unroll
            for (int j = 0; j < 8; j++) vals[j] = fmaxf(vals[j], 0.f);
        }
        size_t ro = (size_t)(bm + tr*8 + i) * N + bn + tc*8;
        *(float4*)&C[ro]     = *(float4*)&vals[0];
        *(float4*)&C[ro + 4] = *(float4*)&vals[4];
    }
}

// ---------------- attention v2: 64x64 tiles, 4x4 microtiles, f32x2 ----------
#define AQT 64
#define AKT 64
#define QS  68   // padded row stride (floats), multiple of 4 for float4

template<bool MASKED>
__global__ __launch_bounds__(256)
void attn2_kernel(const float* __restrict__ qkv, const int* __restrict__ ids,
                  float* __restrict__ ctx, float* __restrict__ part)
{
    extern __shared__ float smf[];
    float* Qts = smf;                  // [64][QS] transposed Qts[e][i]
    float* Kts = Qts + 64*QS;          // [64][QS] transposed Kts[e][j]
    float* Vs  = Kts + 64*QS;          // [64][QS] natural Vs[j][c]
    float* Pt  = Vs  + 64*QS;          // [64][QS] Pt[j][i]
    float* ms  = Pt  + 64*QS;          // [64]
    float* ls  = ms + 64;              // [64]
    int*   qid = (int*)(ls + 64);      // [64]
    int*   kid = qid + 64;             // [64]

    int qt = blockIdx.x, h = blockIdx.y, b = blockIdx.z;
    int tid = threadIdx.x;  // 256
    int q0 = qt * AQT;
    const float scale = 0.125f;

    const float* Qp = qkv;
    const float* Kp = qkv + (size_t)BT_*D_;
    const float* Vp = qkv + (size_t)2*BT_*D_;

    int ti4 = (tid >> 4) * 4;   // micro rows
    int tj4 = (tid & 15) * 4;   // micro cols
    int lrow = tid >> 2;        // loader: row 0..63
    int le0  = (tid & 3) * 16;  // loader: 16 e's

    // load Q transposed + qid
    {
        const float* src = Qp + (size_t)(b*T_ + q0 + lrow) * D_ + h*DH_ + le0;
        #pragma unroll
        for (int u = 0; u < 4; u++) {
            float4 v = *(const float4*)(src + u*4);
            Qts[(le0 + u*4 + 0)*QS + lrow] = v.x;
            Qts[(le0 + u*4 + 1)*QS + lrow] = v.y;
            Qts[(le0 + u*4 + 2)*QS + lrow] = v.z;
            Qts[(le0 + u*4 + 3)*QS + lrow] = v.w;
        }
        if (MASKED && tid < 64) qid[tid] = ids[b*T_ + q0 + tid];
    }
    __syncthreads();
    int qid0 = 0, qidL = 0;
    if (MASKED) { qid0 = qid[0]; qidL = qid[63]; }

    // ================= pass 1: running max + expsum per row =================
    float m = -1e30f, l = 0.f;
    int r = tid >> 2, seg = tid & 3;  // reduction mapping: 4 threads per row

    for (int kt = 0; kt < T_/AKT; kt++) {
        int k0 = kt * AKT;
        if (MASKED && tid < 64) kid[tid] = ids[b*T_ + k0 + tid];
        __syncthreads();
        if (MASKED) {
            if (kid[63] < qid0 || qidL < kid[0]) continue;   // uniform skip
        }
        // load K transposed
        {
            const float* src = Kp + (size_t)(b*T_ + k0 + lrow) * D_ + h*DH_ + le0;
            #pragma unroll
            for (int u = 0; u < 4; u++) {
                float4 v = *(const float4*)(src + u*4);
                Kts[(le0 + u*4 + 0)*QS + lrow] = v.x;
                Kts[(le0 + u*4 + 1)*QS + lrow] = v.y;
                Kts[(le0 + u*4 + 2)*QS + lrow] = v.z;
                Kts[(le0 + u*4 + 3)*QS + lrow] = v.w;
            }
        }
        __syncthreads();
        // score micro-GEMM: 4x4 per thread over e=0..63
        unsigned long long sacc[4][2];
        #pragma unroll
        for (int i = 0; i < 4; i++) { sacc[i][0] = 0ULL; sacc[i][1] = 0ULL; }
        for (int e = 0; e < 64; e++) {
            float4 qa = *(const float4*)&Qts[e*QS + ti4];
            unsigned long long bb[2];
            *(float4*)&bb[0] = *(const float4*)&Kts[e*QS + tj4];
            float aq[4] = {qa.x, qa.y, qa.z, qa.w};
            #pragma unroll
            for (int i = 0; i < 4; i++) {
                unsigned long long aa = pack_dup(aq[i]);
                fma2(sacc[i][0], aa, bb[0]);
                fma2(sacc[i][1], aa, bb[1]);
            }
        }
        #pragma unroll
        for (int ii = 0; ii < 4; ii++) {
            float2 p0 = unpack2(sacc[ii][0]);
            float2 p1 = unpack2(sacc[ii][1]);
            float sv[4] = {p0.x, p0.y, p1.x, p1.y};
            #pragma unroll
            for (int jj = 0; jj < 4; jj++) {
                float s = sv[jj] * scale;
                if (MASKED && qid[ti4 + ii] != kid[tj4 + jj]) s = -1e30f;
                Pt[(tj4 + jj)*QS + ti4 + ii] = s;
            }
        }
        __syncthreads();
        // per-row online max/expsum (4 threads per row, quad shuffle)
        {
            float sv[16]; float tm = -1e30f;
            #pragma unroll
            for (int it = 0; it < 16; it++) {
                sv[it] = Pt[(seg*16 + it)*QS + r];
                tm = fmaxf(tm, sv[it]);
            }
            tm = fmaxf(tm, __shfl_xor_sync(0xffffffffu, tm, 1));
            tm = fmaxf(tm, __shfl_xor_sync(0xffffffffu, tm, 2));
            float nm = fmaxf(m, tm);
            float es = 0.f;
            #pragma unroll
            for (int it = 0; it < 16; it++) es += expf(sv[it] - nm);
            es += __shfl_xor_sync(0xffffffffu, es, 1);
            es += __shfl_xor_sync(0xffffffffu, es, 2);
            l = l * expf(m - nm) + es;
            m = nm;
        }
        // next-iteration top sync protects Pt/Kts reuse
    }
    __syncthreads();
    if (seg == 0) { ms[r] = m; ls[r] = l; }
    __syncthreads();

    // ================= pass 2: probs -> colsums + PV ========================
    unsigned long long pacc[4][2];
    #pragma unroll
    for (int i = 0; i < 4; i++) { pacc[i][0] = 0ULL; pacc[i][1] = 0ULL; }

    for (int kt = 0; kt < T_/AKT; kt++) {
        int k0 = kt * AKT;
        if (MASKED && tid < 64) kid[tid] = ids[b*T_ + k0 + tid];
        __syncthreads();
        if (MASKED) {
            if (kid[63] < qid0 || qidL < kid[0]) {
                if (tid < 64)
                    part[((size_t)((b*H_ + h)*16 + qt))*T_ + k0 + tid] = 0.f;
                continue;
            }
        }
        // load K transposed + V natural
        {
            const float* ksrc = Kp + (size_t)(b*T_ + k0 + lrow) * D_ + h*DH_ + le0;
            #pragma unroll
            for (int u = 0; u < 4; u++) {
                float4 v = *(const float4*)(ksrc + u*4);
                Kts[(le0 + u*4 + 0)*QS + lrow] = v.x;
                Kts[(le0 + u*4 + 1)*QS + lrow] = v.y;
                Kts[(le0 + u*4 + 2)*QS + lrow] = v.z;
                Kts[(le0 + u*4 + 3)*QS + lrow] = v.w;
            }
            const float* vsrc = Vp + (size_t)(b*T_ + k0 + lrow) * D_ + h*DH_ + le0;
            #pragma unroll
            for (int u = 0; u < 4; u++)
                *(float4*)&Vs[lrow*QS + le0 + u*4] = *(const float4*)(vsrc + u*4);
        }
        __syncthreads();
        // recompute scores
        unsigned long long sacc[4][2];
        #pragma unroll
        for (int i = 0; i < 4; i++) { sacc[i][0] = 0ULL; sacc[i][1] = 0ULL; }
        for (int e = 0; e < 64; e++) {
            float4 qa = *(const float4*)&Qts[e*QS + ti4];
            unsigned long long bb[2];
            *(float4*)&bb[0] = *(const float4*)&Kts[e*QS + tj4];
            float aq[4] = {qa.x, qa.y, qa.z, qa.w};
            #pragma unroll
            for (int i = 0; i < 4; i++) {
                unsigned long long aa = pack_dup(aq[i]);
                fma2(sacc[i][0], aa, bb[0]);
                fma2(sacc[i][1], aa, bb[1]);
            }
        }
        #pragma unroll
        for (int ii = 0; ii < 4; ii++) {
            float2 p0 = unpack2(sacc[ii][0]);
            float2 p1 = unpack2(sacc[ii][1]);
            float sv[4] = {p0.x, p0.y, p1.x, p1.y};
            float mi = ms[ti4 + ii], li = ls[ti4 + ii];
            #pragma unroll
            for (int jj = 0; jj < 4; jj++) {
                float p;
                if (MASKED && qid[ti4 + ii] != kid[tj4 + jj]) p = 0.f;
                else p = expf(sv[jj] * scale - mi) / li;
                Pt[(tj4 + jj)*QS + ti4 + ii] = p;
            }
        }
        __syncthreads();
        // fp64 column sums (threshold-critical path)
        if (tid < 64) {
            double cs = 0.0;
            #pragma unroll
            for (int i = 0; i < 64; i++) cs += (double)Pt[tid*QS + i];
            part[((size_t)((b*H_ + h)*16 + qt))*T_ + k0 + tid] = (float)cs;
        }
        // PV micro-GEMM: rows i=ti4.., cols c=tj4.., inner j=0..63
        for (int j = 0; j < 64; j++) {
            float4 pa = *(const float4*)&Pt[j*QS + ti4];
            unsigned long long bb[2];
            *(float4*)&bb[0] = *(const float4*)&Vs[j*QS + tj4];
            float ap[4] = {pa.x, pa.y, pa.z, pa.w};
            #pragma unroll
            for (int i = 0; i < 4; i++) {
                unsigned long long aa = pack_dup(ap[i]);
                fma2(pacc[i][0], aa, bb[0]);
                fma2(pacc[i][1], aa, bb[1]);
            }
        }
        // next-iteration top sync protects Pt/Kts/Vs
    }
    // write ctx
    #pragma unroll
    for (int ii = 0; ii < 4; ii++) {
        float2 c0 = unpack2(pacc[ii][0]);
        float2 c1 = unpack2(pacc[ii][1]);
        float4 v = make_float4(c0.x, c0.y, c1.x, c1.y);
        *(float4*)&ctx[(size_t)(b*T_ + q0 + ti4 + ii)*D_ + h*DH_ + tj4] = v;
    }
}

// ---------------- deterministic fp64 reduction of prob column sums ---------
__global__ void reduce_part_kernel(const float* __restrict__ part, double* __restrict__ wsum)
{
    int idx = blockIdx.x * 256 + threadIdx.x;    // 0..8191
    int b = idx >> 10, j = idx & 1023;
    double s = 0.0;
    for (int g = 0; g < H_*16; g++)
        s += (double)part[((size_t)(b*H_*16 + g)) * T_ + j];
    wsum[idx] = s;
}

// ---------------- y = LayerNorm(x + r), row = 512 ---------------------------
__global__ void add_ln_kernel(const float* __restrict__ x, const float* __restrict__ r,
                              float* __restrict__ y)
{
    __shared__ float sm[256];
    int row = blockIdx.x, tid = threadIdx.x;
    size_t base = (size_t)row * D_;
    float v0 = x[base + tid]        + r[base + tid];
    float v1 = x[base + 256 + tid]  + r[base + 256 + tid];
    sm[tid] = v0 + v1; __syncthreads();
    for (int s = 128; s > 0; s >>= 1) { if (tid < s) sm[tid] += sm[tid + s]; __syncthreads(); }
    float mean = sm[0] * (1.f / D_); __syncthreads();
    float d0 = v0 - mean, d1 = v1 - mean;
    sm[tid] = d0*d0 + d1*d1; __syncthreads();
    for (int s = 128; s > 0; s >>= 1) { if (tid < s) sm[tid] += sm[tid + s]; __syncthreads(); }
    float var = sm[0] * (1.f / D_);
    float inv = 1.f / sqrtf(var + 1e-5f);
    y[base + tid]       = d0 * inv;
    y[base + 256 + tid] = d1 * inv;
}

// ---------------- window-id scan (exact replica of reference scan, fp64) ----
__global__ void scan_kernel(const double* __restrict__ wsum, int* __restrict__ ids,
                            int* __restrict__ ws, int* __restrict__ we)
{
    __shared__ double smn[256], smx[256];
    int b = blockIdx.x, tid = threadIdx.x;
    double mn = 1e300, mx = -1e300;
    for (int t = tid; t < T_; t += 256) {
        double v = wsum[b*T_ + t] * (1.0 / H_);
        mn = fmin(mn, v); mx = fmax(mx, v);
    }
    smn[tid] = mn; smx[tid] = mx; __syncthreads();
    for (int s = 128; s > 0; s >>= 1) {
        if (tid < s) { smn[tid] = fmin(smn[tid], smn[tid+s]); smx[tid] = fmax(smx[tid], smx[tid+s]); }
        __syncthreads();
    }
    for (int t = tid; t < T_; t += 256) { ws[b*T_ + t] = 0; we[b*T_ + t] = 0; }
    __syncthreads();
    if (tid == 0) {
        double MN = smn[0], MX = smx[0];
        double denom = MX - MN + 1e-8;
        double thr = MN + 0.5 * denom;
        int cur = (wsum[b*T_ + 0] * (1.0 / H_)) >= thr ? 1 : 0;
        int start = 0, wid = 0;
        ids[b*T_ + 0] = 0;
        for (int t = 1; t < T_; t++) {
            int wt = (wsum[b*T_ + t] * (1.0 / H_)) >= thr ? 1 : 0;
            if (wt == cur) {
            } else if (start + 1 == t) {
                cur = wt;
            } else {
                cur = wt; start = t; wid++;
            }
            ids[b*T_ + t] = wid;
        }
        int prev = -1;
        for (int t = 0; t < T_; t++) {
            int w = ids[b*T_ + t];
            if (w != prev) { ws[b*T_ + w] = t; prev = w; }
            we[b*T_ + w] = t + 1;
        }
    }
}

// ---------------- wl = softmax_j(wsum/H) ------------------------------------
__global__ void wl_softmax_kernel(const double* __restrict__ wsum, float* __restrict__ wl)
{
    __shared__ float sm[256];
    int b = blockIdx.x, tid = threadIdx.x;
    float vals[4];
    float mx = -1e30f;
    #pragma unroll
    for (int i = 0; i < 4; i++) {
        vals[i] = (float)(wsum[b*T_ + tid + i*256] * (1.0 / H_));
        mx = fmaxf(mx, vals[i]);
    }
    sm[tid] = mx; __syncthreads();
    for (int s = 128; s > 0; s >>= 1) { if (tid < s) sm[tid] = fmaxf(sm[tid], sm[tid+s]); __syncthreads(); }
    float M = sm[0]; __syncthreads();
    float e[4], acc = 0.f;
    #pragma unroll
    for (int i = 0; i < 4; i++) { e[i] = expf(vals[i] - M); acc += e[i]; }
    sm[tid] = acc; __syncthreads();
    for (int s = 128; s > 0; s >>= 1) { if (tid < s) sm[tid] += sm[tid+s]; __syncthreads(); }
    float inv = 1.f / sm[0];
    #pragma unroll
    for (int i = 0; i < 4; i++) wl[b*T_ + tid + i*256] = e[i] * inv;
}

// ---------------- window-weighted pooling (deterministic gather) ------------
__global__ void word_tokens_kernel(const float* __restrict__ outl, const float* __restrict__ wl,
                                   const int* __restrict__ ws, const int* __restrict__ we,
                                   float* __restrict__ out)
{
    int w = blockIdx.x, b = blockIdx.y, tid = threadIdx.x;   // 128 threads
    int s = ws[b*T_ + w], e = we[b*T_ + w];
    float acc[4] = {0.f, 0.f, 0.f, 0.f};
    for (int t = s; t < e; t++) {
        float g = wl[b*T_ + t];
        const float* row = outl + (size_t)(b*T_ + t) * D_;
        #pragma unroll
        for (int u = 0; u < 4; u++) acc[u] += g * row[tid + u*128];
    }
    float* dst = out + ((size_t)(b*2*T_ + w)) * D_;
    #pragma unroll
    for (int u = 0; u < 4; u++) dst[tid + u*128] = acc[u];
}

// ---------------- copy x into second half of concat output ------------------
__global__ void copy_x_kernel(const float* __restrict__ x, float* __restrict__ out)
{
    int idx = blockIdx.x * 256 + threadIdx.x;    // float4 index
    int b = (idx * 4) / (T_*D_);
    float4 v = *(const float4*)&x[(size_t)idx * 4];
    *(float4*)&out[(size_t)idx * 4 + (size_t)(b + 1) * T_ * D_] = v;
}

// ---------------- window_mapping output -------------------------------------
__global__ void winmap_kernel(const int* __restrict__ ids, float* __restrict__ out2)
{
    int idx = blockIdx.x * 256 + threadIdx.x;    // float4 index over B*T*T/4
    int e0 = idx * 4;
    int b = e0 >> 20;
    int k = (e0 >> 10) & 1023;
    int j = e0 & 1023;
    const int* idr = ids + b*T_;
    float4 v;
    v.x = (idr[j+0] == k) ? 1.f : 0.f;
    v.y = (idr[j+1] == k) ? 1.f : 0.f;
    v.z = (idr[j+2] == k) ? 1.f : 0.f;
    v.w = (idr[j+3] == k) ? 1.f : 0.f;
    *(float4*)&out2[(size_t)e0] = v;
}

// ---------------- host launcher ---------------------------------------------
#define SMEM_ATTN ((4*64*QS + 128) * 4 + 128 * 4)   // floats + ints, bytes

extern "C" void kernel_launch(void* const* d_in, const int* in_sizes, int n_in,
                              void* d_out, int out_size)
{
    const float* x       = (const float*)d_in[0];
    const float* v_qkv_w = (const float*)d_in[1];
    const float* v_out_w = (const float*)d_in[2];
    const float* v_w1    = (const float*)d_in[3];
    const float* v_w2    = (const float*)d_in[4];
    const float* l_qkv_w = (const float*)d_in[5];
    const float* l_out_w = (const float*)d_in[6];
    const float* l_w1    = (const float*)d_in[7];
    const float* l_w2    = (const float*)d_in[8];
    float* out = (float*)d_out;

    float *qkv, *ctx, *tmp, *h1, *ffn, *outv, *outl, *part, *wl;
    double *wsum;
    int *ids, *ws, *we;
    cudaGetSymbolAddress((void**)&qkv,  g_qkv);
    cudaGetSymbolAddress((void**)&ctx,  g_ctx);
    cudaGetSymbolAddress((void**)&tmp,  g_tmp);
    cudaGetSymbolAddress((void**)&h1,   g_h1);
    cudaGetSymbolAddress((void**)&ffn,  g_ffn);
    cudaGetSymbolAddress((void**)&outv, g_outv);
    cudaGetSymbolAddress((void**)&outl, g_outl);
    cudaGetSymbolAddress((void**)&part, g_part);
    cudaGetSymbolAddress((void**)&wsum, g_wsum);
    cudaGetSymbolAddress((void**)&wl,   g_wl);
    cudaGetSymbolAddress((void**)&ids,  g_ids);
    cudaGetSymbolAddress((void**)&ws,   g_ws);
    cudaGetSymbolAddress((void**)&we,   g_we);

    cudaFuncSetAttribute(attn2_kernel<false>, cudaFuncAttributeMaxDynamicSharedMemorySize, SMEM_ATTN);
    cudaFuncSetAttribute(attn2_kernel<true>,  cudaFuncAttributeMaxDynamicSharedMemorySize, SMEM_ATTN);

    dim3 gQKV(D_/TN, BT_/TM, 3);    // batched 3 qkv projections
    dim3 gD(D_/TN, BT_/TM, 1);
    dim3 gF1(FF_/TN, BT_/TM, 1);
    dim3 gAttn(T_/AQT, H_, B_);

    // ===== layer 1 (vanilla) =====
    gemm2_kernel<false><<<gQKV, 256>>>(x, v_qkv_w, qkv, BT_, D_, D_,
                                       (long long)D_*D_, (long long)BT_*D_);
    attn2_kernel<false><<<gAttn, 256, SMEM_ATTN>>>(qkv, nullptr, ctx, part);
    reduce_part_kernel<<<(B_*T_)/256, 256>>>(part, wsum);
    gemm2_kernel<false><<<gD, 256>>>(ctx, v_out_w, tmp, BT_, D_, D_, 0, 0);
    add_ln_kernel<<<BT_, 256>>>(x, tmp, h1);
    gemm2_kernel<true ><<<gF1, 256>>>(h1, v_w1, ffn, BT_, FF_, D_, 0, 0);
    gemm2_kernel<false><<<gD, 256>>>(ffn, v_w2, tmp, BT_, D_, FF_, 0, 0);
    add_ln_kernel<<<BT_, 256>>>(h1, tmp, outv);

    // ===== dynamic window mask =====
    scan_kernel<<<B_, 256>>>(wsum, ids, ws, we);

    // ===== layer 2 (masked) =====
    gemm2_kernel<false><<<gQKV, 256>>>(outv, l_qkv_w, qkv, BT_, D_, D_,
                                       (long long)D_*D_, (long long)BT_*D_);
    attn2_kernel<true><<<gAttn, 256, SMEM_ATTN>>>(qkv, ids, ctx, part);
    reduce_part_kernel<<<(B_*T_)/256, 256>>>(part, wsum);
    gemm2_kernel<false><<<gD, 256>>>(ctx, l_out_w, tmp, BT_, D_, D_, 0, 0);
    add_ln_kernel<<<BT_, 256>>>(outv, tmp, h1);
    gemm2_kernel<true ><<<gF1, 256>>>(h1, l_w1, ffn, BT_, FF_, D_, 0, 0);
    gemm2_kernel<false><<<gD, 256>>>(ffn, l_w2, tmp, BT_, D_, FF_, 0, 0);
    add_ln_kernel<<<BT_, 256>>>(h1, tmp, outl);

    // ===== outputs =====
    wl_softmax_kernel<<<B_, 256>>>(wsum, wl);
    word_tokens_kernel<<<dim3(T_, B_), 128>>>(outl, wl, ws, we, out);
    copy_x_kernel<<<(B_*T_*D_/4)/256, 256>>>(x, out);
    winmap_kernel<<<(B_*T_*T_/4)/256, 256>>>(ids, out + (size_t)B_*2*T_*D_);
}

// round 5
// speedup vs baseline: 3.3451x; 1.8963x over previous
#include <cuda_runtime.h>
#include <cuda_bf16.h>
#include <math.h>
#include <stdint.h>

// Problem constants
#define B_  8
#define T_  1024
#define D_  512
#define FF_ 2048
#define H_  8
#define DH_ 64
#define BT_ (B_*T_)          // 8192 rows

// ---------------- scratch (device globals; no allocation allowed) ----------
__device__ float  g_qkv [3*BT_*D_];
__device__ float  g_ctx [BT_*D_];
__device__ float  g_tmp [BT_*D_];
__device__ float  g_h1  [BT_*D_];
__device__ float  g_ffn [BT_*FF_];
__device__ float  g_outv[BT_*D_];
__device__ float  g_outl[BT_*D_];
__device__ float  g_part[B_*H_*16*T_];
__device__ double g_wsum[B_*T_];
__device__ float  g_wl  [B_*T_];
__device__ int    g_ids [B_*T_];
__device__ int    g_ws  [B_*T_];
__device__ int    g_we  [B_*T_];
__device__ float  g_wT  [5505024];      // transposed weights

// transposed-weight offsets (floats)
#define WT_LQKV 0
#define WT_VOUT 786432
#define WT_LOUT 1048576
#define WT_VW1  1310720
#define WT_LW1  2359296
#define WT_VW2  3407872
#define WT_LW2  4456448

// ---------------- tf32 helpers ----------------------------------------------
__device__ __forceinline__ float f2tf32(float x) {
    uint32_t u;
    asm("cvt.rna.tf32.f32 %0, %1;" : "=r"(u) : "f"(x));
    return __uint_as_float(u);
}
#define MMA_TF32(d, a, b) \
    asm volatile("mma.sync.aligned.m16n8k8.row.col.f32.tf32.tf32.f32 " \
        "{%0,%1,%2,%3}, {%4,%5,%6,%7}, {%8,%9}, {%0,%1,%2,%3};" \
        : "+f"((d)[0]), "+f"((d)[1]), "+f"((d)[2]), "+f"((d)[3]) \
        : "r"((a)[0]), "r"((a)[1]), "r"((a)[2]), "r"((a)[3]), \
          "r"((b)[0]), "r"((b)[1]))

// ---------------- weight transpose ------------------------------------------
__global__ void transpose_kernel(const float* __restrict__ in, float* __restrict__ out,
                                 int R, int C)
{
    __shared__ float t[32][33];
    int c0 = blockIdx.x*32, r0 = blockIdx.y*32;
    int tx = threadIdx.x, ty = threadIdx.y;      // 32 x 8
    #pragma unroll
    for (int i = 0; i < 32; i += 8)
        t[ty+i][tx] = in[(size_t)(r0+ty+i)*C + c0+tx];
    __syncthreads();
    #pragma unroll
    for (int i = 0; i < 32; i += 8)
        out[(size_t)(c0+ty+i)*R + r0+tx] = t[tx][ty+i];
}

// ---------------- tensor-core tf32 GEMM: C = A @ B (B given pre-transposed) -
// A [M][K] row-major, BT [N][K] row-major, C [M][N].
// CTA tile 128x128, 4 warps, warp tile 64x64, K chunks of 32. mma.m16n8k8.tf32.
#define MS 36   // smem row stride (floats): 32 + 4 pad -> conflict-free frags
#define GM_SMEM (4 * 128 * MS * 4)   // 2 bufs x (A+B) = 73728 bytes
__global__ __launch_bounds__(128)
void gemm_mma_kernel(const float* __restrict__ A, const float* __restrict__ BTs,
                     float* __restrict__ Cs, int N, int K,
                     long long bt_z, long long c_z, int relu)
{
    extern __shared__ float smf[];
    float* Asm[2] = { smf,            smf + 128*MS };
    float* Bsm[2] = { smf + 2*128*MS, smf + 3*128*MS };

    const float* BT = BTs + (long long)blockIdx.z * bt_z;
    float*       C  = Cs  + (long long)blockIdx.z * c_z;

    int tid = threadIdx.x, lane = tid & 31, wid = tid >> 5;
    int wm = (wid >> 1) * 64, wn = (wid & 1) * 64;
    int bm = blockIdx.y * 128, bn = blockIdx.x * 128;
    int col4 = tid & 7, rbase = tid >> 3;   // loader: 8 f4-cols x 16 row-groups

    float d[4][8][4];
    #pragma unroll
    for (int i = 0; i < 4; i++)
        #pragma unroll
        for (int j = 0; j < 8; j++)
            #pragma unroll
            for (int u = 0; u < 4; u++) d[i][j][u] = 0.f;

    float4 ar[8], br[8];
    // preload chunk 0
    #pragma unroll
    for (int j = 0; j < 8; j++) {
        ar[j] = *(const float4*)&A [(size_t)(bm + rbase + j*16) * K + col4*4];
        br[j] = *(const float4*)&BT[(size_t)(bn + rbase + j*16) * K + col4*4];
    }
    #pragma unroll
    for (int j = 0; j < 8; j++) {
        int r = rbase + j*16;
        float4 av = make_float4(f2tf32(ar[j].x), f2tf32(ar[j].y), f2tf32(ar[j].z), f2tf32(ar[j].w));
        float4 bv = make_float4(f2tf32(br[j].x), f2tf32(br[j].y), f2tf32(br[j].z), f2tf32(br[j].w));
        *(float4*)&Asm[0][r*MS + col4*4] = av;
        *(float4*)&Bsm[0][r*MS + col4*4] = bv;
    }
    __syncthreads();

    int nc = K / 32;
    for (int c = 0; c < nc; c++) {
        int buf = c & 1;
        if (c + 1 < nc) {
            int k0 = (c + 1) * 32;
            #pragma unroll
            for (int j = 0; j < 8; j++) {
                ar[j] = *(const float4*)&A [(size_t)(bm + rbase + j*16) * K + k0 + col4*4];
                br[j] = *(const float4*)&BT[(size_t)(bn + rbase + j*16) * K + k0 + col4*4];
            }
        }
        const float* a_s = Asm[buf];
        const float* b_s = Bsm[buf];
        #pragma unroll
        for (int ks = 0; ks < 4; ks++) {
            int kk = ks*8 + (lane & 3);
            int rq = lane >> 2;
            uint32_t af[4][4];
            #pragma unroll
            for (int fm = 0; fm < 4; fm++) {
                int r0 = wm + fm*16 + rq;
                af[fm][0] = __float_as_uint(a_s[ r0     *MS + kk    ]);
                af[fm][1] = __float_as_uint(a_s[(r0 + 8)*MS + kk    ]);
                af[fm][2] = __float_as_uint(a_s[ r0     *MS + kk + 4]);
                af[fm][3] = __float_as_uint(a_s[(r0 + 8)*MS + kk + 4]);
            }
            uint32_t bf[8][2];
            #pragma unroll
            for (int fn = 0; fn < 8; fn++) {
                int n0 = wn + fn*8 + rq;
                bf[fn][0] = __float_as_uint(b_s[n0*MS + kk    ]);
                bf[fn][1] = __float_as_uint(b_s[n0*MS + kk + 4]);
            }
            #pragma unroll
            for (int fm = 0; fm < 4; fm++)
                #pragma unroll
                for (int fn = 0; fn < 8; fn++)
                    MMA_TF32(d[fm][fn], af[fm], bf[fn]);
        }
        if (c + 1 < nc) {
            int nb = (c + 1) & 1;
            #pragma unroll
            for (int j = 0; j < 8; j++) {
                int r = rbase + j*16;
                float4 av = make_float4(f2tf32(ar[j].x), f2tf32(ar[j].y), f2tf32(ar[j].z), f2tf32(ar[j].w));
                float4 bv = make_float4(f2tf32(br[j].x), f2tf32(br[j].y), f2tf32(br[j].z), f2tf32(br[j].w));
                *(float4*)&Asm[nb][r*MS + col4*4] = av;
                *(float4*)&Bsm[nb][r*MS + col4*4] = bv;
            }
        }
        __syncthreads();
    }

    // epilogue
    #pragma unroll
    for (int fm = 0; fm < 4; fm++) {
        #pragma unroll
        for (int fn = 0; fn < 8; fn++) {
            int r  = bm + wm + fm*16 + (lane >> 2);
            int cc = bn + wn + fn*8 + 2*(lane & 3);
            float2 v0 = make_float2(d[fm][fn][0], d[fm][fn][1]);
            float2 v1 = make_float2(d[fm][fn][2], d[fm][fn][3]);
            if (relu) {
                v0.x = fmaxf(v0.x, 0.f); v0.y = fmaxf(v0.y, 0.f);
                v1.x = fmaxf(v1.x, 0.f); v1.y = fmaxf(v1.y, 0.f);
            }
            *(float2*)&C[(size_t)r*N + cc]       = v0;
            *(float2*)&C[(size_t)(r + 8)*N + cc] = v1;
        }
    }
}

// ---------------- f32x2 helpers --------------------------------------------
__device__ __forceinline__ unsigned long long pack_dup(float a) {
    unsigned long long r;
    asm("mov.b64 %0, {%1, %1};" : "=l"(r) : "f"(a));
    return r;
}
__device__ __forceinline__ void fma2(unsigned long long& d, unsigned long long a, unsigned long long b) {
    asm("fma.rn.f32x2 %0, %1, %2, %0;" : "+l"(d) : "l"(a), "l"(b));
}
__device__ __forceinline__ float2 unpack2(unsigned long long v) {
    float2 r;
    asm("mov.b64 {%0, %1}, %2;" : "=f"(r.x), "=f"(r.y) : "l"(v));
    return r;
}

// ---------------- exact fp32 SIMT GEMM (layer-1 qkv only) -------------------
#define TM 128
#define TN 128
#define TK 8
template<bool RELU>
__global__ __launch_bounds__(256)
void gemm2_kernel(const float* __restrict__ A, const float* __restrict__ Bsrc,
                  float* __restrict__ Csrc, int M, int N, int K,
                  long long bz_stride, long long cz_stride)
{
    const float* Bm = Bsrc + (long long)blockIdx.z * bz_stride;
    float*       C  = Csrc + (long long)blockIdx.z * cz_stride;

    __shared__ float As[2][TK][TM];
    __shared__ float Bs[2][TK][TN];
    int tid = threadIdx.x;
    int bm = blockIdx.y * TM, bn = blockIdx.x * TN;
    int tr = tid >> 4, tc = tid & 15;
    int arow = tid >> 1, ak = (tid & 1) * 4;
    int bk = tid >> 5, bn4 = (tid & 31) * 4;

    unsigned long long acc[8][4];
    #pragma unroll
    for (int i = 0; i < 8; i++)
        #pragma unroll
        for (int j = 0; j < 4; j++) acc[i][j] = 0ULL;

    float4 av = *(const float4*)&A[(size_t)(bm + arow) * K + ak];
    float4 bv = *(const float4*)&Bm[(size_t)bk * N + bn + bn4];
    As[0][ak+0][arow] = av.x; As[0][ak+1][arow] = av.y;
    As[0][ak+2][arow] = av.z; As[0][ak+3][arow] = av.w;
    *(float4*)&Bs[0][bk][bn4] = bv;
    __syncthreads();

    int nkt = K / TK;
    int buf = 0;
    for (int kt = 0; kt < nkt; kt++) {
        if (kt + 1 < nkt) {
            int k0 = (kt + 1) * TK;
            av = *(const float4*)&A[(size_t)(bm + arow) * K + k0 + ak];
            bv = *(const float4*)&Bm[(size_t)(k0 + bk) * N + bn + bn4];
        }
        #pragma unroll
        for (int k = 0; k < TK; k++) {
            float a[8];
            *(float4*)&a[0] = *(float4*)&As[buf][k][tr*8];
            *(float4*)&a[4] = *(float4*)&As[buf][k][tr*8 + 4];
            unsigned long long bb[4];
            *(float4*)&bb[0] = *(float4*)&Bs[buf][k][tc*8];
            *(float4*)&bb[2] = *(float4*)&Bs[buf][k][tc*8 + 4];
            #pragma unroll
            for (int i = 0; i < 8; i++) {
                unsigned long long aa = pack_dup(a[i]);
                #pragma unroll
                for (int j = 0; j < 4; j++) fma2(acc[i][j], aa, bb[j]);
            }
        }
        if (kt + 1 < nkt) {
            int nb = buf ^ 1;
            As[nb][ak+0][arow] = av.x; As[nb][ak+1][arow] = av.y;
            As[nb][ak+2][arow] = av.z; As[nb][ak+3][arow] = av.w;
            *(float4*)&Bs[nb][bk][bn4] = bv;
        }
        __syncthreads();
        buf ^= 1;
    }
    #pragma unroll
    for (int i = 0; i < 8; i++) {
        float vals[8];
        #pragma unroll
        for (int j = 0; j < 4; j++) {
            float2 p = unpack2(acc[i][j]);
            vals[2*j] = p.x; vals[2*j+1] = p.y;
        }
        if (RELU) {
            #pragma unroll
            for (int j = 0; j < 8; j++) vals[j] = fmaxf(vals[j], 0.f);
        }
        size_t ro = (size_t)(bm + tr*8 + i) * N + bn + tc*8;
        *(float4*)&C[ro]     = *(float4*)&vals[0];
        *(float4*)&C[ro + 4] = *(float4*)&vals[4];
    }
}

// ---------------- attention: 64x64 tiles, 4x4 microtiles, f32x2 -------------
#define AQT 64
#define AKT 64
#define QS  68

template<bool MASKED>
__global__ __launch_bounds__(256)
void attn2_kernel(const float* __restrict__ qkv, const int* __restrict__ ids,
                  float* __restrict__ ctx, float* __restrict__ part)
{
    extern __shared__ float smf[];
    float* Qts = smf;
    float* Kts = Qts + 64*QS;
    float* Vs  = Kts + 64*QS;
    float* Pt  = Vs  + 64*QS;
    float* ms  = Pt  + 64*QS;
    float* ls  = ms + 64;
    int*   qid = (int*)(ls + 64);
    int*   kid = qid + 64;

    int qt = blockIdx.x, h = blockIdx.y, b = blockIdx.z;
    int tid = threadIdx.x;
    int q0 = qt * AQT;
    const float scale = 0.125f;

    const float* Qp = qkv;
    const float* Kp = qkv + (size_t)BT_*D_;
    const float* Vp = qkv + (size_t)2*BT_*D_;

    int ti4 = (tid >> 4) * 4;
    int tj4 = (tid & 15) * 4;
    int lrow = tid >> 2;
    int le0  = (tid & 3) * 16;

    {
        const float* src = Qp + (size_t)(b*T_ + q0 + lrow) * D_ + h*DH_ + le0;
        #pragma unroll
        for (int u = 0; u < 4; u++) {
            float4 v = *(const float4*)(src + u*4);
            Qts[(le0 + u*4 + 0)*QS + lrow] = v.x;
            Qts[(le0 + u*4 + 1)*QS + lrow] = v.y;
            Qts[(le0 + u*4 + 2)*QS + lrow] = v.z;
            Qts[(le0 + u*4 + 3)*QS + lrow] = v.w;
        }
        if (MASKED && tid < 64) qid[tid] = ids[b*T_ + q0 + tid];
    }
    __syncthreads();
    int qid0 = 0, qidL = 0;
    if (MASKED) { qid0 = qid[0]; qidL = qid[63]; }

    float m = -1e30f, l = 0.f;
    int r = tid >> 2, seg = tid & 3;

    for (int kt = 0; kt < T_/AKT; kt++) {
        int k0 = kt * AKT;
        if (MASKED && tid < 64) kid[tid] = ids[b*T_ + k0 + tid];
        __syncthreads();
        if (MASKED) {
            if (kid[63] < qid0 || qidL < kid[0]) continue;
        }
        {
            const float* src = Kp + (size_t)(b*T_ + k0 + lrow) * D_ + h*DH_ + le0;
            #pragma unroll
            for (int u = 0; u < 4; u++) {
                float4 v = *(const float4*)(src + u*4);
                Kts[(le0 + u*4 + 0)*QS + lrow] = v.x;
                Kts[(le0 + u*4 + 1)*QS + lrow] = v.y;
                Kts[(le0 + u*4 + 2)*QS + lrow] = v.z;
                Kts[(le0 + u*4 + 3)*QS + lrow] = v.w;
            }
        }
        __syncthreads();
        unsigned long long sacc[4][2];
        #pragma unroll
        for (int i = 0; i < 4; i++) { sacc[i][0] = 0ULL; sacc[i][1] = 0ULL; }
        for (int e = 0; e < 64; e++) {
            float4 qa = *(const float4*)&Qts[e*QS + ti4];
            unsigned long long bb[2];
            *(float4*)&bb[0] = *(const float4*)&Kts[e*QS + tj4];
            float aq[4] = {qa.x, qa.y, qa.z, qa.w};
            #pragma unroll
            for (int i = 0; i < 4; i++) {
                unsigned long long aa = pack_dup(aq[i]);
                fma2(sacc[i][0], aa, bb[0]);
                fma2(sacc[i][1], aa, bb[1]);
            }
        }
        #pragma unroll
        for (int ii = 0; ii < 4; ii++) {
            float2 p0 = unpack2(sacc[ii][0]);
            float2 p1 = unpack2(sacc[ii][1]);
            float sv[4] = {p0.x, p0.y, p1.x, p1.y};
            #pragma unroll
            for (int jj = 0; jj < 4; jj++) {
                float s = sv[jj] * scale;
                if (MASKED && qid[ti4 + ii] != kid[tj4 + jj]) s = -1e30f;
                Pt[(tj4 + jj)*QS + ti4 + ii] = s;
            }
        }
        __syncthreads();
        {
            float sv[16]; float tm = -1e30f;
            #pragma unroll
            for (int it = 0; it < 16; it++) {
                sv[it] = Pt[(seg*16 + it)*QS + r];
                tm = fmaxf(tm, sv[it]);
            }
            tm = fmaxf(tm, __shfl_xor_sync(0xffffffffu, tm, 1));
            tm = fmaxf(tm, __shfl_xor_sync(0xffffffffu, tm, 2));
            float nm = fmaxf(m, tm);
            float es = 0.f;
            #pragma unroll
            for (int it = 0; it < 16; it++) es += expf(sv[it] - nm);
            es += __shfl_xor_sync(0xffffffffu, es, 1);
            es += __shfl_xor_sync(0xffffffffu, es, 2);
            l = l * expf(m - nm) + es;
            m = nm;
        }
    }
    __syncthreads();
    if (seg == 0) { ms[r] = m; ls[r] = l; }
    __syncthreads();

    unsigned long long pacc[4][2];
    #pragma unroll
    for (int i = 0; i < 4; i++) { pacc[i][0] = 0ULL; pacc[i][1] = 0ULL; }

    for (int kt = 0; kt < T_/AKT; kt++) {
        int k0 = kt * AKT;
        if (MASKED && tid < 64) kid[tid] = ids[b*T_ + k0 + tid];
        __syncthreads();
        if (MASKED) {
            if (kid[63] < qid0 || qidL < kid[0]) {
                if (tid < 64)
                    part[((size_t)((b*H_ + h)*16 + qt))*T_ + k0 + tid] = 0.f;
                continue;
            }
        }
        {
            const float* ksrc = Kp + (size_t)(b*T_ + k0 + lrow) * D_ + h*DH_ + le0;
            #pragma unroll
            for (int u = 0; u < 4; u++) {
                float4 v = *(const float4*)(ksrc + u*4);
                Kts[(le0 + u*4 + 0)*QS + lrow] = v.x;
                Kts[(le0 + u*4 + 1)*QS + lrow] = v.y;
                Kts[(le0 + u*4 + 2)*QS + lrow] = v.z;
                Kts[(le0 + u*4 + 3)*QS + lrow] = v.w;
            }
            const float* vsrc = Vp + (size_t)(b*T_ + k0 + lrow) * D_ + h*DH_ + le0;
            #pragma unroll
            for (int u = 0; u < 4; u++)
                *(float4*)&Vs[lrow*QS + le0 + u*4] = *(const float4*)(vsrc + u*4);
        }
        __syncthreads();
        unsigned long long sacc[4][2];
        #pragma unroll
        for (int i = 0; i < 4; i++) { sacc[i][0] = 0ULL; sacc[i][1] = 0ULL; }
        for (int e = 0; e < 64; e++) {
            float4 qa = *(const float4*)&Qts[e*QS + ti4];
            unsigned long long bb[2];
            *(float4*)&bb[0] = *(const float4*)&Kts[e*QS + tj4];
            float aq[4] = {qa.x, qa.y, qa.z, qa.w};
            #pragma unroll
            for (int i = 0; i < 4; i++) {
                unsigned long long aa = pack_dup(aq[i]);
                fma2(sacc[i][0], aa, bb[0]);
                fma2(sacc[i][1], aa, bb[1]);
            }
        }
        #pragma unroll
        for (int ii = 0; ii < 4; ii++) {
            float2 p0 = unpack2(sacc[ii][0]);
            float2 p1 = unpack2(sacc[ii][1]);
            float sv[4] = {p0.x, p0.y, p1.x, p1.y};
            float mi = ms[ti4 + ii], li = ls[ti4 + ii];
            #pragma unroll
            for (int jj = 0; jj < 4; jj++) {
                float p;
                if (MASKED && qid[ti4 + ii] != kid[tj4 + jj]) p = 0.f;
                else p = expf(sv[jj] * scale - mi) / li;
                Pt[(tj4 + jj)*QS + ti4 + ii] = p;
            }
        }
        __syncthreads();
        if (tid < 64) {
            double cs = 0.0;
            #pragma unroll
            for (int i = 0; i < 64; i++) cs += (double)Pt[tid*QS + i];
            part[((size_t)((b*H_ + h)*16 + qt))*T_ + k0 + tid] = (float)cs;
        }
        for (int j = 0; j < 64; j++) {
            float4 pa = *(const float4*)&Pt[j*QS + ti4];
            unsigned long long bb[2];
            *(float4*)&bb[0] = *(const float4*)&Vs[j*QS + tj4];
            float ap[4] = {pa.x, pa.y, pa.z, pa.w};
            #pragma unroll
            for (int i = 0; i < 4; i++) {
                unsigned long long aa = pack_dup(ap[i]);
                fma2(pacc[i][0], aa, bb[0]);
                fma2(pacc[i][1], aa, bb[1]);
            }
        }
    }
    #pragma unroll
    for (int ii = 0; ii < 4; ii++) {
        float2 c0 = unpack2(pacc[ii][0]);
        float2 c1 = unpack2(pacc[ii][1]);
        float4 v = make_float4(c0.x, c0.y, c1.x, c1.y);
        *(float4*)&ctx[(size_t)(b*T_ + q0 + ti4 + ii)*D_ + h*DH_ + tj4] = v;
    }
}

// ---------------- deterministic fp64 reduction of prob column sums ---------
__global__ void reduce_part_kernel(const float* __restrict__ part, double* __restrict__ wsum)
{
    int idx = blockIdx.x * 256 + threadIdx.x;
    int b = idx >> 10, j = idx & 1023;
    double s = 0.0;
    for (int g = 0; g < H_*16; g++)
        s += (double)part[((size_t)(b*H_*16 + g)) * T_ + j];
    wsum[idx] = s;
}

// ---------------- y = LayerNorm(x + r), row = 512 ---------------------------
__global__ void add_ln_kernel(const float* __restrict__ x, const float* __restrict__ r,
                              float* __restrict__ y)
{
    __shared__ float sm[256];
    int row = blockIdx.x, tid = threadIdx.x;
    size_t base = (size_t)row * D_;
    float v0 = x[base + tid]        + r[base + tid];
    float v1 = x[base + 256 + tid]  + r[base + 256 + tid];
    sm[tid] = v0 + v1; __syncthreads();
    for (int s = 128; s > 0; s >>= 1) { if (tid < s) sm[tid] += sm[tid + s]; __syncthreads(); }
    float mean = sm[0] * (1.f / D_); __syncthreads();
    float d0 = v0 - mean, d1 = v1 - mean;
    sm[tid] = d0*d0 + d1*d1; __syncthreads();
    for (int s = 128; s > 0; s >>= 1) { if (tid < s) sm[tid] += sm[tid + s]; __syncthreads(); }
    float var = sm[0] * (1.f / D_);
    float inv = 1.f / sqrtf(var + 1e-5f);
    y[base + tid]       = d0 * inv;
    y[base + 256 + tid] = d1 * inv;
}

// ---------------- window-id scan (exact replica of reference scan, fp64) ----
__global__ void scan_kernel(const double* __restrict__ wsum, int* __restrict__ ids,
                            int* __restrict__ ws, int* __restrict__ we)
{
    __shared__ double smn[256], smx[256];
    int b = blockIdx.x, tid = threadIdx.x;
    double mn = 1e300, mx = -1e300;
    for (int t = tid; t < T_; t += 256) {
        double v = wsum[b*T_ + t] * (1.0 / H_);
        mn = fmin(mn, v); mx = fmax(mx, v);
    }
    smn[tid] = mn; smx[tid] = mx; __syncthreads();
    for (int s = 128; s > 0; s >>= 1) {
        if (tid < s) { smn[tid] = fmin(smn[tid], smn[tid+s]); smx[tid] = fmax(smx[tid], smx[tid+s]); }
        __syncthreads();
    }
    for (int t = tid; t < T_; t += 256) { ws[b*T_ + t] = 0; we[b*T_ + t] = 0; }
    __syncthreads();
    if (tid == 0) {
        double MN = smn[0], MX = smx[0];
        double denom = MX - MN + 1e-8;
        double thr = MN + 0.5 * denom;
        int cur = (wsum[b*T_ + 0] * (1.0 / H_)) >= thr ? 1 : 0;
        int start = 0, wid = 0;
        ids[b*T_ + 0] = 0;
        for (int t = 1; t < T_; t++) {
            int wt = (wsum[b*T_ + t] * (1.0 / H_)) >= thr ? 1 : 0;
            if (wt == cur) {
            } else if (start + 1 == t) {
                cur = wt;
            } else {
                cur = wt; start = t; wid++;
            }
            ids[b*T_ + t] = wid;
        }
        int prev = -1;
        for (int t = 0; t < T_; t++) {
            int w = ids[b*T_ + t];
            if (w != prev) { ws[b*T_ + w] = t; prev = w; }
            we[b*T_ + w] = t + 1;
        }
    }
}

// ---------------- wl = softmax_j(wsum/H) ------------------------------------
__global__ void wl_softmax_kernel(const double* __restrict__ wsum, float* __restrict__ wl)
{
    __shared__ float sm[256];
    int b = blockIdx.x, tid = threadIdx.x;
    float vals[4];
    float mx = -1e30f;
    #pragma unroll
    for (int i = 0; i < 4; i++) {
        vals[i] = (float)(wsum[b*T_ + tid + i*256] * (1.0 / H_));
        mx = fmaxf(mx, vals[i]);
    }
    sm[tid] = mx; __syncthreads();
    for (int s = 128; s > 0; s >>= 1) { if (tid < s) sm[tid] = fmaxf(sm[tid], sm[tid+s]); __syncthreads(); }
    float M = sm[0]; __syncthreads();
    float e[4], acc = 0.f;
    #pragma unroll
    for (int i = 0; i < 4; i++) { e[i] = expf(vals[i] - M); acc += e[i]; }
    sm[tid] = acc; __syncthreads();
    for (int s = 128; s > 0; s >>= 1) { if (tid < s) sm[tid] += sm[tid+s]; __syncthreads(); }
    float inv = 1.f / sm[0];
    #pragma unroll
    for (int i = 0; i < 4; i++) wl[b*T_ + tid + i*256] = e[i] * inv;
}

// ---------------- window-weighted pooling (deterministic gather) ------------
__global__ void word_tokens_kernel(const float* __restrict__ outl, const float* __restrict__ wl,
                                   const int* __restrict__ ws, const int* __restrict__ we,
                                   float* __restrict__ out)
{
    int w = blockIdx.x, b = blockIdx.y, tid = threadIdx.x;
    int s = ws[b*T_ + w], e = we[b*T_ + w];
    float acc[4] = {0.f, 0.f, 0.f, 0.f};
    for (int t = s; t < e; t++) {
        float g = wl[b*T_ + t];
        const float* row = outl + (size_t)(b*T_ + t) * D_;
        #pragma unroll
        for (int u = 0; u < 4; u++) acc[u] += g * row[tid + u*128];
    }
    float* dst = out + ((size_t)(b*2*T_ + w)) * D_;
    #pragma unroll
    for (int u = 0; u < 4; u++) dst[tid + u*128] = acc[u];
}

// ---------------- copy x into second half of concat output ------------------
__global__ void copy_x_kernel(const float* __restrict__ x, float* __restrict__ out)
{
    int idx = blockIdx.x * 256 + threadIdx.x;
    int b = (idx * 4) / (T_*D_);
    float4 v = *(const float4*)&x[(size_t)idx * 4];
    *(float4*)&out[(size_t)idx * 4 + (size_t)(b + 1) * T_ * D_] = v;
}

// ---------------- window_mapping output -------------------------------------
__global__ void winmap_kernel(const int* __restrict__ ids, float* __restrict__ out2)
{
    int idx = blockIdx.x * 256 + threadIdx.x;
    int e0 = idx * 4;
    int b = e0 >> 20;
    int k = (e0 >> 10) & 1023;
    int j = e0 & 1023;
    const int* idr = ids + b*T_;
    float4 v;
    v.x = (idr[j+0] == k) ? 1.f : 0.f;
    v.y = (idr[j+1] == k) ? 1.f : 0.f;
    v.z = (idr[j+2] == k) ? 1.f : 0.f;
    v.w = (idr[j+3] == k) ? 1.f : 0.f;
    *(float4*)&out2[(size_t)e0] = v;
}

// ---------------- host launcher ---------------------------------------------
#define SMEM_ATTN ((4*64*QS + 128) * 4 + 128 * 4)

extern "C" void kernel_launch(void* const* d_in, const int* in_sizes, int n_in,
                              void* d_out, int out_size)
{
    const float* x       = (const float*)d_in[0];
    const float* v_qkv_w = (const float*)d_in[1];
    const float* v_out_w = (const float*)d_in[2];
    const float* v_w1    = (const float*)d_in[3];
    const float* v_w2    = (const float*)d_in[4];
    const float* l_qkv_w = (const float*)d_in[5];
    const float* l_out_w = (const float*)d_in[6];
    const float* l_w1    = (const float*)d_in[7];
    const float* l_w2    = (const float*)d_in[8];
    float* out = (float*)d_out;

    float *qkv, *ctx, *tmp, *h1, *ffn, *outv, *outl, *part, *wl, *wT;
    double *wsum;
    int *ids, *ws, *we;
    cudaGetSymbolAddress((void**)&qkv,  g_qkv);
    cudaGetSymbolAddress((void**)&ctx,  g_ctx);
    cudaGetSymbolAddress((void**)&tmp,  g_tmp);
    cudaGetSymbolAddress((void**)&h1,   g_h1);
    cudaGetSymbolAddress((void**)&ffn,  g_ffn);
    cudaGetSymbolAddress((void**)&outv, g_outv);
    cudaGetSymbolAddress((void**)&outl, g_outl);
    cudaGetSymbolAddress((void**)&part, g_part);
    cudaGetSymbolAddress((void**)&wsum, g_wsum);
    cudaGetSymbolAddress((void**)&wl,   g_wl);
    cudaGetSymbolAddress((void**)&ids,  g_ids);
    cudaGetSymbolAddress((void**)&ws,   g_ws);
    cudaGetSymbolAddress((void**)&we,   g_we);
    cudaGetSymbolAddress((void**)&wT,   g_wT);

    cudaFuncSetAttribute(attn2_kernel<false>, cudaFuncAttributeMaxDynamicSharedMemorySize, SMEM_ATTN);
    cudaFuncSetAttribute(attn2_kernel<true>,  cudaFuncAttributeMaxDynamicSharedMemorySize, SMEM_ATTN);
    cudaFuncSetAttribute(gemm_mma_kernel, cudaFuncAttributeMaxDynamicSharedMemorySize, GM_SMEM);

    // ===== transpose all tensor-path weights ====
    transpose_kernel<<<dim3(D_/32,  D_/32), dim3(32,8)>>>(l_qkv_w,            wT + WT_LQKV,            D_,  D_);
    transpose_kernel<<<dim3(D_/32,  D_/32), dim3(32,8)>>>(l_qkv_w + D_*D_,    wT + WT_LQKV + D_*D_,    D_,  D_);
    transpose_kernel<<<dim3(D_/32,  D_/32), dim3(32,8)>>>(l_qkv_w + 2*D_*D_,  wT + WT_LQKV + 2*D_*D_,  D_,  D_);
    transpose_kernel<<<dim3(D_/32,  D_/32), dim3(32,8)>>>(v_out_w, wT + WT_VOUT, D_,  D_);
    transpose_kernel<<<dim3(D_/32,  D_/32), dim3(32,8)>>>(l_out_w, wT + WT_LOUT, D_,  D_);
    transpose_kernel<<<dim3(FF_/32, D_/32), dim3(32,8)>>>(v_w1,    wT + WT_VW1,  D_,  FF_);
    transpose_kernel<<<dim3(FF_/32, D_/32), dim3(32,8)>>>(l_w1,    wT + WT_LW1,  D_,  FF_);
    transpose_kernel<<<dim3(D_/32, FF_/32), dim3(32,8)>>>(v_w2,    wT + WT_VW2,  FF_, D_);
    transpose_kernel<<<dim3(D_/32, FF_/32), dim3(32,8)>>>(l_w2,    wT + WT_LW2,  FF_, D_);

    dim3 gQKV(D_/TN, BT_/TM, 3);
    dim3 gAttn(T_/AQT, H_, B_);
    dim3 gtD(D_/128, BT_/128, 1);
    dim3 gtF1(FF_/128, BT_/128, 1);
    dim3 gtQKV(D_/128, BT_/128, 3);

    // ===== layer 1 (vanilla) =====
    gemm2_kernel<false><<<gQKV, 256>>>(x, v_qkv_w, qkv, BT_, D_, D_,
                                       (long long)D_*D_, (long long)BT_*D_);  // exact fp32 (decision path)
    attn2_kernel<false><<<gAttn, 256, SMEM_ATTN>>>(qkv, nullptr, ctx, part);
    reduce_part_kernel<<<(B_*T_)/256, 256>>>(part, wsum);
    gemm_mma_kernel<<<gtD, 128, GM_SMEM>>>(ctx, wT + WT_VOUT, tmp, D_, D_, 0, 0, 0);
    add_ln_kernel<<<BT_, 256>>>(x, tmp, h1);
    gemm_mma_kernel<<<gtF1, 128, GM_SMEM>>>(h1, wT + WT_VW1, ffn, FF_, D_, 0, 0, 1);
    gemm_mma_kernel<<<gtD, 128, GM_SMEM>>>(ffn, wT + WT_VW2, tmp, D_, FF_, 0, 0, 0);
    add_ln_kernel<<<BT_, 256>>>(h1, tmp, outv);

    // ===== dynamic window mask =====
    scan_kernel<<<B_, 256>>>(wsum, ids, ws, we);

    // ===== layer 2 (masked) =====
    gemm_mma_kernel<<<gtQKV, 128, GM_SMEM>>>(outv, wT + WT_LQKV, qkv, D_, D_,
                                             (long long)D_*D_, (long long)BT_*D_, 0);
    attn2_kernel<true><<<gAttn, 256, SMEM_ATTN>>>(qkv, ids, ctx, part);
    reduce_part_kernel<<<(B_*T_)/256, 256>>>(part, wsum);
    gemm_mma_kernel<<<gtD, 128, GM_SMEM>>>(ctx, wT + WT_LOUT, tmp, D_, D_, 0, 0, 0);
    add_ln_kernel<<<BT_, 256>>>(outv, tmp, h1);
    gemm_mma_kernel<<<gtF1, 128, GM_SMEM>>>(h1, wT + WT_LW1, ffn, FF_, D_, 0, 0, 1);
    gemm_mma_kernel<<<gtD, 128, GM_SMEM>>>(ffn, wT + WT_LW2, tmp, D_, FF_, 0, 0, 0);
    add_ln_kernel<<<BT_, 256>>>(h1, tmp, outl);

    // ===== outputs =====
    wl_softmax_kernel<<<B_, 256>>>(wsum, wl);
    word_tokens_kernel<<<dim3(T_, B_), 128>>>(outl, wl, ws, we, out);
    copy_x_kernel<<<(B_*T_*D_/4)/256, 256>>>(x, out);
    winmap_kernel<<<(B_*T_*T_/4)/256, 256>>>(ids, out + (size_t)B_*2*T_*D_);
}

// round 6
// speedup vs baseline: 3.9452x; 1.1794x over previous
#include <cuda_runtime.h>
#include <cuda_bf16.h>
#include <math.h>
#include <stdint.h>

// Problem constants
#define B_  8
#define T_  1024
#define D_  512
#define FF_ 2048
#define H_  8
#define DH_ 64
#define BT_ (B_*T_)          // 8192 rows

// ---------------- scratch (device globals; no allocation allowed) ----------
__device__ float  g_qkv [3*BT_*D_];
__device__ float  g_ctx [BT_*D_];
__device__ float  g_tmp [BT_*D_];
__device__ float  g_h1  [BT_*D_];
__device__ float  g_ffn [BT_*FF_];
__device__ float  g_outv[BT_*D_];
__device__ float  g_outl[BT_*D_];
__device__ float  g_part[B_*H_*16*T_];
__device__ double g_wsum[B_*T_];
__device__ float  g_wl  [B_*T_];
__device__ int    g_ids [B_*T_];
__device__ int    g_ws  [B_*T_];
__device__ int    g_we  [B_*T_];
__device__ float  g_wT  [6291456];      // transposed weights

// transposed-weight offsets (floats)
#define WT_LQKV 0
#define WT_VOUT 786432
#define WT_LOUT 1048576
#define WT_VW1  1310720
#define WT_LW1  2359296
#define WT_VW2  3407872
#define WT_LW2  4456448
#define WT_VQKV 5505024

// ---------------- tf32 helpers ----------------------------------------------
__device__ __forceinline__ float f2tf32(float x) {
    uint32_t u;
    asm("cvt.rna.tf32.f32 %0, %1;" : "=r"(u) : "f"(x));
    return __uint_as_float(u);
}
#define MMA_TF32(d, a, b) \
    asm volatile("mma.sync.aligned.m16n8k8.row.col.f32.tf32.tf32.f32 " \
        "{%0,%1,%2,%3}, {%4,%5,%6,%7}, {%8,%9}, {%0,%1,%2,%3};" \
        : "+f"((d)[0]), "+f"((d)[1]), "+f"((d)[2]), "+f"((d)[3]) \
        : "r"((a)[0]), "r"((a)[1]), "r"((a)[2]), "r"((a)[3]), \
          "r"((b)[0]), "r"((b)[1]))

// ---------------- weight transpose ------------------------------------------
__global__ void transpose_kernel(const float* __restrict__ in, float* __restrict__ out,
                                 int R, int C)
{
    __shared__ float t[32][33];
    int c0 = blockIdx.x*32, r0 = blockIdx.y*32;
    int tx = threadIdx.x, ty = threadIdx.y;      // 32 x 8
    #pragma unroll
    for (int i = 0; i < 32; i += 8)
        t[ty+i][tx] = in[(size_t)(r0+ty+i)*C + c0+tx];
    __syncthreads();
    #pragma unroll
    for (int i = 0; i < 32; i += 8)
        out[(size_t)(c0+ty+i)*R + r0+tx] = t[tx][ty+i];
}

// ---------------- plain tf32 GEMM (continuous path) -------------------------
#define MS 36
#define GM_SMEM (4 * 128 * MS * 4)
__global__ __launch_bounds__(128)
void gemm_mma_kernel(const float* __restrict__ A, const float* __restrict__ BTs,
                     float* __restrict__ Cs, int N, int K,
                     long long bt_z, long long c_z, int relu)
{
    extern __shared__ float smf[];
    float* Asm[2] = { smf,            smf + 128*MS };
    float* Bsm[2] = { smf + 2*128*MS, smf + 3*128*MS };

    const float* BT = BTs + (long long)blockIdx.z * bt_z;
    float*       C  = Cs  + (long long)blockIdx.z * c_z;

    int tid = threadIdx.x, lane = tid & 31, wid = tid >> 5;
    int wm = (wid >> 1) * 64, wn = (wid & 1) * 64;
    int bm = blockIdx.y * 128, bn = blockIdx.x * 128;
    int col4 = tid & 7, rbase = tid >> 3;

    float d[4][8][4];
    #pragma unroll
    for (int i = 0; i < 4; i++)
        #pragma unroll
        for (int j = 0; j < 8; j++)
            #pragma unroll
            for (int u = 0; u < 4; u++) d[i][j][u] = 0.f;

    float4 ar[8], br[8];
    #pragma unroll
    for (int j = 0; j < 8; j++) {
        ar[j] = *(const float4*)&A [(size_t)(bm + rbase + j*16) * K + col4*4];
        br[j] = *(const float4*)&BT[(size_t)(bn + rbase + j*16) * K + col4*4];
    }
    #pragma unroll
    for (int j = 0; j < 8; j++) {
        int r = rbase + j*16;
        float4 av = make_float4(f2tf32(ar[j].x), f2tf32(ar[j].y), f2tf32(ar[j].z), f2tf32(ar[j].w));
        float4 bv = make_float4(f2tf32(br[j].x), f2tf32(br[j].y), f2tf32(br[j].z), f2tf32(br[j].w));
        *(float4*)&Asm[0][r*MS + col4*4] = av;
        *(float4*)&Bsm[0][r*MS + col4*4] = bv;
    }
    __syncthreads();

    int nc = K / 32;
    for (int c = 0; c < nc; c++) {
        int buf = c & 1;
        if (c + 1 < nc) {
            int k0 = (c + 1) * 32;
            #pragma unroll
            for (int j = 0; j < 8; j++) {
                ar[j] = *(const float4*)&A [(size_t)(bm + rbase + j*16) * K + k0 + col4*4];
                br[j] = *(const float4*)&BT[(size_t)(bn + rbase + j*16) * K + k0 + col4*4];
            }
        }
        const float* a_s = Asm[buf];
        const float* b_s = Bsm[buf];
        #pragma unroll
        for (int ks = 0; ks < 4; ks++) {
            int kk = ks*8 + (lane & 3);
            int rq = lane >> 2;
            uint32_t af[4][4];
            #pragma unroll
            for (int fm = 0; fm < 4; fm++) {
                int r0 = wm + fm*16 + rq;
                af[fm][0] = __float_as_uint(a_s[ r0     *MS + kk    ]);
                af[fm][1] = __float_as_uint(a_s[(r0 + 8)*MS + kk    ]);
                af[fm][2] = __float_as_uint(a_s[ r0     *MS + kk + 4]);
                af[fm][3] = __float_as_uint(a_s[(r0 + 8)*MS + kk + 4]);
            }
            uint32_t bf[8][2];
            #pragma unroll
            for (int fn = 0; fn < 8; fn++) {
                int n0 = wn + fn*8 + rq;
                bf[fn][0] = __float_as_uint(b_s[n0*MS + kk    ]);
                bf[fn][1] = __float_as_uint(b_s[n0*MS + kk + 4]);
            }
            #pragma unroll
            for (int fm = 0; fm < 4; fm++)
                #pragma unroll
                for (int fn = 0; fn < 8; fn++)
                    MMA_TF32(d[fm][fn], af[fm], bf[fn]);
        }
        if (c + 1 < nc) {
            int nb = (c + 1) & 1;
            #pragma unroll
            for (int j = 0; j < 8; j++) {
                int r = rbase + j*16;
                float4 av = make_float4(f2tf32(ar[j].x), f2tf32(ar[j].y), f2tf32(ar[j].z), f2tf32(ar[j].w));
                float4 bv = make_float4(f2tf32(br[j].x), f2tf32(br[j].y), f2tf32(br[j].z), f2tf32(br[j].w));
                *(float4*)&Asm[nb][r*MS + col4*4] = av;
                *(float4*)&Bsm[nb][r*MS + col4*4] = bv;
            }
        }
        __syncthreads();
    }

    #pragma unroll
    for (int fm = 0; fm < 4; fm++) {
        #pragma unroll
        for (int fn = 0; fn < 8; fn++) {
            int r  = bm + wm + fm*16 + (lane >> 2);
            int cc = bn + wn + fn*8 + 2*(lane & 3);
            float2 v0 = make_float2(d[fm][fn][0], d[fm][fn][1]);
            float2 v1 = make_float2(d[fm][fn][2], d[fm][fn][3]);
            if (relu) {
                v0.x = fmaxf(v0.x, 0.f); v0.y = fmaxf(v0.y, 0.f);
                v1.x = fmaxf(v1.x, 0.f); v1.y = fmaxf(v1.y, 0.f);
            }
            *(float2*)&C[(size_t)r*N + cc]       = v0;
            *(float2*)&C[(size_t)(r + 8)*N + cc] = v1;
        }
    }
}

// ---------------- 3xTF32 GEMM (decision path: layer-1 qkv) ------------------
// 256 threads / 8 warps, warp tile 32x64. ~fp32-accurate.
#define G3_SMEM (8 * 128 * MS * 4)   // hi/lo x (A,B) x 2 bufs = 147456
__global__ __launch_bounds__(256)
void gemm_mma3_kernel(const float* __restrict__ A, const float* __restrict__ BTs,
                      float* __restrict__ Cs, int N, int K,
                      long long bt_z, long long c_z)
{
    extern __shared__ float smf[];
    float* Ah[2] = { smf,            smf + 128*MS };
    float* Al[2] = { smf + 2*128*MS, smf + 3*128*MS };
    float* Bh[2] = { smf + 4*128*MS, smf + 5*128*MS };
    float* Bl[2] = { smf + 6*128*MS, smf + 7*128*MS };

    const float* BT = BTs + (long long)blockIdx.z * bt_z;
    float*       C  = Cs  + (long long)blockIdx.z * c_z;

    int tid = threadIdx.x, lane = tid & 31, wid = tid >> 5;
    int wm = (wid >> 1) * 32, wn = (wid & 1) * 64;
    int bm = blockIdx.y * 128, bn = blockIdx.x * 128;
    int rbase = tid >> 1, cb = (tid & 1) * 16;   // loader: 128 rows x 32 cols

    float d[2][8][4];
    #pragma unroll
    for (int i = 0; i < 2; i++)
        #pragma unroll
        for (int j = 0; j < 8; j++)
            #pragma unroll
            for (int u = 0; u < 4; u++) d[i][j][u] = 0.f;

    float4 ar[4], br[4];
    #pragma unroll
    for (int j = 0; j < 4; j++) {
        ar[j] = *(const float4*)&A [(size_t)(bm + rbase) * K + cb + j*4];
        br[j] = *(const float4*)&BT[(size_t)(bn + rbase) * K + cb + j*4];
    }
    #pragma unroll
    for (int j = 0; j < 4; j++) {
        float4 ah = make_float4(f2tf32(ar[j].x), f2tf32(ar[j].y), f2tf32(ar[j].z), f2tf32(ar[j].w));
        float4 al = make_float4(f2tf32(ar[j].x - ah.x), f2tf32(ar[j].y - ah.y),
                                f2tf32(ar[j].z - ah.z), f2tf32(ar[j].w - ah.w));
        float4 bh = make_float4(f2tf32(br[j].x), f2tf32(br[j].y), f2tf32(br[j].z), f2tf32(br[j].w));
        float4 bl = make_float4(f2tf32(br[j].x - bh.x), f2tf32(br[j].y - bh.y),
                                f2tf32(br[j].z - bh.z), f2tf32(br[j].w - bh.w));
        *(float4*)&Ah[0][rbase*MS + cb + j*4] = ah;
        *(float4*)&Al[0][rbase*MS + cb + j*4] = al;
        *(float4*)&Bh[0][rbase*MS + cb + j*4] = bh;
        *(float4*)&Bl[0][rbase*MS + cb + j*4] = bl;
    }
    __syncthreads();

    int nc = K / 32;
    for (int c = 0; c < nc; c++) {
        int buf = c & 1;
        if (c + 1 < nc) {
            int k0 = (c + 1) * 32;
            #pragma unroll
            for (int j = 0; j < 4; j++) {
                ar[j] = *(const float4*)&A [(size_t)(bm + rbase) * K + k0 + cb + j*4];
                br[j] = *(const float4*)&BT[(size_t)(bn + rbase) * K + k0 + cb + j*4];
            }
        }
        const float* ah_s = Ah[buf]; const float* al_s = Al[buf];
        const float* bh_s = Bh[buf]; const float* bl_s = Bl[buf];
        #pragma unroll
        for (int ks = 0; ks < 4; ks++) {
            int kk = ks*8 + (lane & 3);
            int rq = lane >> 2;
            uint32_t afh[2][4], afl[2][4];
            #pragma unroll
            for (int fm = 0; fm < 2; fm++) {
                int r0 = wm + fm*16 + rq;
                afh[fm][0] = __float_as_uint(ah_s[ r0     *MS + kk    ]);
                afh[fm][1] = __float_as_uint(ah_s[(r0 + 8)*MS + kk    ]);
                afh[fm][2] = __float_as_uint(ah_s[ r0     *MS + kk + 4]);
                afh[fm][3] = __float_as_uint(ah_s[(r0 + 8)*MS + kk + 4]);
                afl[fm][0] = __float_as_uint(al_s[ r0     *MS + kk    ]);
                afl[fm][1] = __float_as_uint(al_s[(r0 + 8)*MS + kk    ]);
                afl[fm][2] = __float_as_uint(al_s[ r0     *MS + kk + 4]);
                afl[fm][3] = __float_as_uint(al_s[(r0 + 8)*MS + kk + 4]);
            }
            #pragma unroll
            for (int fn = 0; fn < 8; fn++) {
                int n0 = wn + fn*8 + rq;
                uint32_t bfh[2] = { __float_as_uint(bh_s[n0*MS + kk]),
                                    __float_as_uint(bh_s[n0*MS + kk + 4]) };
                uint32_t bfl[2] = { __float_as_uint(bl_s[n0*MS + kk]),
                                    __float_as_uint(bl_s[n0*MS + kk + 4]) };
                #pragma unroll
                for (int fm = 0; fm < 2; fm++) {
                    MMA_TF32(d[fm][fn], afh[fm], bfh);
                    MMA_TF32(d[fm][fn], afl[fm], bfh);
                    MMA_TF32(d[fm][fn], afh[fm], bfl);
                }
            }
        }
        if (c + 1 < nc) {
            int nb = (c + 1) & 1;
            #pragma unroll
            for (int j = 0; j < 4; j++) {
                float4 ah = make_float4(f2tf32(ar[j].x), f2tf32(ar[j].y), f2tf32(ar[j].z), f2tf32(ar[j].w));
                float4 al = make_float4(f2tf32(ar[j].x - ah.x), f2tf32(ar[j].y - ah.y),
                                        f2tf32(ar[j].z - ah.z), f2tf32(ar[j].w - ah.w));
                float4 bh = make_float4(f2tf32(br[j].x), f2tf32(br[j].y), f2tf32(br[j].z), f2tf32(br[j].w));
                float4 bl = make_float4(f2tf32(br[j].x - bh.x), f2tf32(br[j].y - bh.y),
                                        f2tf32(br[j].z - bh.z), f2tf32(br[j].w - bh.w));
                *(float4*)&Ah[nb][rbase*MS + cb + j*4] = ah;
                *(float4*)&Al[nb][rbase*MS + cb + j*4] = al;
                *(float4*)&Bh[nb][rbase*MS + cb + j*4] = bh;
                *(float4*)&Bl[nb][rbase*MS + cb + j*4] = bl;
            }
        }
        __syncthreads();
    }

    #pragma unroll
    for (int fm = 0; fm < 2; fm++) {
        #pragma unroll
        for (int fn = 0; fn < 8; fn++) {
            int r  = bm + wm + fm*16 + (lane >> 2);
            int cc = bn + wn + fn*8 + 2*(lane & 3);
            *(float2*)&C[(size_t)r*N + cc]       = make_float2(d[fm][fn][0], d[fm][fn][1]);
            *(float2*)&C[(size_t)(r + 8)*N + cc] = make_float2(d[fm][fn][2], d[fm][fn][3]);
        }
    }
}

// ---------------- attention v3: mma.sync tiles ------------------------------
// PRECISE (layer1): 3xTF32 QK both passes; MASKED (layer2): plain + tile skip.
#define AS 68
template<bool PRECISE, bool MASKED>
__global__ __launch_bounds__(256)
void attn3_kernel(const float* __restrict__ qkv, const int* __restrict__ ids,
                  float* __restrict__ ctx, float* __restrict__ part)
{
    extern __shared__ float smf[];
    float* Qh = smf;                  // [64][AS] natural
    float* Kh = Qh + 64*AS;           // [64][AS] natural
    float* Vt = Kh + 64*AS;           // [64][AS] transposed Vt[c][j]
    float* Ps = Vt + 64*AS;           // [64][AS] scores/probs [i][j]
    float* Ql = Ps + 64*AS;           // PRECISE only
    float* Kl = Ql + 64*AS;
    float* ms = smf + (PRECISE ? 6 : 4)*64*AS;
    float* ls = ms + 64;
    int*   qid = (int*)(ls + 64);
    int*   kid = qid + 64;

    int qt = blockIdx.x, h = blockIdx.y, b = blockIdx.z;
    int tid = threadIdx.x, lane = tid & 31, w = tid >> 5;
    int q0 = qt * 64;
    const float scale = 0.125f;

    const float* Qp = qkv;
    const float* Kp = qkv + (size_t)BT_*D_;
    const float* Vp = qkv + (size_t)2*BT_*D_;

    int lrow = tid >> 2, le0 = (tid & 3) * 16;
    int m0 = (w >> 1) * 16, n0 = (w & 1) * 32;
    int rq = lane >> 2, cq = lane & 3;

    // load Q (+ qid)
    {
        const float* src = Qp + (size_t)(b*T_ + q0 + lrow) * D_ + h*DH_ + le0;
        #pragma unroll
        for (int u = 0; u < 4; u++) {
            float4 v = *(const float4*)(src + u*4);
            if (PRECISE) {
                float4 hv = make_float4(f2tf32(v.x), f2tf32(v.y), f2tf32(v.z), f2tf32(v.w));
                float4 lv = make_float4(f2tf32(v.x - hv.x), f2tf32(v.y - hv.y),
                                        f2tf32(v.z - hv.z), f2tf32(v.w - hv.w));
                *(float4*)&Qh[lrow*AS + le0 + u*4] = hv;
                *(float4*)&Ql[lrow*AS + le0 + u*4] = lv;
            } else {
                *(float4*)&Qh[lrow*AS + le0 + u*4] = v;
            }
        }
        if (MASKED && tid < 64) qid[tid] = ids[b*T_ + q0 + tid];
    }
    __syncthreads();
    int qid0 = 0, qidL = 0;
    if (MASKED) { qid0 = qid[0]; qidL = qid[63]; }

    // ================= pass 1 =================
    float m = -1e30f, l = 0.f;
    int sr = tid >> 2, seg = tid & 3;

    for (int kt = 0; kt < 16; kt++) {
        int k0 = kt * 64;
        if (MASKED && tid < 64) kid[tid] = ids[b*T_ + k0 + tid];
        __syncthreads();
        if (MASKED) { if (kid[63] < qid0 || qidL < kid[0]) continue; }
        {
            const float* src = Kp + (size_t)(b*T_ + k0 + lrow) * D_ + h*DH_ + le0;
            #pragma unroll
            for (int u = 0; u < 4; u++) {
                float4 v = *(const float4*)(src + u*4);
                if (PRECISE) {
                    float4 hv = make_float4(f2tf32(v.x), f2tf32(v.y), f2tf32(v.z), f2tf32(v.w));
                    float4 lv = make_float4(f2tf32(v.x - hv.x), f2tf32(v.y - hv.y),
                                            f2tf32(v.z - hv.z), f2tf32(v.w - hv.w));
                    *(float4*)&Kh[lrow*AS + le0 + u*4] = hv;
                    *(float4*)&Kl[lrow*AS + le0 + u*4] = lv;
                } else {
                    *(float4*)&Kh[lrow*AS + le0 + u*4] = v;
                }
            }
        }
        __syncthreads();
        // QK mma: warp tile 16x32 (1 m-frag x 4 n-frags), k=64 (8 steps)
        float dq[4][4];
        #pragma unroll
        for (int fn = 0; fn < 4; fn++)
            #pragma unroll
            for (int u = 0; u < 4; u++) dq[fn][u] = 0.f;
        #pragma unroll
        for (int ks = 0; ks < 8; ks++) {
            int kk = ks*8 + cq;
            int arr = m0 + rq;
            uint32_t ah[4] = { __float_as_uint(Qh[ arr   *AS + kk]),
                               __float_as_uint(Qh[(arr+8)*AS + kk]),
                               __float_as_uint(Qh[ arr   *AS + kk + 4]),
                               __float_as_uint(Qh[(arr+8)*AS + kk + 4]) };
            #pragma unroll
            for (int fn = 0; fn < 4; fn++) {
                int bnr = n0 + fn*8 + rq;
                uint32_t bh[2] = { __float_as_uint(Kh[bnr*AS + kk]),
                                   __float_as_uint(Kh[bnr*AS + kk + 4]) };
                MMA_TF32(dq[fn], ah, bh);
                if (PRECISE) {
                    uint32_t al[4] = { __float_as_uint(Ql[ arr   *AS + kk]),
                                       __float_as_uint(Ql[(arr+8)*AS + kk]),
                                       __float_as_uint(Ql[ arr   *AS + kk + 4]),
                                       __float_as_uint(Ql[(arr+8)*AS + kk + 4]) };
                    uint32_t bl[2] = { __float_as_uint(Kl[bnr*AS + kk]),
                                       __float_as_uint(Kl[bnr*AS + kk + 4]) };
                    MMA_TF32(dq[fn], al, bh);
                    MMA_TF32(dq[fn], ah, bl);
                }
            }
        }
        // write scores (scale + mask)
        #pragma unroll
        for (int fn = 0; fn < 4; fn++) {
            int i0 = m0 + rq, j0 = n0 + fn*8 + 2*cq;
            float s0 = dq[fn][0]*scale, s1 = dq[fn][1]*scale;
            float s2 = dq[fn][2]*scale, s3 = dq[fn][3]*scale;
            if (MASKED) {
                int qa = qid[i0], qb = qid[i0+8], ka = kid[j0], kb = kid[j0+1];
                if (qa != ka) s0 = -1e30f;
                if (qa != kb) s1 = -1e30f;
                if (qb != ka) s2 = -1e30f;
                if (qb != kb) s3 = -1e30f;
            }
            Ps[ i0   *AS + j0]     = s0;
            Ps[ i0   *AS + j0 + 1] = s1;
            Ps[(i0+8)*AS + j0]     = s2;
            Ps[(i0+8)*AS + j0 + 1] = s3;
        }
        __syncthreads();
        // row stats (4 threads per row, contiguous 16)
        {
            float sv[16]; float tm = -1e30f;
            #pragma unroll
            for (int u = 0; u < 4; u++) {
                float4 v = *(const float4*)&Ps[sr*AS + seg*16 + u*4];
                sv[u*4+0] = v.x; sv[u*4+1] = v.y; sv[u*4+2] = v.z; sv[u*4+3] = v.w;
                tm = fmaxf(tm, fmaxf(fmaxf(v.x, v.y), fmaxf(v.z, v.w)));
            }
            tm = fmaxf(tm, __shfl_xor_sync(0xffffffffu, tm, 1));
            tm = fmaxf(tm, __shfl_xor_sync(0xffffffffu, tm, 2));
            float nm = fmaxf(m, tm);
            float es = 0.f;
            #pragma unroll
            for (int it = 0; it < 16; it++) es += __expf(sv[it] - nm);
            es += __shfl_xor_sync(0xffffffffu, es, 1);
            es += __shfl_xor_sync(0xffffffffu, es, 2);
            l = l * __expf(m - nm) + es;
            m = nm;
        }
    }
    __syncthreads();
    if (seg == 0) { ms[sr] = m; ls[sr] = 1.f / l; }
    __syncthreads();

    // ================= pass 2 =================
    float pacc[4][4];
    #pragma unroll
    for (int fn = 0; fn < 4; fn++)
        #pragma unroll
        for (int u = 0; u < 4; u++) pacc[fn][u] = 0.f;

    for (int kt = 0; kt < 16; kt++) {
        int k0 = kt * 64;
        if (MASKED && tid < 64) kid[tid] = ids[b*T_ + k0 + tid];
        __syncthreads();
        if (MASKED) {
            if (kid[63] < qid0 || qidL < kid[0]) {
                if (tid < 64)
                    part[((size_t)((b*H_ + h)*16 + qt))*T_ + k0 + tid] = 0.f;
                continue;
            }
        }
        {
            const float* ksrc = Kp + (size_t)(b*T_ + k0 + lrow) * D_ + h*DH_ + le0;
            #pragma unroll
            for (int u = 0; u < 4; u++) {
                float4 v = *(const float4*)(ksrc + u*4);
                if (PRECISE) {
                    float4 hv = make_float4(f2tf32(v.x), f2tf32(v.y), f2tf32(v.z), f2tf32(v.w));
                    float4 lv = make_float4(f2tf32(v.x - hv.x), f2tf32(v.y - hv.y),
                                            f2tf32(v.z - hv.z), f2tf32(v.w - hv.w));
                    *(float4*)&Kh[lrow*AS + le0 + u*4] = hv;
                    *(float4*)&Kl[lrow*AS + le0 + u*4] = lv;
                } else {
                    *(float4*)&Kh[lrow*AS + le0 + u*4] = v;
                }
            }
            const float* vsrc = Vp + (size_t)(b*T_ + k0 + lrow) * D_ + h*DH_ + le0;
            #pragma unroll
            for (int u = 0; u < 4; u++) {
                float4 v = *(const float4*)(vsrc + u*4);
                Vt[(le0 + u*4 + 0)*AS + lrow] = v.x;
                Vt[(le0 + u*4 + 1)*AS + lrow] = v.y;
                Vt[(le0 + u*4 + 2)*AS + lrow] = v.z;
                Vt[(le0 + u*4 + 3)*AS + lrow] = v.w;
            }
        }
        __syncthreads();
        // QK mma (same as pass1)
        float dq[4][4];
        #pragma unroll
        for (int fn = 0; fn < 4; fn++)
            #pragma unroll
            for (int u = 0; u < 4; u++) dq[fn][u] = 0.f;
        #pragma unroll
        for (int ks = 0; ks < 8; ks++) {
            int kk = ks*8 + cq;
            int arr = m0 + rq;
            uint32_t ah[4] = { __float_as_uint(Qh[ arr   *AS + kk]),
                               __float_as_uint(Qh[(arr+8)*AS + kk]),
                               __float_as_uint(Qh[ arr   *AS + kk + 4]),
                               __float_as_uint(Qh[(arr+8)*AS + kk + 4]) };
            #pragma unroll
            for (int fn = 0; fn < 4; fn++) {
                int bnr = n0 + fn*8 + rq;
                uint32_t bh[2] = { __float_as_uint(Kh[bnr*AS + kk]),
                                   __float_as_uint(Kh[bnr*AS + kk + 4]) };
                MMA_TF32(dq[fn], ah, bh);
                if (PRECISE) {
                    uint32_t al[4] = { __float_as_uint(Ql[ arr   *AS + kk]),
                                       __float_as_uint(Ql[(arr+8)*AS + kk]),
                                       __float_as_uint(Ql[ arr   *AS + kk + 4]),
                                       __float_as_uint(Ql[(arr+8)*AS + kk + 4]) };
                    uint32_t bl[2] = { __float_as_uint(Kl[bnr*AS + kk]),
                                       __float_as_uint(Kl[bnr*AS + kk + 4]) };
                    MMA_TF32(dq[fn], al, bh);
                    MMA_TF32(dq[fn], ah, bl);
                }
            }
        }
        // write probs
        #pragma unroll
        for (int fn = 0; fn < 4; fn++) {
            int i0 = m0 + rq, j0 = n0 + fn*8 + 2*cq;
            float ma = ms[i0], la = ls[i0];
            float mb = ms[i0+8], lb = ls[i0+8];
            float p0 = __expf(dq[fn][0]*scale - ma) * la;
            float p1 = __expf(dq[fn][1]*scale - ma) * la;
            float p2 = __expf(dq[fn][2]*scale - mb) * lb;
            float p3 = __expf(dq[fn][3]*scale - mb) * lb;
            if (MASKED) {
                int qa = qid[i0], qb = qid[i0+8], ka = kid[j0], kb = kid[j0+1];
                if (qa != ka) p0 = 0.f;
                if (qa != kb) p1 = 0.f;
                if (qb != ka) p2 = 0.f;
                if (qb != kb) p3 = 0.f;
            }
            Ps[ i0   *AS + j0]     = p0;
            Ps[ i0   *AS + j0 + 1] = p1;
            Ps[(i0+8)*AS + j0]     = p2;
            Ps[(i0+8)*AS + j0 + 1] = p3;
        }
        __syncthreads();
        // fp64 column sums (decision-critical)
        if (tid < 64) {
            double cs = 0.0;
            #pragma unroll
            for (int i = 0; i < 64; i++) cs += (double)Ps[i*AS + tid];
            part[((size_t)((b*H_ + h)*16 + qt))*T_ + k0 + tid] = (float)cs;
        }
        // PV mma: A=Ps rows, B=Vt (col-major over j)
        #pragma unroll
        for (int ks = 0; ks < 8; ks++) {
            int kk = ks*8 + cq;
            int arr = m0 + rq;
            uint32_t ap[4] = { __float_as_uint(Ps[ arr   *AS + kk]),
                               __float_as_uint(Ps[(arr+8)*AS + kk]),
                               __float_as_uint(Ps[ arr   *AS + kk + 4]),
                               __float_as_uint(Ps[(arr+8)*AS + kk + 4]) };
            #pragma unroll
            for (int fn = 0; fn < 4; fn++) {
                int bnr = n0 + fn*8 + rq;
                uint32_t bv[2] = { __float_as_uint(Vt[bnr*AS + kk]),
                                   __float_as_uint(Vt[bnr*AS + kk + 4]) };
                MMA_TF32(pacc[fn], ap, bv);
            }
        }
    }
    // write ctx
    #pragma unroll
    for (int fn = 0; fn < 4; fn++) {
        int r  = b*T_ + q0 + m0 + rq;
        int cc = h*DH_ + n0 + fn*8 + 2*cq;
        *(float2*)&ctx[(size_t)r*D_ + cc]       = make_float2(pacc[fn][0], pacc[fn][1]);
        *(float2*)&ctx[(size_t)(r+8)*D_ + cc]   = make_float2(pacc[fn][2], pacc[fn][3]);
    }
}

// ---------------- deterministic fp64 reduction of prob column sums ---------
__global__ void reduce_part_kernel(const float* __restrict__ part, double* __restrict__ wsum)
{
    int idx = blockIdx.x * 256 + threadIdx.x;
    int b = idx >> 10, j = idx & 1023;
    double s = 0.0;
    for (int g = 0; g < H_*16; g++)
        s += (double)part[((size_t)(b*H_*16 + g)) * T_ + j];
    wsum[idx] = s;
}

// ---------------- y = LayerNorm(x + r), row = 512 ---------------------------
__global__ void add_ln_kernel(const float* __restrict__ x, const float* __restrict__ r,
                              float* __restrict__ y)
{
    __shared__ float sm[256];
    int row = blockIdx.x, tid = threadIdx.x;
    size_t base = (size_t)row * D_;
    float v0 = x[base + tid]        + r[base + tid];
    float v1 = x[base + 256 + tid]  + r[base + 256 + tid];
    sm[tid] = v0 + v1; __syncthreads();
    for (int s = 128; s > 0; s >>= 1) { if (tid < s) sm[tid] += sm[tid + s]; __syncthreads(); }
    float mean = sm[0] * (1.f / D_); __syncthreads();
    float d0 = v0 - mean, d1 = v1 - mean;
    sm[tid] = d0*d0 + d1*d1; __syncthreads();
    for (int s = 128; s > 0; s >>= 1) { if (tid < s) sm[tid] += sm[tid + s]; __syncthreads(); }
    float var = sm[0] * (1.f / D_);
    float inv = 1.f / sqrtf(var + 1e-5f);
    y[base + tid]       = d0 * inv;
    y[base + 256 + tid] = d1 * inv;
}

// ---------------- window-id scan (exact replica of reference scan, fp64) ----
__global__ void scan_kernel(const double* __restrict__ wsum, int* __restrict__ ids,
                            int* __restrict__ ws, int* __restrict__ we)
{
    __shared__ double smn[256], smx[256];
    int b = blockIdx.x, tid = threadIdx.x;
    double mn = 1e300, mx = -1e300;
    for (int t = tid; t < T_; t += 256) {
        double v = wsum[b*T_ + t] * (1.0 / H_);
        mn = fmin(mn, v); mx = fmax(mx, v);
    }
    smn[tid] = mn; smx[tid] = mx; __syncthreads();
    for (int s = 128; s > 0; s >>= 1) {
        if (tid < s) { smn[tid] = fmin(smn[tid], smn[tid+s]); smx[tid] = fmax(smx[tid], smx[tid+s]); }
        __syncthreads();
    }
    for (int t = tid; t < T_; t += 256) { ws[b*T_ + t] = 0; we[b*T_ + t] = 0; }
    __syncthreads();
    if (tid == 0) {
        double MN = smn[0], MX = smx[0];
        double denom = MX - MN + 1e-8;
        double thr = MN + 0.5 * denom;
        int cur = (wsum[b*T_ + 0] * (1.0 / H_)) >= thr ? 1 : 0;
        int start = 0, wid = 0;
        ids[b*T_ + 0] = 0;
        for (int t = 1; t < T_; t++) {
            int wt = (wsum[b*T_ + t] * (1.0 / H_)) >= thr ? 1 : 0;
            if (wt == cur) {
            } else if (start + 1 == t) {
                cur = wt;
            } else {
                cur = wt; start = t; wid++;
            }
            ids[b*T_ + t] = wid;
        }
        int prev = -1;
        for (int t = 0; t < T_; t++) {
            int w = ids[b*T_ + t];
            if (w != prev) { ws[b*T_ + w] = t; prev = w; }
            we[b*T_ + w] = t + 1;
        }
    }
}

// ---------------- wl = softmax_j(wsum/H) ------------------------------------
__global__ void wl_softmax_kernel(const double* __restrict__ wsum, float* __restrict__ wl)
{
    __shared__ float sm[256];
    int b = blockIdx.x, tid = threadIdx.x;
    float vals[4];
    float mx = -1e30f;
    #pragma unroll
    for (int i = 0; i < 4; i++) {
        vals[i] = (float)(wsum[b*T_ + tid + i*256] * (1.0 / H_));
        mx = fmaxf(mx, vals[i]);
    }
    sm[tid] = mx; __syncthreads();
    for (int s = 128; s > 0; s >>= 1) { if (tid < s) sm[tid] = fmaxf(sm[tid], sm[tid+s]); __syncthreads(); }
    float M = sm[0]; __syncthreads();
    float e[4], acc = 0.f;
    #pragma unroll
    for (int i = 0; i < 4; i++) { e[i] = expf(vals[i] - M); acc += e[i]; }
    sm[tid] = acc; __syncthreads();
    for (int s = 128; s > 0; s >>= 1) { if (tid < s) sm[tid] += sm[tid+s]; __syncthreads(); }
    float inv = 1.f / sm[0];
    #pragma unroll
    for (int i = 0; i < 4; i++) wl[b*T_ + tid + i*256] = e[i] * inv;
}

// ---------------- window-weighted pooling (deterministic gather) ------------
__global__ void word_tokens_kernel(const float* __restrict__ outl, const float* __restrict__ wl,
                                   const int* __restrict__ ws, const int* __restrict__ we,
                                   float* __restrict__ out)
{
    int w = blockIdx.x, b = blockIdx.y, tid = threadIdx.x;
    int s = ws[b*T_ + w], e = we[b*T_ + w];
    float acc[4] = {0.f, 0.f, 0.f, 0.f};
    for (int t = s; t < e; t++) {
        float g = wl[b*T_ + t];
        const float* row = outl + (size_t)(b*T_ + t) * D_;
        #pragma unroll
        for (int u = 0; u < 4; u++) acc[u] += g * row[tid + u*128];
    }
    float* dst = out + ((size_t)(b*2*T_ + w)) * D_;
    #pragma unroll
    for (int u = 0; u < 4; u++) dst[tid + u*128] = acc[u];
}

// ---------------- copy x into second half of concat output ------------------
__global__ void copy_x_kernel(const float* __restrict__ x, float* __restrict__ out)
{
    int idx = blockIdx.x * 256 + threadIdx.x;
    int b = (idx * 4) / (T_*D_);
    float4 v = *(const float4*)&x[(size_t)idx * 4];
    *(float4*)&out[(size_t)idx * 4 + (size_t)(b + 1) * T_ * D_] = v;
}

// ---------------- window_mapping output -------------------------------------
__global__ void winmap_kernel(const int* __restrict__ ids, float* __restrict__ out2)
{
    int idx = blockIdx.x * 256 + threadIdx.x;
    int e0 = idx * 4;
    int b = e0 >> 20;
    int k = (e0 >> 10) & 1023;
    int j = e0 & 1023;
    const int* idr = ids + b*T_;
    float4 v;
    v.x = (idr[j+0] == k) ? 1.f : 0.f;
    v.y = (idr[j+1] == k) ? 1.f : 0.f;
    v.z = (idr[j+2] == k) ? 1.f : 0.f;
    v.w = (idr[j+3] == k) ? 1.f : 0.f;
    *(float4*)&out2[(size_t)e0] = v;
}

// ---------------- host launcher ---------------------------------------------
#define SMEM_A3P (6*64*AS*4 + 1024)
#define SMEM_A3  (4*64*AS*4 + 1024)

extern "C" void kernel_launch(void* const* d_in, const int* in_sizes, int n_in,
                              void* d_out, int out_size)
{
    const float* x       = (const float*)d_in[0];
    const float* v_qkv_w = (const float*)d_in[1];
    const float* v_out_w = (const float*)d_in[2];
    const float* v_w1    = (const float*)d_in[3];
    const float* v_w2    = (const float*)d_in[4];
    const float* l_qkv_w = (const float*)d_in[5];
    const float* l_out_w = (const float*)d_in[6];
    const float* l_w1    = (const float*)d_in[7];
    const float* l_w2    = (const float*)d_in[8];
    float* out = (float*)d_out;

    float *qkv, *ctx, *tmp, *h1, *ffn, *outv, *outl, *part, *wl, *wT;
    double *wsum;
    int *ids, *ws, *we;
    cudaGetSymbolAddress((void**)&qkv,  g_qkv);
    cudaGetSymbolAddress((void**)&ctx,  g_ctx);
    cudaGetSymbolAddress((void**)&tmp,  g_tmp);
    cudaGetSymbolAddress((void**)&h1,   g_h1);
    cudaGetSymbolAddress((void**)&ffn,  g_ffn);
    cudaGetSymbolAddress((void**)&outv, g_outv);
    cudaGetSymbolAddress((void**)&outl, g_outl);
    cudaGetSymbolAddress((void**)&part, g_part);
    cudaGetSymbolAddress((void**)&wsum, g_wsum);
    cudaGetSymbolAddress((void**)&wl,   g_wl);
    cudaGetSymbolAddress((void**)&ids,  g_ids);
    cudaGetSymbolAddress((void**)&ws,   g_ws);
    cudaGetSymbolAddress((void**)&we,   g_we);
    cudaGetSymbolAddress((void**)&wT,   g_wT);

    cudaFuncSetAttribute(gemm_mma_kernel,  cudaFuncAttributeMaxDynamicSharedMemorySize, GM_SMEM);
    cudaFuncSetAttribute(gemm_mma3_kernel, cudaFuncAttributeMaxDynamicSharedMemorySize, G3_SMEM);
    cudaFuncSetAttribute((const void*)attn3_kernel<true,false>,  cudaFuncAttributeMaxDynamicSharedMemorySize, SMEM_A3P);
    cudaFuncSetAttribute((const void*)attn3_kernel<false,true>,  cudaFuncAttributeMaxDynamicSharedMemorySize, SMEM_A3);

    // ===== transpose all weights ====
    transpose_kernel<<<dim3(D_/32,  D_/32), dim3(32,8)>>>(v_qkv_w,            wT + WT_VQKV,            D_,  D_);
    transpose_kernel<<<dim3(D_/32,  D_/32), dim3(32,8)>>>(v_qkv_w + D_*D_,    wT + WT_VQKV + D_*D_,    D_,  D_);
    transpose_kernel<<<dim3(D_/32,  D_/32), dim3(32,8)>>>(v_qkv_w + 2*D_*D_,  wT + WT_VQKV + 2*D_*D_,  D_,  D_);
    transpose_kernel<<<dim3(D_/32,  D_/32), dim3(32,8)>>>(l_qkv_w,            wT + WT_LQKV,            D_,  D_);
    transpose_kernel<<<dim3(D_/32,  D_/32), dim3(32,8)>>>(l_qkv_w + D_*D_,    wT + WT_LQKV + D_*D_,    D_,  D_);
    transpose_kernel<<<dim3(D_/32,  D_/32), dim3(32,8)>>>(l_qkv_w + 2*D_*D_,  wT + WT_LQKV + 2*D_*D_,  D_,  D_);
    transpose_kernel<<<dim3(D_/32,  D_/32), dim3(32,8)>>>(v_out_w, wT + WT_VOUT, D_,  D_);
    transpose_kernel<<<dim3(D_/32,  D_/32), dim3(32,8)>>>(l_out_w, wT + WT_LOUT, D_,  D_);
    transpose_kernel<<<dim3(FF_/32, D_/32), dim3(32,8)>>>(v_w1,    wT + WT_VW1,  D_,  FF_);
    transpose_kernel<<<dim3(FF_/32, D_/32), dim3(32,8)>>>(l_w1,    wT + WT_LW1,  D_,  FF_);
    transpose_kernel<<<dim3(D_/32, FF_/32), dim3(32,8)>>>(v_w2,    wT + WT_VW2,  FF_, D_);
    transpose_kernel<<<dim3(D_/32, FF_/32), dim3(32,8)>>>(l_w2,    wT + WT_LW2,  FF_, D_);

    dim3 gAttn(T_/64, H_, B_);
    dim3 gtD(D_/128, BT_/128, 1);
    dim3 gtF1(FF_/128, BT_/128, 1);
    dim3 gtQKV(D_/128, BT_/128, 3);

    // ===== layer 1 (vanilla) =====
    gemm_mma3_kernel<<<gtQKV, 256, G3_SMEM>>>(x, wT + WT_VQKV, qkv, D_, D_,
                                              (long long)D_*D_, (long long)BT_*D_);
    attn3_kernel<true,false><<<gAttn, 256, SMEM_A3P>>>(qkv, nullptr, ctx, part);
    reduce_part_kernel<<<(B_*T_)/256, 256>>>(part, wsum);
    gemm_mma_kernel<<<gtD, 128, GM_SMEM>>>(ctx, wT + WT_VOUT, tmp, D_, D_, 0, 0, 0);
    add_ln_kernel<<<BT_, 256>>>(x, tmp, h1);
    gemm_mma_kernel<<<gtF1, 128, GM_SMEM>>>(h1, wT + WT_VW1, ffn, FF_, D_, 0, 0, 1);
    gemm_mma_kernel<<<gtD, 128, GM_SMEM>>>(ffn, wT + WT_VW2, tmp, D_, FF_, 0, 0, 0);
    add_ln_kernel<<<BT_, 256>>>(h1, tmp, outv);

    // ===== dynamic window mask =====
    scan_kernel<<<B_, 256>>>(wsum, ids, ws, we);

    // ===== layer 2 (masked) =====
    gemm_mma_kernel<<<gtQKV, 128, GM_SMEM>>>(outv, wT + WT_LQKV, qkv, D_, D_,
                                             (long long)D_*D_, (long long)BT_*D_, 0);
    attn3_kernel<false,true><<<gAttn, 256, SMEM_A3>>>(qkv, ids, ctx, part);
    reduce_part_kernel<<<(B_*T_)/256, 256>>>(part, wsum);
    gemm_mma_kernel<<<gtD, 128, GM_SMEM>>>(ctx, wT + WT_LOUT, tmp, D_, D_, 0, 0, 0);
    add_ln_kernel<<<BT_, 256>>>(outv, tmp, h1);
    gemm_mma_kernel<<<gtF1, 128, GM_SMEM>>>(h1, wT + WT_LW1, ffn, FF_, D_, 0, 0, 1);
    gemm_mma_kernel<<<gtD, 128, GM_SMEM>>>(ffn, wT + WT_LW2, tmp, D_, FF_, 0, 0, 0);
    add_ln_kernel<<<BT_, 256>>>(h1, tmp, outl);

    // ===== outputs =====
    wl_softmax_kernel<<<B_, 256>>>(wsum, wl);
    word_tokens_kernel<<<dim3(T_, B_), 128>>>(outl, wl, ws, we, out);
    copy_x_kernel<<<(B_*T_*D_/4)/256, 256>>>(x, out);
    winmap_kernel<<<(B_*T_*T_/4)/256, 256>>>(ids, out + (size_t)B_*2*T_*D_);
}

// round 7
// speedup vs baseline: 4.6188x; 1.1707x over previous
#include <cuda_runtime.h>
#include <cuda_bf16.h>
#include <math.h>
#include <stdint.h>

// Problem constants
#define B_  8
#define T_  1024
#define D_  512
#define FF_ 2048
#define H_  8
#define DH_ 64
#define BT_ (B_*T_)          // 8192 rows

// ---------------- scratch (device globals; no allocation allowed) ----------
__device__ float  g_qkv [3*BT_*D_];
__device__ float  g_ctx [BT_*D_];
__device__ float  g_tmp [BT_*D_];
__device__ float  g_h1  [BT_*D_];
__device__ float  g_ffn [BT_*FF_];
__device__ float  g_outv[BT_*D_];
__device__ float  g_outl[BT_*D_];
__device__ float  g_part[B_*H_*16*T_];
__device__ double g_wsum[B_*T_];
__device__ float  g_wl  [B_*T_];
__device__ int    g_ids [B_*T_];
__device__ int    g_ws  [B_*T_];
__device__ int    g_we  [B_*T_];
__device__ float  g_wT  [6291456];      // transposed weights
__device__ float  g_scores[(size_t)B_*H_*T_*T_];  // layer-1 score cache (256MB)

// transposed-weight offsets (floats)
#define WT_LQKV 0
#define WT_VOUT 786432
#define WT_LOUT 1048576
#define WT_VW1  1310720
#define WT_LW1  2359296
#define WT_VW2  3407872
#define WT_LW2  4456448
#define WT_VQKV 5505024

// ---------------- tf32 helpers ----------------------------------------------
__device__ __forceinline__ float f2tf32(float x) {
    uint32_t u;
    asm("cvt.rna.tf32.f32 %0, %1;" : "=r"(u) : "f"(x));
    return __uint_as_float(u);
}
#define MMA_TF32(d, a, b) \
    asm volatile("mma.sync.aligned.m16n8k8.row.col.f32.tf32.tf32.f32 " \
        "{%0,%1,%2,%3}, {%4,%5,%6,%7}, {%8,%9}, {%0,%1,%2,%3};" \
        : "+f"((d)[0]), "+f"((d)[1]), "+f"((d)[2]), "+f"((d)[3]) \
        : "r"((a)[0]), "r"((a)[1]), "r"((a)[2]), "r"((a)[3]), \
          "r"((b)[0]), "r"((b)[1]))
#define MMA_BF16(d, a, b) \
    asm volatile("mma.sync.aligned.m16n8k16.row.col.f32.bf16.bf16.f32 " \
        "{%0,%1,%2,%3}, {%4,%5,%6,%7}, {%8,%9}, {%0,%1,%2,%3};" \
        : "+f"((d)[0]), "+f"((d)[1]), "+f"((d)[2]), "+f"((d)[3]) \
        : "r"((a)[0]), "r"((a)[1]), "r"((a)[2]), "r"((a)[3]), \
          "r"((b)[0]), "r"((b)[1]))

__device__ __forceinline__ uint32_t pack_bf16x2(float lo, float hi) {
    __nv_bfloat162 h = __float22bfloat162_rn(make_float2(lo, hi));
    return *(uint32_t*)&h;
}

// ---------------- batched weight transpose ----------------------------------
__global__ void transpose_all_kernel(
    const float* __restrict__ vqkv, const float* __restrict__ lqkv,
    const float* __restrict__ vout, const float* __restrict__ lout,
    const float* __restrict__ vw1,  const float* __restrict__ lw1,
    const float* __restrict__ vw2,  const float* __restrict__ lw2,
    float* __restrict__ wT)
{
    __shared__ float t[32][33];
    int bid = blockIdx.x;
    int task, local;
    if (bid < 2048) { task = bid >> 8; local = bid & 255; }
    else { int r = bid - 2048; task = 8 + (r >> 10); local = r & 1023; }
    const float* src; float* dst; int R, C;
    switch (task) {
        case 0:  src = vqkv;           dst = wT + WT_VQKV;           R = 512;  C = 512;  break;
        case 1:  src = vqkv + 262144;  dst = wT + WT_VQKV + 262144;  R = 512;  C = 512;  break;
        case 2:  src = vqkv + 524288;  dst = wT + WT_VQKV + 524288;  R = 512;  C = 512;  break;
        case 3:  src = lqkv;           dst = wT + WT_LQKV;           R = 512;  C = 512;  break;
        case 4:  src = lqkv + 262144;  dst = wT + WT_LQKV + 262144;  R = 512;  C = 512;  break;
        case 5:  src = lqkv + 524288;  dst = wT + WT_LQKV + 524288;  R = 512;  C = 512;  break;
        case 6:  src = vout;           dst = wT + WT_VOUT;           R = 512;  C = 512;  break;
        case 7:  src = lout;           dst = wT + WT_LOUT;           R = 512;  C = 512;  break;
        case 8:  src = vw1;            dst = wT + WT_VW1;            R = 512;  C = 2048; break;
        case 9:  src = lw1;            dst = wT + WT_LW1;            R = 512;  C = 2048; break;
        case 10: src = vw2;            dst = wT + WT_VW2;            R = 2048; C = 512;  break;
        default: src = lw2;            dst = wT + WT_LW2;            R = 2048; C = 512;  break;
    }
    int nbx = C >> 5;
    int c0 = (local % nbx) * 32, r0 = (local / nbx) * 32;
    int tx = threadIdx.x, ty = threadIdx.y;
    #pragma unroll
    for (int i = 0; i < 32; i += 8)
        t[ty+i][tx] = src[(size_t)(r0+ty+i)*C + c0+tx];
    __syncthreads();
    #pragma unroll
    for (int i = 0; i < 32; i += 8)
        dst[(size_t)(c0+ty+i)*R + r0+tx] = t[tx][ty+i];
}

// ---------------- bf16 tensor GEMM (continuous path) ------------------------
// A [M][K] fp32 row-major, BT [N][K] fp32 row-major, C [M][N] fp32.
// CTA 128x128, 4 warps (64x64), K chunks of 32, bf16 m16n8k16.
#define MSB 40   // bf16 elements per smem row (32 + 8 pad -> conflict-free)
#define GB_SMEM (4 * 128 * MSB * 2)   // 2 bufs x (A+B) = 40960 bytes
__global__ __launch_bounds__(128)
void gemm_bf16_kernel(const float* __restrict__ A, const float* __restrict__ BTs,
                      float* __restrict__ Cs, int N, int K,
                      long long bt_z, long long c_z, int relu)
{
    extern __shared__ char smraw[];
    __nv_bfloat16* sb = (__nv_bfloat16*)smraw;
    __nv_bfloat16* Asm[2] = { sb,            sb + 128*MSB };
    __nv_bfloat16* Bsm[2] = { sb + 2*128*MSB, sb + 3*128*MSB };

    const float* BT = BTs + (long long)blockIdx.z * bt_z;
    float*       C  = Cs  + (long long)blockIdx.z * c_z;

    int tid = threadIdx.x, lane = tid & 31, wid = tid >> 5;
    int wm = (wid >> 1) * 64, wn = (wid & 1) * 64;
    int bm = blockIdx.y * 128, bn = blockIdx.x * 128;
    int col4 = tid & 7, rbase = tid >> 3;
    int rq = lane >> 2, cq = lane & 3;

    float d[4][8][4];
    #pragma unroll
    for (int i = 0; i < 4; i++)
        #pragma unroll
        for (int j = 0; j < 8; j++)
            #pragma unroll
            for (int u = 0; u < 4; u++) d[i][j][u] = 0.f;

    float4 ar[8], br[8];
    #pragma unroll
    for (int j = 0; j < 8; j++) {
        ar[j] = *(const float4*)&A [(size_t)(bm + rbase + j*16) * K + col4*4];
        br[j] = *(const float4*)&BT[(size_t)(bn + rbase + j*16) * K + col4*4];
    }
    #pragma unroll
    for (int j = 0; j < 8; j++) {
        int r = rbase + j*16;
        uint2 pa = make_uint2(pack_bf16x2(ar[j].x, ar[j].y), pack_bf16x2(ar[j].z, ar[j].w));
        uint2 pb = make_uint2(pack_bf16x2(br[j].x, br[j].y), pack_bf16x2(br[j].z, br[j].w));
        *(uint2*)&Asm[0][r*MSB + col4*4] = pa;
        *(uint2*)&Bsm[0][r*MSB + col4*4] = pb;
    }
    __syncthreads();

    int nc = K / 32;
    for (int c = 0; c < nc; c++) {
        int buf = c & 1;
        if (c + 1 < nc) {
            int k0 = (c + 1) * 32;
            #pragma unroll
            for (int j = 0; j < 8; j++) {
                ar[j] = *(const float4*)&A [(size_t)(bm + rbase + j*16) * K + k0 + col4*4];
                br[j] = *(const float4*)&BT[(size_t)(bn + rbase + j*16) * K + k0 + col4*4];
            }
        }
        const __nv_bfloat16* a_s = Asm[buf];
        const __nv_bfloat16* b_s = Bsm[buf];
        #pragma unroll
        for (int ks = 0; ks < 2; ks++) {
            int k2 = ks*16 + cq*2;
            uint32_t af[4][4];
            #pragma unroll
            for (int fm = 0; fm < 4; fm++) {
                int r0 = wm + fm*16 + rq;
                af[fm][0] = *(const uint32_t*)&a_s[ r0     *MSB + k2];
                af[fm][1] = *(const uint32_t*)&a_s[(r0 + 8)*MSB + k2];
                af[fm][2] = *(const uint32_t*)&a_s[ r0     *MSB + k2 + 8];
                af[fm][3] = *(const uint32_t*)&a_s[(r0 + 8)*MSB + k2 + 8];
            }
            #pragma unroll
            for (int fn = 0; fn < 8; fn++) {
                int n0 = wn + fn*8 + rq;
                uint32_t bf[2] = { *(const uint32_t*)&b_s[n0*MSB + k2],
                                   *(const uint32_t*)&b_s[n0*MSB + k2 + 8] };
                #pragma unroll
                for (int fm = 0; fm < 4; fm++)
                    MMA_BF16(d[fm][fn], af[fm], bf);
            }
        }
        if (c + 1 < nc) {
            int nb = (c + 1) & 1;
            #pragma unroll
            for (int j = 0; j < 8; j++) {
                int r = rbase + j*16;
                uint2 pa = make_uint2(pack_bf16x2(ar[j].x, ar[j].y), pack_bf16x2(ar[j].z, ar[j].w));
                uint2 pb = make_uint2(pack_bf16x2(br[j].x, br[j].y), pack_bf16x2(br[j].z, br[j].w));
                *(uint2*)&Asm[nb][r*MSB + col4*4] = pa;
                *(uint2*)&Bsm[nb][r*MSB + col4*4] = pb;
            }
        }
        __syncthreads();
    }

    #pragma unroll
    for (int fm = 0; fm < 4; fm++) {
        #pragma unroll
        for (int fn = 0; fn < 8; fn++) {
            int r  = bm + wm + fm*16 + rq;
            int cc = bn + wn + fn*8 + 2*cq;
            float2 v0 = make_float2(d[fm][fn][0], d[fm][fn][1]);
            float2 v1 = make_float2(d[fm][fn][2], d[fm][fn][3]);
            if (relu) {
                v0.x = fmaxf(v0.x, 0.f); v0.y = fmaxf(v0.y, 0.f);
                v1.x = fmaxf(v1.x, 0.f); v1.y = fmaxf(v1.y, 0.f);
            }
            *(float2*)&C[(size_t)r*N + cc]       = v0;
            *(float2*)&C[(size_t)(r + 8)*N + cc] = v1;
        }
    }
}

// ---------------- 3xTF32 GEMM (decision path: layer-1 Q/K proj) -------------
#define MS 36
#define G3_SMEM (8 * 128 * MS * 4)
__global__ __launch_bounds__(256)
void gemm_mma3_kernel(const float* __restrict__ A, const float* __restrict__ BTs,
                      float* __restrict__ Cs, int N, int K,
                      long long bt_z, long long c_z)
{
    extern __shared__ float smf[];
    float* Ah[2] = { smf,            smf + 128*MS };
    float* Al[2] = { smf + 2*128*MS, smf + 3*128*MS };
    float* Bh[2] = { smf + 4*128*MS, smf + 5*128*MS };
    float* Bl[2] = { smf + 6*128*MS, smf + 7*128*MS };

    const float* BT = BTs + (long long)blockIdx.z * bt_z;
    float*       C  = Cs  + (long long)blockIdx.z * c_z;

    int tid = threadIdx.x, lane = tid & 31, wid = tid >> 5;
    int wm = (wid >> 1) * 32, wn = (wid & 1) * 64;
    int bm = blockIdx.y * 128, bn = blockIdx.x * 128;
    int rbase = tid >> 1, cb = (tid & 1) * 16;

    float d[2][8][4];
    #pragma unroll
    for (int i = 0; i < 2; i++)
        #pragma unroll
        for (int j = 0; j < 8; j++)
            #pragma unroll
            for (int u = 0; u < 4; u++) d[i][j][u] = 0.f;

    float4 ar[4], br[4];
    #pragma unroll
    for (int j = 0; j < 4; j++) {
        ar[j] = *(const float4*)&A [(size_t)(bm + rbase) * K + cb + j*4];
        br[j] = *(const float4*)&BT[(size_t)(bn + rbase) * K + cb + j*4];
    }
    #pragma unroll
    for (int j = 0; j < 4; j++) {
        float4 ah = make_float4(f2tf32(ar[j].x), f2tf32(ar[j].y), f2tf32(ar[j].z), f2tf32(ar[j].w));
        float4 al = make_float4(f2tf32(ar[j].x - ah.x), f2tf32(ar[j].y - ah.y),
                                f2tf32(ar[j].z - ah.z), f2tf32(ar[j].w - ah.w));
        float4 bh = make_float4(f2tf32(br[j].x), f2tf32(br[j].y), f2tf32(br[j].z), f2tf32(br[j].w));
        float4 bl = make_float4(f2tf32(br[j].x - bh.x), f2tf32(br[j].y - bh.y),
                                f2tf32(br[j].z - bh.z), f2tf32(br[j].w - bh.w));
        *(float4*)&Ah[0][rbase*MS + cb + j*4] = ah;
        *(float4*)&Al[0][rbase*MS + cb + j*4] = al;
        *(float4*)&Bh[0][rbase*MS + cb + j*4] = bh;
        *(float4*)&Bl[0][rbase*MS + cb + j*4] = bl;
    }
    __syncthreads();

    int nc = K / 32;
    for (int c = 0; c < nc; c++) {
        int buf = c & 1;
        if (c + 1 < nc) {
            int k0 = (c + 1) * 32;
            #pragma unroll
            for (int j = 0; j < 4; j++) {
                ar[j] = *(const float4*)&A [(size_t)(bm + rbase) * K + k0 + cb + j*4];
                br[j] = *(const float4*)&BT[(size_t)(bn + rbase) * K + k0 + cb + j*4];
            }
        }
        const float* ah_s = Ah[buf]; const float* al_s = Al[buf];
        const float* bh_s = Bh[buf]; const float* bl_s = Bl[buf];
        #pragma unroll
        for (int ks = 0; ks < 4; ks++) {
            int kk = ks*8 + (lane & 3);
            int rq = lane >> 2;
            uint32_t afh[2][4], afl[2][4];
            #pragma unroll
            for (int fm = 0; fm < 2; fm++) {
                int r0 = wm + fm*16 + rq;
                afh[fm][0] = __float_as_uint(ah_s[ r0     *MS + kk    ]);
                afh[fm][1] = __float_as_uint(ah_s[(r0 + 8)*MS + kk    ]);
                afh[fm][2] = __float_as_uint(ah_s[ r0     *MS + kk + 4]);
                afh[fm][3] = __float_as_uint(ah_s[(r0 + 8)*MS + kk + 4]);
                afl[fm][0] = __float_as_uint(al_s[ r0     *MS + kk    ]);
                afl[fm][1] = __float_as_uint(al_s[(r0 + 8)*MS + kk    ]);
                afl[fm][2] = __float_as_uint(al_s[ r0     *MS + kk + 4]);
                afl[fm][3] = __float_as_uint(al_s[(r0 + 8)*MS + kk + 4]);
            }
            #pragma unroll
            for (int fn = 0; fn < 8; fn++) {
                int n0 = wn + fn*8 + rq;
                uint32_t bfh[2] = { __float_as_uint(bh_s[n0*MS + kk]),
                                    __float_as_uint(bh_s[n0*MS + kk + 4]) };
                uint32_t bfl[2] = { __float_as_uint(bl_s[n0*MS + kk]),
                                    __float_as_uint(bl_s[n0*MS + kk + 4]) };
                #pragma unroll
                for (int fm = 0; fm < 2; fm++) {
                    MMA_TF32(d[fm][fn], afh[fm], bfh);
                    MMA_TF32(d[fm][fn], afl[fm], bfh);
                    MMA_TF32(d[fm][fn], afh[fm], bfl);
                }
            }
        }
        if (c + 1 < nc) {
            int nb = (c + 1) & 1;
            #pragma unroll
            for (int j = 0; j < 4; j++) {
                float4 ah = make_float4(f2tf32(ar[j].x), f2tf32(ar[j].y), f2tf32(ar[j].z), f2tf32(ar[j].w));
                float4 al = make_float4(f2tf32(ar[j].x - ah.x), f2tf32(ar[j].y - ah.y),
                                        f2tf32(ar[j].z - ah.z), f2tf32(ar[j].w - ah.w));
                float4 bh = make_float4(f2tf32(br[j].x), f2tf32(br[j].y), f2tf32(br[j].z), f2tf32(br[j].w));
                float4 bl = make_float4(f2tf32(br[j].x - bh.x), f2tf32(br[j].y - bh.y),
                                        f2tf32(br[j].z - bh.z), f2tf32(br[j].w - bh.w));
                *(float4*)&Ah[nb][rbase*MS + cb + j*4] = ah;
                *(float4*)&Al[nb][rbase*MS + cb + j*4] = al;
                *(float4*)&Bh[nb][rbase*MS + cb + j*4] = bh;
                *(float4*)&Bl[nb][rbase*MS + cb + j*4] = bl;
            }
        }
        __syncthreads();
    }

    #pragma unroll
    for (int fm = 0; fm < 2; fm++) {
        #pragma unroll
        for (int fn = 0; fn < 8; fn++) {
            int r  = bm + wm + fm*16 + (lane >> 2);
            int cc = bn + wn + fn*8 + 2*(lane & 3);
            *(float2*)&C[(size_t)r*N + cc]       = make_float2(d[fm][fn][0], d[fm][fn][1]);
            *(float2*)&C[(size_t)(r + 8)*N + cc] = make_float2(d[fm][fn][2], d[fm][fn][3]);
        }
    }
}

// ---------------- attention v3: mma.sync + score cache ----------------------
// PRECISE (layer1): 3xTF32 QK once, scores cached in gmem for pass 2.
// MASKED (layer2): plain tf32 + tile skip.
#define AS 68
template<bool PRECISE, bool MASKED>
__global__ __launch_bounds__(256)
void attn3_kernel(const float* __restrict__ qkv, const int* __restrict__ ids,
                  float* __restrict__ ctx, float* __restrict__ part,
                  float* __restrict__ scores)
{
    extern __shared__ float smf[];
    float* Qh = smf;
    float* Kh = Qh + 64*AS;
    float* Vt = Kh + 64*AS;           // transposed Vt[c][j]
    float* Ps = Vt + 64*AS;           // scores/probs [i][j]
    float* Ql = Ps + 64*AS;           // PRECISE only
    float* Kl = Ql + 64*AS;
    float* ms = smf + (PRECISE ? 6 : 4)*64*AS;
    float* ls = ms + 64;
    int*   qid = (int*)(ls + 64);
    int*   kid = qid + 64;

    int qt = blockIdx.x, h = blockIdx.y, b = blockIdx.z;
    int tid = threadIdx.x, lane = tid & 31, w = tid >> 5;
    int q0 = qt * 64;
    const float scale = 0.125f;

    const float* Qp = qkv;
    const float* Kp = qkv + (size_t)BT_*D_;
    const float* Vp = qkv + (size_t)2*BT_*D_;
    float* sc = PRECISE ? scores + ((size_t)(b*H_ + h)*T_ + q0)*T_ : (float*)0;

    int lrow = tid >> 2, le0 = (tid & 3) * 16;
    int m0 = (w >> 1) * 16, n0 = (w & 1) * 32;
    int rq = lane >> 2, cq = lane & 3;

    // load Q (+ qid)
    {
        const float* src = Qp + (size_t)(b*T_ + q0 + lrow) * D_ + h*DH_ + le0;
        #pragma unroll
        for (int u = 0; u < 4; u++) {
            float4 v = *(const float4*)(src + u*4);
            if (PRECISE) {
                float4 hv = make_float4(f2tf32(v.x), f2tf32(v.y), f2tf32(v.z), f2tf32(v.w));
                float4 lv = make_float4(f2tf32(v.x - hv.x), f2tf32(v.y - hv.y),
                                        f2tf32(v.z - hv.z), f2tf32(v.w - hv.w));
                *(float4*)&Qh[lrow*AS + le0 + u*4] = hv;
                *(float4*)&Ql[lrow*AS + le0 + u*4] = lv;
            } else {
                *(float4*)&Qh[lrow*AS + le0 + u*4] = v;
            }
        }
        if (MASKED && tid < 64) qid[tid] = ids[b*T_ + q0 + tid];
    }
    __syncthreads();
    int qid0 = 0, qidL = 0;
    if (MASKED) { qid0 = qid[0]; qidL = qid[63]; }

    // ================= pass 1 =================
    float m = -1e30f, l = 0.f;
    int sr = tid >> 2, seg = tid & 3;

    for (int kt = 0; kt < 16; kt++) {
        int k0 = kt * 64;
        if (MASKED && tid < 64) kid[tid] = ids[b*T_ + k0 + tid];
        __syncthreads();
        if (MASKED) { if (kid[63] < qid0 || qidL < kid[0]) continue; }
        {
            const float* src = Kp + (size_t)(b*T_ + k0 + lrow) * D_ + h*DH_ + le0;
            #pragma unroll
            for (int u = 0; u < 4; u++) {
                float4 v = *(const float4*)(src + u*4);
                if (PRECISE) {
                    float4 hv = make_float4(f2tf32(v.x), f2tf32(v.y), f2tf32(v.z), f2tf32(v.w));
                    float4 lv = make_float4(f2tf32(v.x - hv.x), f2tf32(v.y - hv.y),
                                            f2tf32(v.z - hv.z), f2tf32(v.w - hv.w));
                    *(float4*)&Kh[lrow*AS + le0 + u*4] = hv;
                    *(float4*)&Kl[lrow*AS + le0 + u*4] = lv;
                } else {
                    *(float4*)&Kh[lrow*AS + le0 + u*4] = v;
                }
            }
        }
        __syncthreads();
        float dq[4][4];
        #pragma unroll
        for (int fn = 0; fn < 4; fn++)
            #pragma unroll
            for (int u = 0; u < 4; u++) dq[fn][u] = 0.f;
        #pragma unroll
        for (int ks = 0; ks < 8; ks++) {
            int kk = ks*8 + cq;
            int arr = m0 + rq;
            uint32_t ah[4] = { __float_as_uint(Qh[ arr   *AS + kk]),
                               __float_as_uint(Qh[(arr+8)*AS + kk]),
                               __float_as_uint(Qh[ arr   *AS + kk + 4]),
                               __float_as_uint(Qh[(arr+8)*AS + kk + 4]) };
            #pragma unroll
            for (int fn = 0; fn < 4; fn++) {
                int bnr = n0 + fn*8 + rq;
                uint32_t bh[2] = { __float_as_uint(Kh[bnr*AS + kk]),
                                   __float_as_uint(Kh[bnr*AS + kk + 4]) };
                MMA_TF32(dq[fn], ah, bh);
                if (PRECISE) {
                    uint32_t al[4] = { __float_as_uint(Ql[ arr   *AS + kk]),
                                       __float_as_uint(Ql[(arr+8)*AS + kk]),
                                       __float_as_uint(Ql[ arr   *AS + kk + 4]),
                                       __float_as_uint(Ql[(arr+8)*AS + kk + 4]) };
                    uint32_t bl[2] = { __float_as_uint(Kl[bnr*AS + kk]),
                                       __float_as_uint(Kl[bnr*AS + kk + 4]) };
                    MMA_TF32(dq[fn], al, bh);
                    MMA_TF32(dq[fn], ah, bl);
                }
            }
        }
        #pragma unroll
        for (int fn = 0; fn < 4; fn++) {
            int i0 = m0 + rq, j0 = n0 + fn*8 + 2*cq;
            float s0 = dq[fn][0]*scale, s1 = dq[fn][1]*scale;
            float s2 = dq[fn][2]*scale, s3 = dq[fn][3]*scale;
            if (MASKED) {
                int qa = qid[i0], qb = qid[i0+8], ka = kid[j0], kb = kid[j0+1];
                if (qa != ka) s0 = -1e30f;
                if (qa != kb) s1 = -1e30f;
                if (qb != ka) s2 = -1e30f;
                if (qb != kb) s3 = -1e30f;
            }
            if (PRECISE) {
                *(float2*)&sc[(size_t)i0*T_ + k0 + j0]     = make_float2(s0, s1);
                *(float2*)&sc[(size_t)(i0+8)*T_ + k0 + j0] = make_float2(s2, s3);
            }
            Ps[ i0   *AS + j0]     = s0;
            Ps[ i0   *AS + j0 + 1] = s1;
            Ps[(i0+8)*AS + j0]     = s2;
            Ps[(i0+8)*AS + j0 + 1] = s3;
        }
        __syncthreads();
        {
            float sv[16]; float tm = -1e30f;
            #pragma unroll
            for (int u = 0; u < 4; u++) {
                float4 v = *(const float4*)&Ps[sr*AS + seg*16 + u*4];
                sv[u*4+0] = v.x; sv[u*4+1] = v.y; sv[u*4+2] = v.z; sv[u*4+3] = v.w;
                tm = fmaxf(tm, fmaxf(fmaxf(v.x, v.y), fmaxf(v.z, v.w)));
            }
            tm = fmaxf(tm, __shfl_xor_sync(0xffffffffu, tm, 1));
            tm = fmaxf(tm, __shfl_xor_sync(0xffffffffu, tm, 2));
            float nm = fmaxf(m, tm);
            float es = 0.f;
            #pragma unroll
            for (int it = 0; it < 16; it++) es += __expf(sv[it] - nm);
            es += __shfl_xor_sync(0xffffffffu, es, 1);
            es += __shfl_xor_sync(0xffffffffu, es, 2);
            l = l * __expf(m - nm) + es;
            m = nm;
        }
    }
    __syncthreads();
    if (seg == 0) { ms[sr] = m; ls[sr] = 1.f / l; }
    __syncthreads();

    // ================= pass 2 =================
    float pacc[4][4];
    #pragma unroll
    for (int fn = 0; fn < 4; fn++)
        #pragma unroll
        for (int u = 0; u < 4; u++) pacc[fn][u] = 0.f;

    for (int kt = 0; kt < 16; kt++) {
        int k0 = kt * 64;
        if (MASKED && tid < 64) kid[tid] = ids[b*T_ + k0 + tid];
        __syncthreads();
        if (MASKED) {
            if (kid[63] < qid0 || qidL < kid[0]) {
                if (tid < 64)
                    part[((size_t)((b*H_ + h)*16 + qt))*T_ + k0 + tid] = 0.f;
                continue;
            }
        }
        {
            if (!PRECISE) {
                const float* ksrc = Kp + (size_t)(b*T_ + k0 + lrow) * D_ + h*DH_ + le0;
                #pragma unroll
                for (int u = 0; u < 4; u++)
                    *(float4*)&Kh[lrow*AS + le0 + u*4] = *(const float4*)(ksrc + u*4);
            }
            const float* vsrc = Vp + (size_t)(b*T_ + k0 + lrow) * D_ + h*DH_ + le0;
            #pragma unroll
            for (int u = 0; u < 4; u++) {
                float4 v = *(const float4*)(vsrc + u*4);
                Vt[(le0 + u*4 + 0)*AS + lrow] = v.x;
                Vt[(le0 + u*4 + 1)*AS + lrow] = v.y;
                Vt[(le0 + u*4 + 2)*AS + lrow] = v.z;
                Vt[(le0 + u*4 + 3)*AS + lrow] = v.w;
            }
        }
        __syncthreads();
        // scores: cached (PRECISE) or recompute (MASKED)
        float dq[4][4];
        if (PRECISE) {
            #pragma unroll
            for (int fn = 0; fn < 4; fn++) {
                int i0 = m0 + rq, j0 = n0 + fn*8 + 2*cq;
                float2 v0 = *(const float2*)&sc[(size_t)i0*T_ + k0 + j0];
                float2 v1 = *(const float2*)&sc[(size_t)(i0+8)*T_ + k0 + j0];
                dq[fn][0] = v0.x; dq[fn][1] = v0.y;
                dq[fn][2] = v1.x; dq[fn][3] = v1.y;
            }
        } else {
            #pragma unroll
            for (int fn = 0; fn < 4; fn++)
                #pragma unroll
                for (int u = 0; u < 4; u++) dq[fn][u] = 0.f;
            #pragma unroll
            for (int ks = 0; ks < 8; ks++) {
                int kk = ks*8 + cq;
                int arr = m0 + rq;
                uint32_t ah[4] = { __float_as_uint(Qh[ arr   *AS + kk]),
                                   __float_as_uint(Qh[(arr+8)*AS + kk]),
                                   __float_as_uint(Qh[ arr   *AS + kk + 4]),
                                   __float_as_uint(Qh[(arr+8)*AS + kk + 4]) };
                #pragma unroll
                for (int fn = 0; fn < 4; fn++) {
                    int bnr = n0 + fn*8 + rq;
                    uint32_t bh[2] = { __float_as_uint(Kh[bnr*AS + kk]),
                                       __float_as_uint(Kh[bnr*AS + kk + 4]) };
                    MMA_TF32(dq[fn], ah, bh);
                }
            }
            #pragma unroll
            for (int fn = 0; fn < 4; fn++)
                #pragma unroll
                for (int u = 0; u < 4; u++) dq[fn][u] *= scale;
        }
        // probs
        #pragma unroll
        for (int fn = 0; fn < 4; fn++) {
            int i0 = m0 + rq, j0 = n0 + fn*8 + 2*cq;
            float ma = ms[i0], la = ls[i0];
            float mb = ms[i0+8], lb = ls[i0+8];
            float p0 = __expf(dq[fn][0] - ma) * la;
            float p1 = __expf(dq[fn][1] - ma) * la;
            float p2 = __expf(dq[fn][2] - mb) * lb;
            float p3 = __expf(dq[fn][3] - mb) * lb;
            if (MASKED) {
                int qa = qid[i0], qb = qid[i0+8], ka = kid[j0], kb = kid[j0+1];
                if (qa != ka) p0 = 0.f;
                if (qa != kb) p1 = 0.f;
                if (qb != ka) p2 = 0.f;
                if (qb != kb) p3 = 0.f;
            }
            Ps[ i0   *AS + j0]     = p0;
            Ps[ i0   *AS + j0 + 1] = p1;
            Ps[(i0+8)*AS + j0]     = p2;
            Ps[(i0+8)*AS + j0 + 1] = p3;
        }
        __syncthreads();
        if (tid < 64) {
            double cs = 0.0;
            #pragma unroll
            for (int i = 0; i < 64; i++) cs += (double)Ps[i*AS + tid];
            part[((size_t)((b*H_ + h)*16 + qt))*T_ + k0 + tid] = (float)cs;
        }
        #pragma unroll
        for (int ks = 0; ks < 8; ks++) {
            int kk = ks*8 + cq;
            int arr = m0 + rq;
            uint32_t ap[4] = { __float_as_uint(Ps[ arr   *AS + kk]),
                               __float_as_uint(Ps[(arr+8)*AS + kk]),
                               __float_as_uint(Ps[ arr   *AS + kk + 4]),
                               __float_as_uint(Ps[(arr+8)*AS + kk + 4]) };
            #pragma unroll
            for (int fn = 0; fn < 4; fn++) {
                int bnr = n0 + fn*8 + rq;
                uint32_t bv[2] = { __float_as_uint(Vt[bnr*AS + kk]),
                                   __float_as_uint(Vt[bnr*AS + kk + 4]) };
                MMA_TF32(pacc[fn], ap, bv);
            }
        }
    }
    #pragma unroll
    for (int fn = 0; fn < 4; fn++) {
        int r  = b*T_ + q0 + m0 + rq;
        int cc = h*DH_ + n0 + fn*8 + 2*cq;
        *(float2*)&ctx[(size_t)r*D_ + cc]       = make_float2(pacc[fn][0], pacc[fn][1]);
        *(float2*)&ctx[(size_t)(r+8)*D_ + cc]   = make_float2(pacc[fn][2], pacc[fn][3]);
    }
}

// ---------------- deterministic fp64 reduction of prob column sums ---------
__global__ void reduce_part_kernel(const float* __restrict__ part, double* __restrict__ wsum)
{
    int idx = blockIdx.x * 256 + threadIdx.x;
    int b = idx >> 10, j = idx & 1023;
    double s = 0.0;
    for (int g = 0; g < H_*16; g++)
        s += (double)part[((size_t)(b*H_*16 + g)) * T_ + j];
    wsum[idx] = s;
}

// ---------------- y = LayerNorm(x + r), row = 512 ---------------------------
__global__ void add_ln_kernel(const float* __restrict__ x, const float* __restrict__ r,
                              float* __restrict__ y)
{
    __shared__ float sm[256];
    int row = blockIdx.x, tid = threadIdx.x;
    size_t base = (size_t)row * D_;
    float v0 = x[base + tid]        + r[base + tid];
    float v1 = x[base + 256 + tid]  + r[base + 256 + tid];
    sm[tid] = v0 + v1; __syncthreads();
    for (int s = 128; s > 0; s >>= 1) { if (tid < s) sm[tid] += sm[tid + s]; __syncthreads(); }
    float mean = sm[0] * (1.f / D_); __syncthreads();
    float d0 = v0 - mean, d1 = v1 - mean;
    sm[tid] = d0*d0 + d1*d1; __syncthreads();
    for (int s = 128; s > 0; s >>= 1) { if (tid < s) sm[tid] += sm[tid + s]; __syncthreads(); }
    float var = sm[0] * (1.f / D_);
    float inv = 1.f / sqrtf(var + 1e-5f);
    y[base + tid]       = d0 * inv;
    y[base + 256 + tid] = d1 * inv;
}

// ---------------- window-id scan (exact replica of reference scan, fp64) ----
__global__ void scan_kernel(const double* __restrict__ wsum, int* __restrict__ ids,
                            int* __restrict__ ws, int* __restrict__ we)
{
    __shared__ double smn[256], smx[256];
    int b = blockIdx.x, tid = threadIdx.x;
    double mn = 1e300, mx = -1e300;
    for (int t = tid; t < T_; t += 256) {
        double v = wsum[b*T_ + t] * (1.0 / H_);
        mn = fmin(mn, v); mx = fmax(mx, v);
    }
    smn[tid] = mn; smx[tid] = mx; __syncthreads();
    for (int s = 128; s > 0; s >>= 1) {
        if (tid < s) { smn[tid] = fmin(smn[tid], smn[tid+s]); smx[tid] = fmax(smx[tid], smx[tid+s]); }
        __syncthreads();
    }
    for (int t = tid; t < T_; t += 256) { ws[b*T_ + t] = 0; we[b*T_ + t] = 0; }
    __syncthreads();
    if (tid == 0) {
        double MN = smn[0], MX = smx[0];
        double denom = MX - MN + 1e-8;
        double thr = MN + 0.5 * denom;
        int cur = (wsum[b*T_ + 0] * (1.0 / H_)) >= thr ? 1 : 0;
        int start = 0, wid = 0;
        ids[b*T_ + 0] = 0;
        for (int t = 1; t < T_; t++) {
            int wt = (wsum[b*T_ + t] * (1.0 / H_)) >= thr ? 1 : 0;
            if (wt == cur) {
            } else if (start + 1 == t) {
                cur = wt;
            } else {
                cur = wt; start = t; wid++;
            }
            ids[b*T_ + t] = wid;
        }
        int prev = -1;
        for (int t = 0; t < T_; t++) {
            int w = ids[b*T_ + t];
            if (w != prev) { ws[b*T_ + w] = t; prev = w; }
            we[b*T_ + w] = t + 1;
        }
    }
}

// ---------------- wl = softmax_j(wsum/H) ------------------------------------
__global__ void wl_softmax_kernel(const double* __restrict__ wsum, float* __restrict__ wl)
{
    __shared__ float sm[256];
    int b = blockIdx.x, tid = threadIdx.x;
    float vals[4];
    float mx = -1e30f;
    #pragma unroll
    for (int i = 0; i < 4; i++) {
        vals[i] = (float)(wsum[b*T_ + tid + i*256] * (1.0 / H_));
        mx = fmaxf(mx, vals[i]);
    }
    sm[tid] = mx; __syncthreads();
    for (int s = 128; s > 0; s >>= 1) { if (tid < s) sm[tid] = fmaxf(sm[tid], sm[tid+s]); __syncthreads(); }
    float M = sm[0]; __syncthreads();
    float e[4], acc = 0.f;
    #pragma unroll
    for (int i = 0; i < 4; i++) { e[i] = expf(vals[i] - M); acc += e[i]; }
    sm[tid] = acc; __syncthreads();
    for (int s = 128; s > 0; s >>= 1) { if (tid < s) sm[tid] += sm[tid+s]; __syncthreads(); }
    float inv = 1.f / sm[0];
    #pragma unroll
    for (int i = 0; i < 4; i++) wl[b*T_ + tid + i*256] = e[i] * inv;
}

// ---------------- window-weighted pooling (deterministic gather) ------------
__global__ void word_tokens_kernel(const float* __restrict__ outl, const float* __restrict__ wl,
                                   const int* __restrict__ ws, const int* __restrict__ we,
                                   float* __restrict__ out)
{
    int w = blockIdx.x, b = blockIdx.y, tid = threadIdx.x;
    int s = ws[b*T_ + w], e = we[b*T_ + w];
    float acc[4] = {0.f, 0.f, 0.f, 0.f};
    for (int t = s; t < e; t++) {
        float g = wl[b*T_ + t];
        const float* row = outl + (size_t)(b*T_ + t) * D_;
        #pragma unroll
        for (int u = 0; u < 4; u++) acc[u] += g * row[tid + u*128];
    }
    float* dst = out + ((size_t)(b*2*T_ + w)) * D_;
    #pragma unroll
    for (int u = 0; u < 4; u++) dst[tid + u*128] = acc[u];
}

// ---------------- copy x into second half of concat output ------------------
__global__ void copy_x_kernel(const float* __restrict__ x, float* __restrict__ out)
{
    int idx = blockIdx.x * 256 + threadIdx.x;
    int b = (idx * 4) / (T_*D_);
    float4 v = *(const float4*)&x[(size_t)idx * 4];
    *(float4*)&out[(size_t)idx * 4 + (size_t)(b + 1) * T_ * D_] = v;
}

// ---------------- window_mapping output -------------------------------------
__global__ void winmap_kernel(const int* __restrict__ ids, float* __restrict__ out2)
{
    int idx = blockIdx.x * 256 + threadIdx.x;
    int e0 = idx * 4;
    int b = e0 >> 20;
    int k = (e0 >> 10) & 1023;
    int j = e0 & 1023;
    const int* idr = ids + b*T_;
    float4 v;
    v.x = (idr[j+0] == k) ? 1.f : 0.f;
    v.y = (idr[j+1] == k) ? 1.f : 0.f;
    v.z = (idr[j+2] == k) ? 1.f : 0.f;
    v.w = (idr[j+3] == k) ? 1.f : 0.f;
    *(float4*)&out2[(size_t)e0] = v;
}

// ---------------- host launcher ---------------------------------------------
#define SMEM_A3P (6*64*AS*4 + 1024)
#define SMEM_A3  (4*64*AS*4 + 1024)

extern "C" void kernel_launch(void* const* d_in, const int* in_sizes, int n_in,
                              void* d_out, int out_size)
{
    const float* x       = (const float*)d_in[0];
    const float* v_qkv_w = (const float*)d_in[1];
    const float* v_out_w = (const float*)d_in[2];
    const float* v_w1    = (const float*)d_in[3];
    const float* v_w2    = (const float*)d_in[4];
    const float* l_qkv_w = (const float*)d_in[5];
    const float* l_out_w = (const float*)d_in[6];
    const float* l_w1    = (const float*)d_in[7];
    const float* l_w2    = (const float*)d_in[8];
    float* out = (float*)d_out;

    float *qkv, *ctx, *tmp, *h1, *ffn, *outv, *outl, *part, *wl, *wT, *scores;
    double *wsum;
    int *ids, *ws, *we;
    cudaGetSymbolAddress((void**)&qkv,  g_qkv);
    cudaGetSymbolAddress((void**)&ctx,  g_ctx);
    cudaGetSymbolAddress((void**)&tmp,  g_tmp);
    cudaGetSymbolAddress((void**)&h1,   g_h1);
    cudaGetSymbolAddress((void**)&ffn,  g_ffn);
    cudaGetSymbolAddress((void**)&outv, g_outv);
    cudaGetSymbolAddress((void**)&outl, g_outl);
    cudaGetSymbolAddress((void**)&part, g_part);
    cudaGetSymbolAddress((void**)&wsum, g_wsum);
    cudaGetSymbolAddress((void**)&wl,   g_wl);
    cudaGetSymbolAddress((void**)&ids,  g_ids);
    cudaGetSymbolAddress((void**)&ws,   g_ws);
    cudaGetSymbolAddress((void**)&we,   g_we);
    cudaGetSymbolAddress((void**)&wT,   g_wT);
    cudaGetSymbolAddress((void**)&scores, g_scores);

    cudaFuncSetAttribute(gemm_bf16_kernel, cudaFuncAttributeMaxDynamicSharedMemorySize, GB_SMEM);
    cudaFuncSetAttribute(gemm_mma3_kernel, cudaFuncAttributeMaxDynamicSharedMemorySize, G3_SMEM);
    cudaFuncSetAttribute((const void*)attn3_kernel<true,false>,  cudaFuncAttributeMaxDynamicSharedMemorySize, SMEM_A3P);
    cudaFuncSetAttribute((const void*)attn3_kernel<false,true>,  cudaFuncAttributeMaxDynamicSharedMemorySize, SMEM_A3);

    // ===== transpose all weights (one batched launch) ====
    transpose_all_kernel<<<6144, dim3(32,8)>>>(v_qkv_w, l_qkv_w, v_out_w, l_out_w,
                                               v_w1, l_w1, v_w2, l_w2, wT);

    dim3 gAttn(T_/64, H_, B_);
    dim3 gtD(D_/128, BT_/128, 1);
    dim3 gtF1(FF_/128, BT_/128, 1);
    dim3 gtQK(D_/128, BT_/128, 2);
    dim3 gtQKV(D_/128, BT_/128, 3);

    // ===== layer 1 (vanilla) =====
    // Q,K projections: 3xTF32 (decision path); V projection: bf16 (continuous)
    gemm_mma3_kernel<<<gtQK, 256, G3_SMEM>>>(x, wT + WT_VQKV, qkv, D_, D_,
                                             (long long)D_*D_, (long long)BT_*D_);
    gemm_bf16_kernel<<<gtD, 128, GB_SMEM>>>(x, wT + WT_VQKV + 2*D_*D_, qkv + (size_t)2*BT_*D_,
                                            D_, D_, 0, 0, 0);
    attn3_kernel<true,false><<<gAttn, 256, SMEM_A3P>>>(qkv, nullptr, ctx, part, scores);
    reduce_part_kernel<<<(B_*T_)/256, 256>>>(part, wsum);
    gemm_bf16_kernel<<<gtD, 128, GB_SMEM>>>(ctx, wT + WT_VOUT, tmp, D_, D_, 0, 0, 0);
    add_ln_kernel<<<BT_, 256>>>(x, tmp, h1);
    gemm_bf16_kernel<<<gtF1, 128, GB_SMEM>>>(h1, wT + WT_VW1, ffn, FF_, D_, 0, 0, 1);
    gemm_bf16_kernel<<<gtD, 128, GB_SMEM>>>(ffn, wT + WT_VW2, tmp, D_, FF_, 0, 0, 0);
    add_ln_kernel<<<BT_, 256>>>(h1, tmp, outv);

    // ===== dynamic window mask =====
    scan_kernel<<<B_, 256>>>(wsum, ids, ws, we);

    // ===== layer 2 (masked) =====
    gemm_bf16_kernel<<<gtQKV, 128, GB_SMEM>>>(outv, wT + WT_LQKV, qkv, D_, D_,
                                              (long long)D_*D_, (long long)BT_*D_, 0);
    attn3_kernel<false,true><<<gAttn, 256, SMEM_A3>>>(qkv, ids, ctx, part, nullptr);
    reduce_part_kernel<<<(B_*T_)/256, 256>>>(part, wsum);
    gemm_bf16_kernel<<<gtD, 128, GB_SMEM>>>(ctx, wT + WT_LOUT, tmp, D_, D_, 0, 0, 0);
    add_ln_kernel<<<BT_, 256>>>(outv, tmp, h1);
    gemm_bf16_kernel<<<gtF1, 128, GB_SMEM>>>(h1, wT + WT_LW1, ffn, FF_, D_, 0, 0, 1);
    gemm_bf16_kernel<<<gtD, 128, GB_SMEM>>>(ffn, wT + WT_LW2, tmp, D_, FF_, 0, 0, 0);
    add_ln_kernel<<<BT_, 256>>>(h1, tmp, outl);

    // ===== outputs =====
    wl_softmax_kernel<<<B_, 256>>>(wsum, wl);
    word_tokens_kernel<<<dim3(T_, B_), 128>>>(outl, wl, ws, we, out);
    copy_x_kernel<<<(B_*T_*D_/4)/256, 256>>>(x, out);
    winmap_kernel<<<(B_*T_*T_/4)/256, 256>>>(ids, out + (size_t)B_*2*T_*D_);
}

// round 8
// speedup vs baseline: 5.0284x; 1.0887x over previous
#include <cuda_runtime.h>
#include <cuda_bf16.h>
#include <math.h>
#include <stdint.h>

// Problem constants
#define B_  8
#define T_  1024
#define D_  512
#define FF_ 2048
#define H_  8
#define DH_ 64
#define BT_ (B_*T_)          // 8192 rows

// ---------------- scratch (device globals; no allocation allowed) ----------
__device__ float  g_qkv [3*BT_*D_];
__device__ float  g_ctx [BT_*D_];
__device__ float  g_tmp [BT_*D_];
__device__ float  g_h1  [BT_*D_];
__device__ float  g_ffn [BT_*FF_];
__device__ float  g_outv[BT_*D_];
__device__ float  g_outl[BT_*D_];
__device__ float  g_part[B_*H_*16*T_];
__device__ double g_wsum[B_*T_];
__device__ float  g_wl  [B_*T_];
__device__ int    g_ids [B_*T_];
__device__ int    g_ws  [B_*T_];
__device__ int    g_we  [B_*T_];
__device__ float  g_wT  [6291456];      // transposed weights
__device__ float  g_scores[(size_t)B_*H_*T_*T_];  // layer-1 exp(score) cache (256MB)

// transposed-weight offsets (floats)
#define WT_LQKV 0
#define WT_VOUT 786432
#define WT_LOUT 1048576
#define WT_VW1  1310720
#define WT_LW1  2359296
#define WT_VW2  3407872
#define WT_LW2  4456448
#define WT_VQKV 5505024

// ---------------- tf32 helpers ----------------------------------------------
__device__ __forceinline__ float f2tf32(float x) {
    uint32_t u;
    asm("cvt.rna.tf32.f32 %0, %1;" : "=r"(u) : "f"(x));
    return __uint_as_float(u);
}
#define MMA_TF32(d, a, b) \
    asm volatile("mma.sync.aligned.m16n8k8.row.col.f32.tf32.tf32.f32 " \
        "{%0,%1,%2,%3}, {%4,%5,%6,%7}, {%8,%9}, {%0,%1,%2,%3};" \
        : "+f"((d)[0]), "+f"((d)[1]), "+f"((d)[2]), "+f"((d)[3]) \
        : "r"((a)[0]), "r"((a)[1]), "r"((a)[2]), "r"((a)[3]), \
          "r"((b)[0]), "r"((b)[1]))
#define MMA_BF16(d, a, b) \
    asm volatile("mma.sync.aligned.m16n8k16.row.col.f32.bf16.bf16.f32 " \
        "{%0,%1,%2,%3}, {%4,%5,%6,%7}, {%8,%9}, {%0,%1,%2,%3};" \
        : "+f"((d)[0]), "+f"((d)[1]), "+f"((d)[2]), "+f"((d)[3]) \
        : "r"((a)[0]), "r"((a)[1]), "r"((a)[2]), "r"((a)[3]), \
          "r"((b)[0]), "r"((b)[1]))

__device__ __forceinline__ uint32_t pack_bf16x2(float lo, float hi) {
    __nv_bfloat162 h = __float22bfloat162_rn(make_float2(lo, hi));
    return *(uint32_t*)&h;
}

// ---------------- batched weight transpose ----------------------------------
__global__ void transpose_all_kernel(
    const float* __restrict__ vqkv, const float* __restrict__ lqkv,
    const float* __restrict__ vout, const float* __restrict__ lout,
    const float* __restrict__ vw1,  const float* __restrict__ lw1,
    const float* __restrict__ vw2,  const float* __restrict__ lw2,
    float* __restrict__ wT)
{
    __shared__ float t[32][33];
    int bid = blockIdx.x;
    int task, local;
    if (bid < 2048) { task = bid >> 8; local = bid & 255; }
    else { int r = bid - 2048; task = 8 + (r >> 10); local = r & 1023; }
    const float* src; float* dst; int R, C;
    switch (task) {
        case 0:  src = vqkv;           dst = wT + WT_VQKV;           R = 512;  C = 512;  break;
        case 1:  src = vqkv + 262144;  dst = wT + WT_VQKV + 262144;  R = 512;  C = 512;  break;
        case 2:  src = vqkv + 524288;  dst = wT + WT_VQKV + 524288;  R = 512;  C = 512;  break;
        case 3:  src = lqkv;           dst = wT + WT_LQKV;           R = 512;  C = 512;  break;
        case 4:  src = lqkv + 262144;  dst = wT + WT_LQKV + 262144;  R = 512;  C = 512;  break;
        case 5:  src = lqkv + 524288;  dst = wT + WT_LQKV + 524288;  R = 512;  C = 512;  break;
        case 6:  src = vout;           dst = wT + WT_VOUT;           R = 512;  C = 512;  break;
        case 7:  src = lout;           dst = wT + WT_LOUT;           R = 512;  C = 512;  break;
        case 8:  src = vw1;            dst = wT + WT_VW1;            R = 512;  C = 2048; break;
        case 9:  src = lw1;            dst = wT + WT_LW1;            R = 512;  C = 2048; break;
        case 10: src = vw2;            dst = wT + WT_VW2;            R = 2048; C = 512;  break;
        default: src = lw2;            dst = wT + WT_LW2;            R = 2048; C = 512;  break;
    }
    int nbx = C >> 5;
    int c0 = (local % nbx) * 32, r0 = (local / nbx) * 32;
    int tx = threadIdx.x, ty = threadIdx.y;
    #pragma unroll
    for (int i = 0; i < 32; i += 8)
        t[ty+i][tx] = src[(size_t)(r0+ty+i)*C + c0+tx];
    __syncthreads();
    #pragma unroll
    for (int i = 0; i < 32; i += 8)
        dst[(size_t)(c0+ty+i)*R + r0+tx] = t[tx][ty+i];
}

// ---------------- bf16 tensor GEMM (continuous path) ------------------------
#define MSB 40
#define GB_SMEM (4 * 128 * MSB * 2)
__global__ __launch_bounds__(128)
void gemm_bf16_kernel(const float* __restrict__ A, const float* __restrict__ BTs,
                      float* __restrict__ Cs, int N, int K,
                      long long bt_z, long long c_z, int relu)
{
    extern __shared__ char smraw[];
    __nv_bfloat16* sb = (__nv_bfloat16*)smraw;
    __nv_bfloat16* Asm[2] = { sb,            sb + 128*MSB };
    __nv_bfloat16* Bsm[2] = { sb + 2*128*MSB, sb + 3*128*MSB };

    const float* BT = BTs + (long long)blockIdx.z * bt_z;
    float*       C  = Cs  + (long long)blockIdx.z * c_z;

    int tid = threadIdx.x, lane = tid & 31, wid = tid >> 5;
    int wm = (wid >> 1) * 64, wn = (wid & 1) * 64;
    int bm = blockIdx.y * 128, bn = blockIdx.x * 128;
    int col4 = tid & 7, rbase = tid >> 3;
    int rq = lane >> 2, cq = lane & 3;

    float d[4][8][4];
    #pragma unroll
    for (int i = 0; i < 4; i++)
        #pragma unroll
        for (int j = 0; j < 8; j++)
            #pragma unroll
            for (int u = 0; u < 4; u++) d[i][j][u] = 0.f;

    float4 ar[8], br[8];
    #pragma unroll
    for (int j = 0; j < 8; j++) {
        ar[j] = *(const float4*)&A [(size_t)(bm + rbase + j*16) * K + col4*4];
        br[j] = *(const float4*)&BT[(size_t)(bn + rbase + j*16) * K + col4*4];
    }
    #pragma unroll
    for (int j = 0; j < 8; j++) {
        int r = rbase + j*16;
        uint2 pa = make_uint2(pack_bf16x2(ar[j].x, ar[j].y), pack_bf16x2(ar[j].z, ar[j].w));
        uint2 pb = make_uint2(pack_bf16x2(br[j].x, br[j].y), pack_bf16x2(br[j].z, br[j].w));
        *(uint2*)&Asm[0][r*MSB + col4*4] = pa;
        *(uint2*)&Bsm[0][r*MSB + col4*4] = pb;
    }
    __syncthreads();

    int nc = K / 32;
    for (int c = 0; c < nc; c++) {
        int buf = c & 1;
        if (c + 1 < nc) {
            int k0 = (c + 1) * 32;
            #pragma unroll
            for (int j = 0; j < 8; j++) {
                ar[j] = *(const float4*)&A [(size_t)(bm + rbase + j*16) * K + k0 + col4*4];
                br[j] = *(const float4*)&BT[(size_t)(bn + rbase + j*16) * K + k0 + col4*4];
            }
        }
        const __nv_bfloat16* a_s = Asm[buf];
        const __nv_bfloat16* b_s = Bsm[buf];
        #pragma unroll
        for (int ks = 0; ks < 2; ks++) {
            int k2 = ks*16 + cq*2;
            uint32_t af[4][4];
            #pragma unroll
            for (int fm = 0; fm < 4; fm++) {
                int r0 = wm + fm*16 + rq;
                af[fm][0] = *(const uint32_t*)&a_s[ r0     *MSB + k2];
                af[fm][1] = *(const uint32_t*)&a_s[(r0 + 8)*MSB + k2];
                af[fm][2] = *(const uint32_t*)&a_s[ r0     *MSB + k2 + 8];
                af[fm][3] = *(const uint32_t*)&a_s[(r0 + 8)*MSB + k2 + 8];
            }
            #pragma unroll
            for (int fn = 0; fn < 8; fn++) {
                int n0 = wn + fn*8 + rq;
                uint32_t bf[2] = { *(const uint32_t*)&b_s[n0*MSB + k2],
                                   *(const uint32_t*)&b_s[n0*MSB + k2 + 8] };
                #pragma unroll
                for (int fm = 0; fm < 4; fm++)
                    MMA_BF16(d[fm][fn], af[fm], bf);
            }
        }
        if (c + 1 < nc) {
            int nb = (c + 1) & 1;
            #pragma unroll
            for (int j = 0; j < 8; j++) {
                int r = rbase + j*16;
                uint2 pa = make_uint2(pack_bf16x2(ar[j].x, ar[j].y), pack_bf16x2(ar[j].z, ar[j].w));
                uint2 pb = make_uint2(pack_bf16x2(br[j].x, br[j].y), pack_bf16x2(br[j].z, br[j].w));
                *(uint2*)&Asm[nb][r*MSB + col4*4] = pa;
                *(uint2*)&Bsm[nb][r*MSB + col4*4] = pb;
            }
        }
        __syncthreads();
    }

    #pragma unroll
    for (int fm = 0; fm < 4; fm++) {
        #pragma unroll
        for (int fn = 0; fn < 8; fn++) {
            int r  = bm + wm + fm*16 + rq;
            int cc = bn + wn + fn*8 + 2*cq;
            float2 v0 = make_float2(d[fm][fn][0], d[fm][fn][1]);
            float2 v1 = make_float2(d[fm][fn][2], d[fm][fn][3]);
            if (relu) {
                v0.x = fmaxf(v0.x, 0.f); v0.y = fmaxf(v0.y, 0.f);
                v1.x = fmaxf(v1.x, 0.f); v1.y = fmaxf(v1.y, 0.f);
            }
            *(float2*)&C[(size_t)r*N + cc]       = v0;
            *(float2*)&C[(size_t)(r + 8)*N + cc] = v1;
        }
    }
}

// ---------------- 3xTF32 GEMM (decision path: layer-1 Q/K proj) -------------
#define MS 36
#define G3_SMEM (8 * 128 * MS * 4)
__global__ __launch_bounds__(256)
void gemm_mma3_kernel(const float* __restrict__ A, const float* __restrict__ BTs,
                      float* __restrict__ Cs, int N, int K,
                      long long bt_z, long long c_z)
{
    extern __shared__ float smf[];
    float* Ah[2] = { smf,            smf + 128*MS };
    float* Al[2] = { smf + 2*128*MS, smf + 3*128*MS };
    float* Bh[2] = { smf + 4*128*MS, smf + 5*128*MS };
    float* Bl[2] = { smf + 6*128*MS, smf + 7*128*MS };

    const float* BT = BTs + (long long)blockIdx.z * bt_z;
    float*       C  = Cs  + (long long)blockIdx.z * c_z;

    int tid = threadIdx.x, lane = tid & 31, wid = tid >> 5;
    int wm = (wid >> 1) * 32, wn = (wid & 1) * 64;
    int bm = blockIdx.y * 128, bn = blockIdx.x * 128;
    int rbase = tid >> 1, cb = (tid & 1) * 16;

    float d[2][8][4];
    #pragma unroll
    for (int i = 0; i < 2; i++)
        #pragma unroll
        for (int j = 0; j < 8; j++)
            #pragma unroll
            for (int u = 0; u < 4; u++) d[i][j][u] = 0.f;

    float4 ar[4], br[4];
    #pragma unroll
    for (int j = 0; j < 4; j++) {
        ar[j] = *(const float4*)&A [(size_t)(bm + rbase) * K + cb + j*4];
        br[j] = *(const float4*)&BT[(size_t)(bn + rbase) * K + cb + j*4];
    }
    #pragma unroll
    for (int j = 0; j < 4; j++) {
        float4 ah = make_float4(f2tf32(ar[j].x), f2tf32(ar[j].y), f2tf32(ar[j].z), f2tf32(ar[j].w));
        float4 al = make_float4(f2tf32(ar[j].x - ah.x), f2tf32(ar[j].y - ah.y),
                                f2tf32(ar[j].z - ah.z), f2tf32(ar[j].w - ah.w));
        float4 bh = make_float4(f2tf32(br[j].x), f2tf32(br[j].y), f2tf32(br[j].z), f2tf32(br[j].w));
        float4 bl = make_float4(f2tf32(br[j].x - bh.x), f2tf32(br[j].y - bh.y),
                                f2tf32(br[j].z - bh.z), f2tf32(br[j].w - bh.w));
        *(float4*)&Ah[0][rbase*MS + cb + j*4] = ah;
        *(float4*)&Al[0][rbase*MS + cb + j*4] = al;
        *(float4*)&Bh[0][rbase*MS + cb + j*4] = bh;
        *(float4*)&Bl[0][rbase*MS + cb + j*4] = bl;
    }
    __syncthreads();

    int nc = K / 32;
    for (int c = 0; c < nc; c++) {
        int buf = c & 1;
        if (c + 1 < nc) {
            int k0 = (c + 1) * 32;
            #pragma unroll
            for (int j = 0; j < 4; j++) {
                ar[j] = *(const float4*)&A [(size_t)(bm + rbase) * K + k0 + cb + j*4];
                br[j] = *(const float4*)&BT[(size_t)(bn + rbase) * K + k0 + cb + j*4];
            }
        }
        const float* ah_s = Ah[buf]; const float* al_s = Al[buf];
        const float* bh_s = Bh[buf]; const float* bl_s = Bl[buf];
        #pragma unroll
        for (int ks = 0; ks < 4; ks++) {
            int kk = ks*8 + (lane & 3);
            int rq = lane >> 2;
            uint32_t afh[2][4], afl[2][4];
            #pragma unroll
            for (int fm = 0; fm < 2; fm++) {
                int r0 = wm + fm*16 + rq;
                afh[fm][0] = __float_as_uint(ah_s[ r0     *MS + kk    ]);
                afh[fm][1] = __float_as_uint(ah_s[(r0 + 8)*MS + kk    ]);
                afh[fm][2] = __float_as_uint(ah_s[ r0     *MS + kk + 4]);
                afh[fm][3] = __float_as_uint(ah_s[(r0 + 8)*MS + kk + 4]);
                afl[fm][0] = __float_as_uint(al_s[ r0     *MS + kk    ]);
                afl[fm][1] = __float_as_uint(al_s[(r0 + 8)*MS + kk    ]);
                afl[fm][2] = __float_as_uint(al_s[ r0     *MS + kk + 4]);
                afl[fm][3] = __float_as_uint(al_s[(r0 + 8)*MS + kk + 4]);
            }
            #pragma unroll
            for (int fn = 0; fn < 8; fn++) {
                int n0 = wn + fn*8 + rq;
                uint32_t bfh[2] = { __float_as_uint(bh_s[n0*MS + kk]),
                                    __float_as_uint(bh_s[n0*MS + kk + 4]) };
                uint32_t bfl[2] = { __float_as_uint(bl_s[n0*MS + kk]),
                                    __float_as_uint(bl_s[n0*MS + kk + 4]) };
                #pragma unroll
                for (int fm = 0; fm < 2; fm++) {
                    MMA_TF32(d[fm][fn], afh[fm], bfh);
                    MMA_TF32(d[fm][fn], afl[fm], bfh);
                    MMA_TF32(d[fm][fn], afh[fm], bfl);
                }
            }
        }
        if (c + 1 < nc) {
            int nb = (c + 1) & 1;
            #pragma unroll
            for (int j = 0; j < 4; j++) {
                float4 ah = make_float4(f2tf32(ar[j].x), f2tf32(ar[j].y), f2tf32(ar[j].z), f2tf32(ar[j].w));
                float4 al = make_float4(f2tf32(ar[j].x - ah.x), f2tf32(ar[j].y - ah.y),
                                        f2tf32(ar[j].z - ah.z), f2tf32(ar[j].w - ah.w));
                float4 bh = make_float4(f2tf32(br[j].x), f2tf32(br[j].y), f2tf32(br[j].z), f2tf32(br[j].w));
                float4 bl = make_float4(f2tf32(br[j].x - bh.x), f2tf32(br[j].y - bh.y),
                                        f2tf32(br[j].z - bh.z), f2tf32(br[j].w - bh.w));
                *(float4*)&Ah[nb][rbase*MS + cb + j*4] = ah;
                *(float4*)&Al[nb][rbase*MS + cb + j*4] = al;
                *(float4*)&Bh[nb][rbase*MS + cb + j*4] = bh;
                *(float4*)&Bl[nb][rbase*MS + cb + j*4] = bl;
            }
        }
        __syncthreads();
    }

    #pragma unroll
    for (int fm = 0; fm < 2; fm++) {
        #pragma unroll
        for (int fn = 0; fn < 8; fn++) {
            int r  = bm + wm + fm*16 + (lane >> 2);
            int cc = bn + wn + fn*8 + 2*(lane & 3);
            *(float2*)&C[(size_t)r*N + cc]       = make_float2(d[fm][fn][0], d[fm][fn][1]);
            *(float2*)&C[(size_t)(r + 8)*N + cc] = make_float2(d[fm][fn][2], d[fm][fn][3]);
        }
    }
}

// ---------------- layer-1 attention v4: single pass, no-max softmax ---------
// e = exp(s) computed ONCE, cached to gmem; ctx = (E V) * (1/Z);
// colsum sweep re-reads cached e with z weights in fp64.
#define AS 68
#define SMEM_A4 (6*64*AS*4 + 256)
__global__ __launch_bounds__(256)
void attn4_kernel(const float* __restrict__ qkv, float* __restrict__ ctx,
                  float* __restrict__ part, float* __restrict__ ecache)
{
    extern __shared__ float smf[];
    float* Qh = smf;
    float* Ql = Qh + 64*AS;
    float* Kh = Ql + 64*AS;
    float* Kl = Kh + 64*AS;
    float* Vt = Kl + 64*AS;           // transposed Vt[c][j]
    float* Ps = Vt + 64*AS;           // e tile [i][j]
    float* zs = smf + 6*64*AS;        // [64] reciprocal row sums

    int qt = blockIdx.x, h = blockIdx.y, b = blockIdx.z;
    int tid = threadIdx.x, lane = tid & 31, w = tid >> 5;
    int q0 = qt * 64;
    const float scale = 0.125f;

    const float* Qp = qkv;
    const float* Kp = qkv + (size_t)BT_*D_;
    const float* Vp = qkv + (size_t)2*BT_*D_;
    float* ec = ecache + ((size_t)(b*H_ + h)*T_ + q0)*T_;

    int lrow = tid >> 2, le0 = (tid & 3) * 16;
    int m0 = (w >> 1) * 16, n0 = (w & 1) * 32;
    int rq = lane >> 2, cq = lane & 3;
    int sr = tid >> 2, seg = tid & 3;

    // load Q hi/lo
    {
        const float* src = Qp + (size_t)(b*T_ + q0 + lrow) * D_ + h*DH_ + le0;
        #pragma unroll
        for (int u = 0; u < 4; u++) {
            float4 v = *(const float4*)(src + u*4);
            float4 hv = make_float4(f2tf32(v.x), f2tf32(v.y), f2tf32(v.z), f2tf32(v.w));
            float4 lv = make_float4(f2tf32(v.x - hv.x), f2tf32(v.y - hv.y),
                                    f2tf32(v.z - hv.z), f2tf32(v.w - hv.w));
            *(float4*)&Qh[lrow*AS + le0 + u*4] = hv;
            *(float4*)&Ql[lrow*AS + le0 + u*4] = lv;
        }
    }

    float l = 0.f;                    // row expsum (4 threads per row)
    float pacc[4][4];
    #pragma unroll
    for (int fn = 0; fn < 4; fn++)
        #pragma unroll
        for (int u = 0; u < 4; u++) pacc[fn][u] = 0.f;

    for (int kt = 0; kt < 16; kt++) {
        int k0 = kt * 64;
        __syncthreads();              // protect Kh/Kl/Vt/Ps reuse
        {
            const float* src = Kp + (size_t)(b*T_ + k0 + lrow) * D_ + h*DH_ + le0;
            #pragma unroll
            for (int u = 0; u < 4; u++) {
                float4 v = *(const float4*)(src + u*4);
                float4 hv = make_float4(f2tf32(v.x), f2tf32(v.y), f2tf32(v.z), f2tf32(v.w));
                float4 lv = make_float4(f2tf32(v.x - hv.x), f2tf32(v.y - hv.y),
                                        f2tf32(v.z - hv.z), f2tf32(v.w - hv.w));
                *(float4*)&Kh[lrow*AS + le0 + u*4] = hv;
                *(float4*)&Kl[lrow*AS + le0 + u*4] = lv;
            }
            const float* vsrc = Vp + (size_t)(b*T_ + k0 + lrow) * D_ + h*DH_ + le0;
            #pragma unroll
            for (int u = 0; u < 4; u++) {
                float4 v = *(const float4*)(vsrc + u*4);
                Vt[(le0 + u*4 + 0)*AS + lrow] = v.x;
                Vt[(le0 + u*4 + 1)*AS + lrow] = v.y;
                Vt[(le0 + u*4 + 2)*AS + lrow] = v.z;
                Vt[(le0 + u*4 + 3)*AS + lrow] = v.w;
            }
        }
        __syncthreads();
        // QK 3xTF32
        float dq[4][4];
        #pragma unroll
        for (int fn = 0; fn < 4; fn++)
            #pragma unroll
            for (int u = 0; u < 4; u++) dq[fn][u] = 0.f;
        #pragma unroll
        for (int ks = 0; ks < 8; ks++) {
            int kk = ks*8 + cq;
            int arr = m0 + rq;
            uint32_t ah[4] = { __float_as_uint(Qh[ arr   *AS + kk]),
                               __float_as_uint(Qh[(arr+8)*AS + kk]),
                               __float_as_uint(Qh[ arr   *AS + kk + 4]),
                               __float_as_uint(Qh[(arr+8)*AS + kk + 4]) };
            uint32_t al[4] = { __float_as_uint(Ql[ arr   *AS + kk]),
                               __float_as_uint(Ql[(arr+8)*AS + kk]),
                               __float_as_uint(Ql[ arr   *AS + kk + 4]),
                               __float_as_uint(Ql[(arr+8)*AS + kk + 4]) };
            #pragma unroll
            for (int fn = 0; fn < 4; fn++) {
                int bnr = n0 + fn*8 + rq;
                uint32_t bh[2] = { __float_as_uint(Kh[bnr*AS + kk]),
                                   __float_as_uint(Kh[bnr*AS + kk + 4]) };
                uint32_t bl[2] = { __float_as_uint(Kl[bnr*AS + kk]),
                                   __float_as_uint(Kl[bnr*AS + kk + 4]) };
                MMA_TF32(dq[fn], ah, bh);
                MMA_TF32(dq[fn], al, bh);
                MMA_TF32(dq[fn], ah, bl);
            }
        }
        // e = exp(score), write to smem + gmem cache (exp computed ONCE)
        #pragma unroll
        for (int fn = 0; fn < 4; fn++) {
            int i0 = m0 + rq, j0 = n0 + fn*8 + 2*cq;
            float e0 = __expf(dq[fn][0]*scale);
            float e1 = __expf(dq[fn][1]*scale);
            float e2 = __expf(dq[fn][2]*scale);
            float e3 = __expf(dq[fn][3]*scale);
            *(float2*)&ec[(size_t)i0*T_ + k0 + j0]     = make_float2(e0, e1);
            *(float2*)&ec[(size_t)(i0+8)*T_ + k0 + j0] = make_float2(e2, e3);
            Ps[ i0   *AS + j0]     = e0;
            Ps[ i0   *AS + j0 + 1] = e1;
            Ps[(i0+8)*AS + j0]     = e2;
            Ps[(i0+8)*AS + j0 + 1] = e3;
        }
        __syncthreads();
        // row expsum accumulation
        {
            float es = 0.f;
            #pragma unroll
            for (int u = 0; u < 4; u++) {
                float4 v = *(const float4*)&Ps[sr*AS + seg*16 + u*4];
                es += (v.x + v.y) + (v.z + v.w);
            }
            es += __shfl_xor_sync(0xffffffffu, es, 1);
            es += __shfl_xor_sync(0xffffffffu, es, 2);
            l += es;
        }
        // unnormalized PV mma
        #pragma unroll
        for (int ks = 0; ks < 8; ks++) {
            int kk = ks*8 + cq;
            int arr = m0 + rq;
            uint32_t ap[4] = { __float_as_uint(Ps[ arr   *AS + kk]),
                               __float_as_uint(Ps[(arr+8)*AS + kk]),
                               __float_as_uint(Ps[ arr   *AS + kk + 4]),
                               __float_as_uint(Ps[(arr+8)*AS + kk + 4]) };
            #pragma unroll
            for (int fn = 0; fn < 4; fn++) {
                int bnr = n0 + fn*8 + rq;
                uint32_t bv[2] = { __float_as_uint(Vt[bnr*AS + kk]),
                                   __float_as_uint(Vt[bnr*AS + kk + 4]) };
                MMA_TF32(pacc[fn], ap, bv);
            }
        }
    }
    __syncthreads();
    if (seg == 0) zs[sr] = 1.f / l;
    __syncthreads();

    // write ctx (scale rows by z)
    {
        float za = zs[m0 + rq], zb = zs[m0 + rq + 8];
        #pragma unroll
        for (int fn = 0; fn < 4; fn++) {
            int r  = b*T_ + q0 + m0 + rq;
            int cc = h*DH_ + n0 + fn*8 + 2*cq;
            *(float2*)&ctx[(size_t)r*D_ + cc]     = make_float2(pacc[fn][0]*za, pacc[fn][1]*za);
            *(float2*)&ctx[(size_t)(r+8)*D_ + cc] = make_float2(pacc[fn][2]*zb, pacc[fn][3]*zb);
        }
    }

    // ---- colsum sweep over cached e (fp64, deterministic) ----
    double cs[4] = {0.0, 0.0, 0.0, 0.0};
    for (int i = 0; i < 64; i++) {
        double zi = (double)zs[i];
        const float* row = ec + (size_t)i*T_;
        #pragma unroll
        for (int g = 0; g < 4; g++)
            cs[g] += (double)row[tid + g*256] * zi;
    }
    float* pr = part + ((size_t)((b*H_ + h)*16 + qt))*T_;
    #pragma unroll
    for (int g = 0; g < 4; g++) pr[tid + g*256] = (float)cs[g];
}

// ---------------- layer-2 masked attention (two-pass, tile skip) ------------
__global__ __launch_bounds__(256)
void attn_masked_kernel(const float* __restrict__ qkv, const int* __restrict__ ids,
                        float* __restrict__ ctx, float* __restrict__ part)
{
    extern __shared__ float smf[];
    float* Qh = smf;
    float* Kh = Qh + 64*AS;
    float* Vt = Kh + 64*AS;
    float* Ps = Vt + 64*AS;
    float* ms = smf + 4*64*AS;
    float* ls = ms + 64;
    int*   qid = (int*)(ls + 64);
    int*   kid = qid + 64;

    int qt = blockIdx.x, h = blockIdx.y, b = blockIdx.z;
    int tid = threadIdx.x, lane = tid & 31, w = tid >> 5;
    int q0 = qt * 64;
    const float scale = 0.125f;

    const float* Qp = qkv;
    const float* Kp = qkv + (size_t)BT_*D_;
    const float* Vp = qkv + (size_t)2*BT_*D_;

    int lrow = tid >> 2, le0 = (tid & 3) * 16;
    int m0 = (w >> 1) * 16, n0 = (w & 1) * 32;
    int rq = lane >> 2, cq = lane & 3;
    int sr = tid >> 2, seg = tid & 3;

    {
        const float* src = Qp + (size_t)(b*T_ + q0 + lrow) * D_ + h*DH_ + le0;
        #pragma unroll
        for (int u = 0; u < 4; u++)
            *(float4*)&Qh[lrow*AS + le0 + u*4] = *(const float4*)(src + u*4);
        if (tid < 64) qid[tid] = ids[b*T_ + q0 + tid];
    }
    __syncthreads();
    int qid0 = qid[0], qidL = qid[63];

    float m = -1e30f, l = 0.f;

    for (int kt = 0; kt < 16; kt++) {
        int k0 = kt * 64;
        if (tid < 64) kid[tid] = ids[b*T_ + k0 + tid];
        __syncthreads();
        if (kid[63] < qid0 || qidL < kid[0]) continue;
        {
            const float* src = Kp + (size_t)(b*T_ + k0 + lrow) * D_ + h*DH_ + le0;
            #pragma unroll
            for (int u = 0; u < 4; u++)
                *(float4*)&Kh[lrow*AS + le0 + u*4] = *(const float4*)(src + u*4);
        }
        __syncthreads();
        float dq[4][4];
        #pragma unroll
        for (int fn = 0; fn < 4; fn++)
            #pragma unroll
            for (int u = 0; u < 4; u++) dq[fn][u] = 0.f;
        #pragma unroll
        for (int ks = 0; ks < 8; ks++) {
            int kk = ks*8 + cq;
            int arr = m0 + rq;
            uint32_t ah[4] = { __float_as_uint(Qh[ arr   *AS + kk]),
                               __float_as_uint(Qh[(arr+8)*AS + kk]),
                               __float_as_uint(Qh[ arr   *AS + kk + 4]),
                               __float_as_uint(Qh[(arr+8)*AS + kk + 4]) };
            #pragma unroll
            for (int fn = 0; fn < 4; fn++) {
                int bnr = n0 + fn*8 + rq;
                uint32_t bh[2] = { __float_as_uint(Kh[bnr*AS + kk]),
                                   __float_as_uint(Kh[bnr*AS + kk + 4]) };
                MMA_TF32(dq[fn], ah, bh);
            }
        }
        #pragma unroll
        for (int fn = 0; fn < 4; fn++) {
            int i0 = m0 + rq, j0 = n0 + fn*8 + 2*cq;
            float s0 = dq[fn][0]*scale, s1 = dq[fn][1]*scale;
            float s2 = dq[fn][2]*scale, s3 = dq[fn][3]*scale;
            int qa = qid[i0], qb = qid[i0+8], ka = kid[j0], kb = kid[j0+1];
            if (qa != ka) s0 = -1e30f;
            if (qa != kb) s1 = -1e30f;
            if (qb != ka) s2 = -1e30f;
            if (qb != kb) s3 = -1e30f;
            Ps[ i0   *AS + j0]     = s0;
            Ps[ i0   *AS + j0 + 1] = s1;
            Ps[(i0+8)*AS + j0]     = s2;
            Ps[(i0+8)*AS + j0 + 1] = s3;
        }
        __syncthreads();
        {
            float sv[16]; float tm = -1e30f;
            #pragma unroll
            for (int u = 0; u < 4; u++) {
                float4 v = *(const float4*)&Ps[sr*AS + seg*16 + u*4];
                sv[u*4+0] = v.x; sv[u*4+1] = v.y; sv[u*4+2] = v.z; sv[u*4+3] = v.w;
                tm = fmaxf(tm, fmaxf(fmaxf(v.x, v.y), fmaxf(v.z, v.w)));
            }
            tm = fmaxf(tm, __shfl_xor_sync(0xffffffffu, tm, 1));
            tm = fmaxf(tm, __shfl_xor_sync(0xffffffffu, tm, 2));
            float nm = fmaxf(m, tm);
            float es = 0.f;
            #pragma unroll
            for (int it = 0; it < 16; it++) es += __expf(sv[it] - nm);
            es += __shfl_xor_sync(0xffffffffu, es, 1);
            es += __shfl_xor_sync(0xffffffffu, es, 2);
            l = l * __expf(m - nm) + es;
            m = nm;
        }
    }
    __syncthreads();
    if (seg == 0) { ms[sr] = m; ls[sr] = 1.f / l; }
    __syncthreads();

    float pacc[4][4];
    #pragma unroll
    for (int fn = 0; fn < 4; fn++)
        #pragma unroll
        for (int u = 0; u < 4; u++) pacc[fn][u] = 0.f;

    for (int kt = 0; kt < 16; kt++) {
        int k0 = kt * 64;
        if (tid < 64) kid[tid] = ids[b*T_ + k0 + tid];
        __syncthreads();
        if (kid[63] < qid0 || qidL < kid[0]) {
            if (tid < 64)
                part[((size_t)((b*H_ + h)*16 + qt))*T_ + k0 + tid] = 0.f;
            continue;
        }
        {
            const float* ksrc = Kp + (size_t)(b*T_ + k0 + lrow) * D_ + h*DH_ + le0;
            #pragma unroll
            for (int u = 0; u < 4; u++)
                *(float4*)&Kh[lrow*AS + le0 + u*4] = *(const float4*)(ksrc + u*4);
            const float* vsrc = Vp + (size_t)(b*T_ + k0 + lrow) * D_ + h*DH_ + le0;
            #pragma unroll
            for (int u = 0; u < 4; u++) {
                float4 v = *(const float4*)(vsrc + u*4);
                Vt[(le0 + u*4 + 0)*AS + lrow] = v.x;
                Vt[(le0 + u*4 + 1)*AS + lrow] = v.y;
                Vt[(le0 + u*4 + 2)*AS + lrow] = v.z;
                Vt[(le0 + u*4 + 3)*AS + lrow] = v.w;
            }
        }
        __syncthreads();
        float dq[4][4];
        #pragma unroll
        for (int fn = 0; fn < 4; fn++)
            #pragma unroll
            for (int u = 0; u < 4; u++) dq[fn][u] = 0.f;
        #pragma unroll
        for (int ks = 0; ks < 8; ks++) {
            int kk = ks*8 + cq;
            int arr = m0 + rq;
            uint32_t ah[4] = { __float_as_uint(Qh[ arr   *AS + kk]),
                               __float_as_uint(Qh[(arr+8)*AS + kk]),
                               __float_as_uint(Qh[ arr   *AS + kk + 4]),
                               __float_as_uint(Qh[(arr+8)*AS + kk + 4]) };
            #pragma unroll
            for (int fn = 0; fn < 4; fn++) {
                int bnr = n0 + fn*8 + rq;
                uint32_t bh[2] = { __float_as_uint(Kh[bnr*AS + kk]),
                                   __float_as_uint(Kh[bnr*AS + kk + 4]) };
                MMA_TF32(dq[fn], ah, bh);
            }
        }
        #pragma unroll
        for (int fn = 0; fn < 4; fn++) {
            int i0 = m0 + rq, j0 = n0 + fn*8 + 2*cq;
            float ma = ms[i0], la = ls[i0];
            float mb = ms[i0+8], lb = ls[i0+8];
            float p0 = __expf(dq[fn][0]*scale - ma) * la;
            float p1 = __expf(dq[fn][1]*scale - ma) * la;
            float p2 = __expf(dq[fn][2]*scale - mb) * lb;
            float p3 = __expf(dq[fn][3]*scale - mb) * lb;
            int qa = qid[i0], qb = qid[i0+8], ka = kid[j0], kb = kid[j0+1];
            if (qa != ka) p0 = 0.f;
            if (qa != kb) p1 = 0.f;
            if (qb != ka) p2 = 0.f;
            if (qb != kb) p3 = 0.f;
            Ps[ i0   *AS + j0]     = p0;
            Ps[ i0   *AS + j0 + 1] = p1;
            Ps[(i0+8)*AS + j0]     = p2;
            Ps[(i0+8)*AS + j0 + 1] = p3;
        }
        __syncthreads();
        if (tid < 64) {
            double cs = 0.0;
            #pragma unroll
            for (int i = 0; i < 64; i++) cs += (double)Ps[i*AS + tid];
            part[((size_t)((b*H_ + h)*16 + qt))*T_ + k0 + tid] = (float)cs;
        }
        #pragma unroll
        for (int ks = 0; ks < 8; ks++) {
            int kk = ks*8 + cq;
            int arr = m0 + rq;
            uint32_t ap[4] = { __float_as_uint(Ps[ arr   *AS + kk]),
                               __float_as_uint(Ps[(arr+8)*AS + kk]),
                               __float_as_uint(Ps[ arr   *AS + kk + 4]),
                               __float_as_uint(Ps[(arr+8)*AS + kk + 4]) };
            #pragma unroll
            for (int fn = 0; fn < 4; fn++) {
                int bnr = n0 + fn*8 + rq;
                uint32_t bv[2] = { __float_as_uint(Vt[bnr*AS + kk]),
                                   __float_as_uint(Vt[bnr*AS + kk + 4]) };
                MMA_TF32(pacc[fn], ap, bv);
            }
        }
    }
    #pragma unroll
    for (int fn = 0; fn < 4; fn++) {
        int r  = b*T_ + q0 + m0 + rq;
        int cc = h*DH_ + n0 + fn*8 + 2*cq;
        *(float2*)&ctx[(size_t)r*D_ + cc]       = make_float2(pacc[fn][0], pacc[fn][1]);
        *(float2*)&ctx[(size_t)(r+8)*D_ + cc]   = make_float2(pacc[fn][2], pacc[fn][3]);
    }
}

// ---------------- deterministic fp64 reduction of prob column sums ---------
__global__ void reduce_part_kernel(const float* __restrict__ part, double* __restrict__ wsum)
{
    int idx = blockIdx.x * 256 + threadIdx.x;
    int b = idx >> 10, j = idx & 1023;
    double s = 0.0;
    for (int g = 0; g < H_*16; g++)
        s += (double)part[((size_t)(b*H_*16 + g)) * T_ + j];
    wsum[idx] = s;
}

// ---------------- y = LayerNorm(x + r), row = 512 ---------------------------
__global__ void add_ln_kernel(const float* __restrict__ x, const float* __restrict__ r,
                              float* __restrict__ y)
{
    __shared__ float sm[256];
    int row = blockIdx.x, tid = threadIdx.x;
    size_t base = (size_t)row * D_;
    float v0 = x[base + tid]        + r[base + tid];
    float v1 = x[base + 256 + tid]  + r[base + 256 + tid];
    sm[tid] = v0 + v1; __syncthreads();
    for (int s = 128; s > 0; s >>= 1) { if (tid < s) sm[tid] += sm[tid + s]; __syncthreads(); }
    float mean = sm[0] * (1.f / D_); __syncthreads();
    float d0 = v0 - mean, d1 = v1 - mean;
    sm[tid] = d0*d0 + d1*d1; __syncthreads();
    for (int s = 128; s > 0; s >>= 1) { if (tid < s) sm[tid] += sm[tid + s]; __syncthreads(); }
    float var = sm[0] * (1.f / D_);
    float inv = 1.f / sqrtf(var + 1e-5f);
    y[base + tid]       = d0 * inv;
    y[base + 256 + tid] = d1 * inv;
}

// ---------------- window-id scan (exact replica of reference scan, fp64) ----
__global__ void scan_kernel(const double* __restrict__ wsum, int* __restrict__ ids,
                            int* __restrict__ ws, int* __restrict__ we)
{
    __shared__ double smn[256], smx[256];
    int b = blockIdx.x, tid = threadIdx.x;
    double mn = 1e300, mx = -1e300;
    for (int t = tid; t < T_; t += 256) {
        double v = wsum[b*T_ + t] * (1.0 / H_);
        mn = fmin(mn, v); mx = fmax(mx, v);
    }
    smn[tid] = mn; smx[tid] = mx; __syncthreads();
    for (int s = 128; s > 0; s >>= 1) {
        if (tid < s) { smn[tid] = fmin(smn[tid], smn[tid+s]); smx[tid] = fmax(smx[tid], smx[tid+s]); }
        __syncthreads();
    }
    for (int t = tid; t < T_; t += 256) { ws[b*T_ + t] = 0; we[b*T_ + t] = 0; }
    __syncthreads();
    if (tid == 0) {
        double MN = smn[0], MX = smx[0];
        double denom = MX - MN + 1e-8;
        double thr = MN + 0.5 * denom;
        int cur = (wsum[b*T_ + 0] * (1.0 / H_)) >= thr ? 1 : 0;
        int start = 0, wid = 0;
        ids[b*T_ + 0] = 0;
        for (int t = 1; t < T_; t++) {
            int wt = (wsum[b*T_ + t] * (1.0 / H_)) >= thr ? 1 : 0;
            if (wt == cur) {
            } else if (start + 1 == t) {
                cur = wt;
            } else {
                cur = wt; start = t; wid++;
            }
            ids[b*T_ + t] = wid;
        }
        int prev = -1;
        for (int t = 0; t < T_; t++) {
            int w = ids[b*T_ + t];
            if (w != prev) { ws[b*T_ + w] = t; prev = w; }
            we[b*T_ + w] = t + 1;
        }
    }
}

// ---------------- wl = softmax_j(wsum/H) ------------------------------------
__global__ void wl_softmax_kernel(const double* __restrict__ wsum, float* __restrict__ wl)
{
    __shared__ float sm[256];
    int b = blockIdx.x, tid = threadIdx.x;
    float vals[4];
    float mx = -1e30f;
    #pragma unroll
    for (int i = 0; i < 4; i++) {
        vals[i] = (float)(wsum[b*T_ + tid + i*256] * (1.0 / H_));
        mx = fmaxf(mx, vals[i]);
    }
    sm[tid] = mx; __syncthreads();
    for (int s = 128; s > 0; s >>= 1) { if (tid < s) sm[tid] = fmaxf(sm[tid], sm[tid+s]); __syncthreads(); }
    float M = sm[0]; __syncthreads();
    float e[4], acc = 0.f;
    #pragma unroll
    for (int i = 0; i < 4; i++) { e[i] = expf(vals[i] - M); acc += e[i]; }
    sm[tid] = acc; __syncthreads();
    for (int s = 128; s > 0; s >>= 1) { if (tid < s) sm[tid] += sm[tid+s]; __syncthreads(); }
    float inv = 1.f / sm[0];
    #pragma unroll
    for (int i = 0; i < 4; i++) wl[b*T_ + tid + i*256] = e[i] * inv;
}

// ---------------- window-weighted pooling (deterministic gather) ------------
__global__ void word_tokens_kernel(const float* __restrict__ outl, const float* __restrict__ wl,
                                   const int* __restrict__ ws, const int* __restrict__ we,
                                   float* __restrict__ out)
{
    int w = blockIdx.x, b = blockIdx.y, tid = threadIdx.x;
    int s = ws[b*T_ + w], e = we[b*T_ + w];
    float acc[4] = {0.f, 0.f, 0.f, 0.f};
    for (int t = s; t < e; t++) {
        float g = wl[b*T_ + t];
        const float* row = outl + (size_t)(b*T_ + t) * D_;
        #pragma unroll
        for (int u = 0; u < 4; u++) acc[u] += g * row[tid + u*128];
    }
    float* dst = out + ((size_t)(b*2*T_ + w)) * D_;
    #pragma unroll
    for (int u = 0; u < 4; u++) dst[tid + u*128] = acc[u];
}

// ---------------- copy x into second half of concat output ------------------
__global__ void copy_x_kernel(const float* __restrict__ x, float* __restrict__ out)
{
    int idx = blockIdx.x * 256 + threadIdx.x;
    int b = (idx * 4) / (T_*D_);
    float4 v = *(const float4*)&x[(size_t)idx * 4];
    *(float4*)&out[(size_t)idx * 4 + (size_t)(b + 1) * T_ * D_] = v;
}

// ---------------- window_mapping output -------------------------------------
__global__ void winmap_kernel(const int* __restrict__ ids, float* __restrict__ out2)
{
    int idx = blockIdx.x * 256 + threadIdx.x;
    int e0 = idx * 4;
    int b = e0 >> 20;
    int k = (e0 >> 10) & 1023;
    int j = e0 & 1023;
    const int* idr = ids + b*T_;
    float4 v;
    v.x = (idr[j+0] == k) ? 1.f : 0.f;
    v.y = (idr[j+1] == k) ? 1.f : 0.f;
    v.z = (idr[j+2] == k) ? 1.f : 0.f;
    v.w = (idr[j+3] == k) ? 1.f : 0.f;
    *(float4*)&out2[(size_t)e0] = v;
}

// ---------------- host launcher ---------------------------------------------
#define SMEM_AM  (4*64*AS*4 + 1024)

extern "C" void kernel_launch(void* const* d_in, const int* in_sizes, int n_in,
                              void* d_out, int out_size)
{
    const float* x       = (const float*)d_in[0];
    const float* v_qkv_w = (const float*)d_in[1];
    const float* v_out_w = (const float*)d_in[2];
    const float* v_w1    = (const float*)d_in[3];
    const float* v_w2    = (const float*)d_in[4];
    const float* l_qkv_w = (const float*)d_in[5];
    const float* l_out_w = (const float*)d_in[6];
    const float* l_w1    = (const float*)d_in[7];
    const float* l_w2    = (const float*)d_in[8];
    float* out = (float*)d_out;

    float *qkv, *ctx, *tmp, *h1, *ffn, *outv, *outl, *part, *wl, *wT, *scores;
    double *wsum;
    int *ids, *ws, *we;
    cudaGetSymbolAddress((void**)&qkv,  g_qkv);
    cudaGetSymbolAddress((void**)&ctx,  g_ctx);
    cudaGetSymbolAddress((void**)&tmp,  g_tmp);
    cudaGetSymbolAddress((void**)&h1,   g_h1);
    cudaGetSymbolAddress((void**)&ffn,  g_ffn);
    cudaGetSymbolAddress((void**)&outv, g_outv);
    cudaGetSymbolAddress((void**)&outl, g_outl);
    cudaGetSymbolAddress((void**)&part, g_part);
    cudaGetSymbolAddress((void**)&wsum, g_wsum);
    cudaGetSymbolAddress((void**)&wl,   g_wl);
    cudaGetSymbolAddress((void**)&ids,  g_ids);
    cudaGetSymbolAddress((void**)&ws,   g_ws);
    cudaGetSymbolAddress((void**)&we,   g_we);
    cudaGetSymbolAddress((void**)&wT,   g_wT);
    cudaGetSymbolAddress((void**)&scores, g_scores);

    cudaFuncSetAttribute(gemm_bf16_kernel, cudaFuncAttributeMaxDynamicSharedMemorySize, GB_SMEM);
    cudaFuncSetAttribute(gemm_mma3_kernel, cudaFuncAttributeMaxDynamicSharedMemorySize, G3_SMEM);
    cudaFuncSetAttribute(attn4_kernel, cudaFuncAttributeMaxDynamicSharedMemorySize, SMEM_A4);
    cudaFuncSetAttribute(attn_masked_kernel, cudaFuncAttributeMaxDynamicSharedMemorySize, SMEM_AM);

    // ===== transpose all weights (one batched launch) ====
    transpose_all_kernel<<<6144, dim3(32,8)>>>(v_qkv_w, l_qkv_w, v_out_w, l_out_w,
                                               v_w1, l_w1, v_w2, l_w2, wT);

    dim3 gAttn(T_/64, H_, B_);
    dim3 gtD(D_/128, BT_/128, 1);
    dim3 gtF1(FF_/128, BT_/128, 1);
    dim3 gtQK(D_/128, BT_/128, 2);
    dim3 gtQKV(D_/128, BT_/128, 3);

    // ===== layer 1 (vanilla) =====
    gemm_mma3_kernel<<<gtQK, 256, G3_SMEM>>>(x, wT + WT_VQKV, qkv, D_, D_,
                                             (long long)D_*D_, (long long)BT_*D_);
    gemm_bf16_kernel<<<gtD, 128, GB_SMEM>>>(x, wT + WT_VQKV + 2*D_*D_, qkv + (size_t)2*BT_*D_,
                                            D_, D_, 0, 0, 0);
    attn4_kernel<<<gAttn, 256, SMEM_A4>>>(qkv, ctx, part, scores);
    reduce_part_kernel<<<(B_*T_)/256, 256>>>(part, wsum);
    gemm_bf16_kernel<<<gtD, 128, GB_SMEM>>>(ctx, wT + WT_VOUT, tmp, D_, D_, 0, 0, 0);
    add_ln_kernel<<<BT_, 256>>>(x, tmp, h1);
    gemm_bf16_kernel<<<gtF1, 128, GB_SMEM>>>(h1, wT + WT_VW1, ffn, FF_, D_, 0, 0, 1);
    gemm_bf16_kernel<<<gtD, 128, GB_SMEM>>>(ffn, wT + WT_VW2, tmp, D_, FF_, 0, 0, 0);
    add_ln_kernel<<<BT_, 256>>>(h1, tmp, outv);

    // ===== dynamic window mask =====
    scan_kernel<<<B_, 256>>>(wsum, ids, ws, we);

    // ===== layer 2 (masked) =====
    gemm_bf16_kernel<<<gtQKV, 128, GB_SMEM>>>(outv, wT + WT_LQKV, qkv, D_, D_,
                                              (long long)D_*D_, (long long)BT_*D_, 0);
    attn_masked_kernel<<<gAttn, 256, SMEM_AM>>>(qkv, ids, ctx, part);
    reduce_part_kernel<<<(B_*T_)/256, 256>>>(part, wsum);
    gemm_bf16_kernel<<<gtD, 128, GB_SMEM>>>(ctx, wT + WT_LOUT, tmp, D_, D_, 0, 0, 0);
    add_ln_kernel<<<BT_, 256>>>(outv, tmp, h1);
    gemm_bf16_kernel<<<gtF1, 128, GB_SMEM>>>(h1, wT + WT_LW1, ffn, FF_, D_, 0, 0, 1);
    gemm_bf16_kernel<<<gtD, 128, GB_SMEM>>>(ffn, wT + WT_LW2, tmp, D_, FF_, 0, 0, 0);
    add_ln_kernel<<<BT_, 256>>>(h1, tmp, outl);

    // ===== outputs =====
    wl_softmax_kernel<<<B_, 256>>>(wsum, wl);
    word_tokens_kernel<<<dim3(T_, B_), 128>>>(outl, wl, ws, we, out);
    copy_x_kernel<<<(B_*T_*D_/4)/256, 256>>>(x, out);
    winmap_kernel<<<(B_*T_*T_/4)/256, 256>>>(ids, out + (size_t)B_*2*T_*D_);
}

// round 9
// speedup vs baseline: 5.3533x; 1.0646x over previous
#include <cuda_runtime.h>
#include <cuda_bf16.h>
#include <math.h>
#include <stdint.h>

// Problem constants
#define B_  8
#define T_  1024
#define D_  512
#define FF_ 2048
#define H_  8
#define DH_ 64
#define BT_ (B_*T_)          // 8192 rows

// ---------------- scratch (device globals; no allocation allowed) ----------
__device__ float  g_qkv [3*BT_*D_];
__device__ float  g_ctx [BT_*D_];
__device__ float  g_tmp [BT_*D_];
__device__ float  g_h1  [BT_*D_];
__device__ float  g_ffn [BT_*FF_];
__device__ float  g_outv[BT_*D_];
__device__ float  g_outl[BT_*D_];
__device__ float  g_part[B_*H_*16*T_];
__device__ double g_wsum[B_*T_];
__device__ float  g_wl  [B_*T_];
__device__ int    g_ids [B_*T_];
__device__ int    g_ws  [B_*T_];
__device__ int    g_we  [B_*T_];
__device__ float  g_wT  [6291456];      // transposed weights
__device__ float  g_scores[(size_t)B_*H_*T_*T_];  // layer-1 exp(score) cache

// transposed-weight offsets (floats)
#define WT_LQKV 0
#define WT_VOUT 786432
#define WT_LOUT 1048576
#define WT_VW1  1310720
#define WT_LW1  2359296
#define WT_VW2  3407872
#define WT_LW2  4456448
#define WT_VQKV 5505024

// ---------------- tf32 helpers ----------------------------------------------
__device__ __forceinline__ float f2tf32(float x) {
    uint32_t u;
    asm("cvt.rna.tf32.f32 %0, %1;" : "=r"(u) : "f"(x));
    return __uint_as_float(u);
}
__device__ __forceinline__ void split_tf32(float x, uint32_t& hi, uint32_t& lo) {
    float h = f2tf32(x);
    float l = f2tf32(x - h);
    hi = __float_as_uint(h);
    lo = __float_as_uint(l);
}
#define MMA_TF32(d, a, b) \
    asm volatile("mma.sync.aligned.m16n8k8.row.col.f32.tf32.tf32.f32 " \
        "{%0,%1,%2,%3}, {%4,%5,%6,%7}, {%8,%9}, {%0,%1,%2,%3};" \
        : "+f"((d)[0]), "+f"((d)[1]), "+f"((d)[2]), "+f"((d)[3]) \
        : "r"((a)[0]), "r"((a)[1]), "r"((a)[2]), "r"((a)[3]), \
          "r"((b)[0]), "r"((b)[1]))
#define MMA_BF16(d, a, b) \
    asm volatile("mma.sync.aligned.m16n8k16.row.col.f32.bf16.bf16.f32 " \
        "{%0,%1,%2,%3}, {%4,%5,%6,%7}, {%8,%9}, {%0,%1,%2,%3};" \
        : "+f"((d)[0]), "+f"((d)[1]), "+f"((d)[2]), "+f"((d)[3]) \
        : "r"((a)[0]), "r"((a)[1]), "r"((a)[2]), "r"((a)[3]), \
          "r"((b)[0]), "r"((b)[1]))

__device__ __forceinline__ uint32_t pack_bf16x2(float lo, float hi) {
    __nv_bfloat162 h = __float22bfloat162_rn(make_float2(lo, hi));
    return *(uint32_t*)&h;
}

// ---------------- batched weight transpose ----------------------------------
__global__ void transpose_all_kernel(
    const float* __restrict__ vqkv, const float* __restrict__ lqkv,
    const float* __restrict__ vout, const float* __restrict__ lout,
    const float* __restrict__ vw1,  const float* __restrict__ lw1,
    const float* __restrict__ vw2,  const float* __restrict__ lw2,
    float* __restrict__ wT)
{
    __shared__ float t[32][33];
    int bid = blockIdx.x;
    int task, local;
    if (bid < 2048) { task = bid >> 8; local = bid & 255; }
    else { int r = bid - 2048; task = 8 + (r >> 10); local = r & 1023; }
    const float* src; float* dst; int R, C;
    switch (task) {
        case 0:  src = vqkv;           dst = wT + WT_VQKV;           R = 512;  C = 512;  break;
        case 1:  src = vqkv + 262144;  dst = wT + WT_VQKV + 262144;  R = 512;  C = 512;  break;
        case 2:  src = vqkv + 524288;  dst = wT + WT_VQKV + 524288;  R = 512;  C = 512;  break;
        case 3:  src = lqkv;           dst = wT + WT_LQKV;           R = 512;  C = 512;  break;
        case 4:  src = lqkv + 262144;  dst = wT + WT_LQKV + 262144;  R = 512;  C = 512;  break;
        case 5:  src = lqkv + 524288;  dst = wT + WT_LQKV + 524288;  R = 512;  C = 512;  break;
        case 6:  src = vout;           dst = wT + WT_VOUT;           R = 512;  C = 512;  break;
        case 7:  src = lout;           dst = wT + WT_LOUT;           R = 512;  C = 512;  break;
        case 8:  src = vw1;            dst = wT + WT_VW1;            R = 512;  C = 2048; break;
        case 9:  src = lw1;            dst = wT + WT_LW1;            R = 512;  C = 2048; break;
        case 10: src = vw2;            dst = wT + WT_VW2;            R = 2048; C = 512;  break;
        default: src = lw2;            dst = wT + WT_LW2;            R = 2048; C = 512;  break;
    }
    int nbx = C >> 5;
    int c0 = (local % nbx) * 32, r0 = (local / nbx) * 32;
    int tx = threadIdx.x, ty = threadIdx.y;
    #pragma unroll
    for (int i = 0; i < 32; i += 8)
        t[ty+i][tx] = src[(size_t)(r0+ty+i)*C + c0+tx];
    __syncthreads();
    #pragma unroll
    for (int i = 0; i < 32; i += 8)
        dst[(size_t)(c0+ty+i)*R + r0+tx] = t[tx][ty+i];
}

// ---------------- bf16 tensor GEMM (continuous path) ------------------------
#define MSB 40
#define GB_SMEM (4 * 128 * MSB * 2)
__global__ __launch_bounds__(128)
void gemm_bf16_kernel(const float* __restrict__ A, const float* __restrict__ BTs,
                      float* __restrict__ Cs, int N, int K,
                      long long bt_z, long long c_z, int relu)
{
    extern __shared__ char smraw[];
    __nv_bfloat16* sb = (__nv_bfloat16*)smraw;
    __nv_bfloat16* Asm[2] = { sb,            sb + 128*MSB };
    __nv_bfloat16* Bsm[2] = { sb + 2*128*MSB, sb + 3*128*MSB };

    const float* BT = BTs + (long long)blockIdx.z * bt_z;
    float*       C  = Cs  + (long long)blockIdx.z * c_z;

    int tid = threadIdx.x, lane = tid & 31, wid = tid >> 5;
    int wm = (wid >> 1) * 64, wn = (wid & 1) * 64;
    int bm = blockIdx.y * 128, bn = blockIdx.x * 128;
    int col4 = tid & 7, rbase = tid >> 3;
    int rq = lane >> 2, cq = lane & 3;

    float d[4][8][4];
    #pragma unroll
    for (int i = 0; i < 4; i++)
        #pragma unroll
        for (int j = 0; j < 8; j++)
            #pragma unroll
            for (int u = 0; u < 4; u++) d[i][j][u] = 0.f;

    float4 ar[8], br[8];
    #pragma unroll
    for (int j = 0; j < 8; j++) {
        ar[j] = *(const float4*)&A [(size_t)(bm + rbase + j*16) * K + col4*4];
        br[j] = *(const float4*)&BT[(size_t)(bn + rbase + j*16) * K + col4*4];
    }
    #pragma unroll
    for (int j = 0; j < 8; j++) {
        int r = rbase + j*16;
        uint2 pa = make_uint2(pack_bf16x2(ar[j].x, ar[j].y), pack_bf16x2(ar[j].z, ar[j].w));
        uint2 pb = make_uint2(pack_bf16x2(br[j].x, br[j].y), pack_bf16x2(br[j].z, br[j].w));
        *(uint2*)&Asm[0][r*MSB + col4*4] = pa;
        *(uint2*)&Bsm[0][r*MSB + col4*4] = pb;
    }
    __syncthreads();

    int nc = K / 32;
    for (int c = 0; c < nc; c++) {
        int buf = c & 1;
        if (c + 1 < nc) {
            int k0 = (c + 1) * 32;
            #pragma unroll
            for (int j = 0; j < 8; j++) {
                ar[j] = *(const float4*)&A [(size_t)(bm + rbase + j*16) * K + k0 + col4*4];
                br[j] = *(const float4*)&BT[(size_t)(bn + rbase + j*16) * K + k0 + col4*4];
            }
        }
        const __nv_bfloat16* a_s = Asm[buf];
        const __nv_bfloat16* b_s = Bsm[buf];
        #pragma unroll
        for (int ks = 0; ks < 2; ks++) {
            int k2 = ks*16 + cq*2;
            uint32_t af[4][4];
            #pragma unroll
            for (int fm = 0; fm < 4; fm++) {
                int r0 = wm + fm*16 + rq;
                af[fm][0] = *(const uint32_t*)&a_s[ r0     *MSB + k2];
                af[fm][1] = *(const uint32_t*)&a_s[(r0 + 8)*MSB + k2];
                af[fm][2] = *(const uint32_t*)&a_s[ r0     *MSB + k2 + 8];
                af[fm][3] = *(const uint32_t*)&a_s[(r0 + 8)*MSB + k2 + 8];
            }
            #pragma unroll
            for (int fn = 0; fn < 8; fn++) {
                int n0 = wn + fn*8 + rq;
                uint32_t bf[2] = { *(const uint32_t*)&b_s[n0*MSB + k2],
                                   *(const uint32_t*)&b_s[n0*MSB + k2 + 8] };
                #pragma unroll
                for (int fm = 0; fm < 4; fm++)
                    MMA_BF16(d[fm][fn], af[fm], bf);
            }
        }
        if (c + 1 < nc) {
            int nb = (c + 1) & 1;
            #pragma unroll
            for (int j = 0; j < 8; j++) {
                int r = rbase + j*16;
                uint2 pa = make_uint2(pack_bf16x2(ar[j].x, ar[j].y), pack_bf16x2(ar[j].z, ar[j].w));
                uint2 pb = make_uint2(pack_bf16x2(br[j].x, br[j].y), pack_bf16x2(br[j].z, br[j].w));
                *(uint2*)&Asm[nb][r*MSB + col4*4] = pa;
                *(uint2*)&Bsm[nb][r*MSB + col4*4] = pb;
            }
        }
        __syncthreads();
    }

    #pragma unroll
    for (int fm = 0; fm < 4; fm++) {
        #pragma unroll
        for (int fn = 0; fn < 8; fn++) {
            int r  = bm + wm + fm*16 + rq;
            int cc = bn + wn + fn*8 + 2*cq;
            float2 v0 = make_float2(d[fm][fn][0], d[fm][fn][1]);
            float2 v1 = make_float2(d[fm][fn][2], d[fm][fn][3]);
            if (relu) {
                v0.x = fmaxf(v0.x, 0.f); v0.y = fmaxf(v0.y, 0.f);
                v1.x = fmaxf(v1.x, 0.f); v1.y = fmaxf(v1.y, 0.f);
            }
            *(float2*)&C[(size_t)r*N + cc]       = v0;
            *(float2*)&C[(size_t)(r + 8)*N + cc] = v1;
        }
    }
}

// ---------------- 3xTF32 GEMM (decision path), fp32 smem + reg split --------
#define MS 36
#define G3_SMEM (4 * 128 * MS * 4)   // 2 bufs x (A+B), fp32 only = 73728
__global__ __launch_bounds__(256)
void gemm_mma3_kernel(const float* __restrict__ A, const float* __restrict__ BTs,
                      float* __restrict__ Cs, int N, int K,
                      long long bt_z, long long c_z)
{
    extern __shared__ float smf[];
    float* As[2] = { smf,            smf + 128*MS };
    float* Bs[2] = { smf + 2*128*MS, smf + 3*128*MS };

    const float* BT = BTs + (long long)blockIdx.z * bt_z;
    float*       C  = Cs  + (long long)blockIdx.z * c_z;

    int tid = threadIdx.x, lane = tid & 31, wid = tid >> 5;
    int wm = (wid >> 1) * 32, wn = (wid & 1) * 64;
    int bm = blockIdx.y * 128, bn = blockIdx.x * 128;
    int rbase = tid >> 1, cb = (tid & 1) * 16;

    float d[2][8][4];
    #pragma unroll
    for (int i = 0; i < 2; i++)
        #pragma unroll
        for (int j = 0; j < 8; j++)
            #pragma unroll
            for (int u = 0; u < 4; u++) d[i][j][u] = 0.f;

    float4 ar[4], br[4];
    #pragma unroll
    for (int j = 0; j < 4; j++) {
        ar[j] = *(const float4*)&A [(size_t)(bm + rbase) * K + cb + j*4];
        br[j] = *(const float4*)&BT[(size_t)(bn + rbase) * K + cb + j*4];
    }
    #pragma unroll
    for (int j = 0; j < 4; j++) {
        *(float4*)&As[0][rbase*MS + cb + j*4] = ar[j];
        *(float4*)&Bs[0][rbase*MS + cb + j*4] = br[j];
    }
    __syncthreads();

    int nc = K / 32;
    for (int c = 0; c < nc; c++) {
        int buf = c & 1;
        if (c + 1 < nc) {
            int k0 = (c + 1) * 32;
            #pragma unroll
            for (int j = 0; j < 4; j++) {
                ar[j] = *(const float4*)&A [(size_t)(bm + rbase) * K + k0 + cb + j*4];
                br[j] = *(const float4*)&BT[(size_t)(bn + rbase) * K + k0 + cb + j*4];
            }
        }
        const float* a_s = As[buf];
        const float* b_s = Bs[buf];
        #pragma unroll
        for (int ks = 0; ks < 4; ks++) {
            int kk = ks*8 + (lane & 3);
            int rq = lane >> 2;
            uint32_t afh[2][4], afl[2][4];
            #pragma unroll
            for (int fm = 0; fm < 2; fm++) {
                int r0 = wm + fm*16 + rq;
                split_tf32(a_s[ r0     *MS + kk    ], afh[fm][0], afl[fm][0]);
                split_tf32(a_s[(r0 + 8)*MS + kk    ], afh[fm][1], afl[fm][1]);
                split_tf32(a_s[ r0     *MS + kk + 4], afh[fm][2], afl[fm][2]);
                split_tf32(a_s[(r0 + 8)*MS + kk + 4], afh[fm][3], afl[fm][3]);
            }
            #pragma unroll
            for (int fn = 0; fn < 8; fn++) {
                int n0 = wn + fn*8 + rq;
                uint32_t bfh[2], bfl[2];
                split_tf32(b_s[n0*MS + kk    ], bfh[0], bfl[0]);
                split_tf32(b_s[n0*MS + kk + 4], bfh[1], bfl[1]);
                #pragma unroll
                for (int fm = 0; fm < 2; fm++) {
                    MMA_TF32(d[fm][fn], afh[fm], bfh);
                    MMA_TF32(d[fm][fn], afl[fm], bfh);
                    MMA_TF32(d[fm][fn], afh[fm], bfl);
                }
            }
        }
        if (c + 1 < nc) {
            int nb = (c + 1) & 1;
            #pragma unroll
            for (int j = 0; j < 4; j++) {
                *(float4*)&As[nb][rbase*MS + cb + j*4] = ar[j];
                *(float4*)&Bs[nb][rbase*MS + cb + j*4] = br[j];
            }
        }
        __syncthreads();
    }

    #pragma unroll
    for (int fm = 0; fm < 2; fm++) {
        #pragma unroll
        for (int fn = 0; fn < 8; fn++) {
            int r  = bm + wm + fm*16 + (lane >> 2);
            int cc = bn + wn + fn*8 + 2*(lane & 3);
            *(float2*)&C[(size_t)r*N + cc]       = make_float2(d[fm][fn][0], d[fm][fn][1]);
            *(float2*)&C[(size_t)(r + 8)*N + cc] = make_float2(d[fm][fn][2], d[fm][fn][3]);
        }
    }
}

// ---------------- layer-1 attention v5: fp32 smem, reg-split 3xTF32 ---------
#define AS 68
#define VS2 72   // V natural row stride (72 mod 32 = 8 -> conflict-free frags)
#define SMEM_A4 ((3*64*AS + 64*VS2 + 64)*4 + 256)
__global__ __launch_bounds__(256)
void attn4_kernel(const float* __restrict__ qkv, float* __restrict__ ctx,
                  float* __restrict__ part, float* __restrict__ ecache)
{
    extern __shared__ float smf[];
    float* Qf = smf;                  // [64][AS] fp32
    float* Kf = Qf + 64*AS;           // [64][AS] fp32
    float* Ps = Kf + 64*AS;           // [64][AS] e tile
    float* Vs = Ps + 64*AS;           // [64][VS2] natural
    float* zs = Vs + 64*VS2;          // [64]

    int qt = blockIdx.x, h = blockIdx.y, b = blockIdx.z;
    int tid = threadIdx.x, lane = tid & 31, w = tid >> 5;
    int q0 = qt * 64;
    const float scale = 0.125f;

    const float* Qp = qkv;
    const float* Kp = qkv + (size_t)BT_*D_;
    const float* Vp = qkv + (size_t)2*BT_*D_;
    float* ec = ecache + ((size_t)(b*H_ + h)*T_ + q0)*T_;

    int lrow = tid >> 2, le0 = (tid & 3) * 16;
    int m0 = (w >> 1) * 16, n0 = (w & 1) * 32;
    int rq = lane >> 2, cq = lane & 3;
    int sr = tid >> 2, seg = tid & 3;

    // load Q fp32
    {
        const float* src = Qp + (size_t)(b*T_ + q0 + lrow) * D_ + h*DH_ + le0;
        #pragma unroll
        for (int u = 0; u < 4; u++)
            *(float4*)&Qf[lrow*AS + le0 + u*4] = *(const float4*)(src + u*4);
    }

    float l = 0.f;
    float pacc[4][4];
    #pragma unroll
    for (int fn = 0; fn < 4; fn++)
        #pragma unroll
        for (int u = 0; u < 4; u++) pacc[fn][u] = 0.f;

    for (int kt = 0; kt < 16; kt++) {
        int k0 = kt * 64;
        __syncthreads();
        {
            const float* src = Kp + (size_t)(b*T_ + k0 + lrow) * D_ + h*DH_ + le0;
            #pragma unroll
            for (int u = 0; u < 4; u++)
                *(float4*)&Kf[lrow*AS + le0 + u*4] = *(const float4*)(src + u*4);
            const float* vsrc = Vp + (size_t)(b*T_ + k0 + lrow) * D_ + h*DH_ + le0;
            #pragma unroll
            for (int u = 0; u < 4; u++)
                *(float4*)&Vs[lrow*VS2 + le0 + u*4] = *(const float4*)(vsrc + u*4);
        }
        __syncthreads();
        // QK 3xTF32 with register hi/lo split
        float dq[4][4];
        #pragma unroll
        for (int fn = 0; fn < 4; fn++)
            #pragma unroll
            for (int u = 0; u < 4; u++) dq[fn][u] = 0.f;
        #pragma unroll
        for (int ks = 0; ks < 8; ks++) {
            int kk = ks*8 + cq;
            int arr = m0 + rq;
            uint32_t ah[4], al[4];
            split_tf32(Qf[ arr   *AS + kk    ], ah[0], al[0]);
            split_tf32(Qf[(arr+8)*AS + kk    ], ah[1], al[1]);
            split_tf32(Qf[ arr   *AS + kk + 4], ah[2], al[2]);
            split_tf32(Qf[(arr+8)*AS + kk + 4], ah[3], al[3]);
            #pragma unroll
            for (int fn = 0; fn < 4; fn++) {
                int bnr = n0 + fn*8 + rq;
                uint32_t bh[2], bl[2];
                split_tf32(Kf[bnr*AS + kk    ], bh[0], bl[0]);
                split_tf32(Kf[bnr*AS + kk + 4], bh[1], bl[1]);
                MMA_TF32(dq[fn], ah, bh);
                MMA_TF32(dq[fn], al, bh);
                MMA_TF32(dq[fn], ah, bl);
            }
        }
        // e = exp(score) once; write smem (float2) + gmem cache
        #pragma unroll
        for (int fn = 0; fn < 4; fn++) {
            int i0 = m0 + rq, j0 = n0 + fn*8 + 2*cq;
            float e0 = __expf(dq[fn][0]*scale);
            float e1 = __expf(dq[fn][1]*scale);
            float e2 = __expf(dq[fn][2]*scale);
            float e3 = __expf(dq[fn][3]*scale);
            *(float2*)&ec[(size_t)i0*T_ + k0 + j0]     = make_float2(e0, e1);
            *(float2*)&ec[(size_t)(i0+8)*T_ + k0 + j0] = make_float2(e2, e3);
            *(float2*)&Ps[ i0   *AS + j0] = make_float2(e0, e1);
            *(float2*)&Ps[(i0+8)*AS + j0] = make_float2(e2, e3);
        }
        __syncthreads();
        // row expsum accumulation
        {
            float es = 0.f;
            #pragma unroll
            for (int u = 0; u < 4; u++) {
                float4 v = *(const float4*)&Ps[sr*AS + seg*16 + u*4];
                es += (v.x + v.y) + (v.z + v.w);
            }
            es += __shfl_xor_sync(0xffffffffu, es, 1);
            es += __shfl_xor_sync(0xffffffffu, es, 2);
            l += es;
        }
        // unnormalized PV mma (tf32, V natural stride VS2)
        #pragma unroll
        for (int ks = 0; ks < 8; ks++) {
            int kk = ks*8 + cq;
            int arr = m0 + rq;
            uint32_t ap[4] = { __float_as_uint(f2tf32(Ps[ arr   *AS + kk])),
                               __float_as_uint(f2tf32(Ps[(arr+8)*AS + kk])),
                               __float_as_uint(f2tf32(Ps[ arr   *AS + kk + 4])),
                               __float_as_uint(f2tf32(Ps[(arr+8)*AS + kk + 4])) };
            #pragma unroll
            for (int fn = 0; fn < 4; fn++) {
                int bnr = n0 + fn*8 + rq;
                uint32_t bv[2] = { __float_as_uint(f2tf32(Vs[ kk   *VS2 + bnr])),
                                   __float_as_uint(f2tf32(Vs[(kk+4)*VS2 + bnr])) };
                MMA_TF32(pacc[fn], ap, bv);
            }
        }
    }
    __syncthreads();
    if (seg == 0) zs[sr] = 1.f / l;
    __syncthreads();

    // write ctx (scale rows by z)
    {
        float za = zs[m0 + rq], zb = zs[m0 + rq + 8];
        #pragma unroll
        for (int fn = 0; fn < 4; fn++) {
            int r  = b*T_ + q0 + m0 + rq;
            int cc = h*DH_ + n0 + fn*8 + 2*cq;
            *(float2*)&ctx[(size_t)r*D_ + cc]     = make_float2(pacc[fn][0]*za, pacc[fn][1]*za);
            *(float2*)&ctx[(size_t)(r+8)*D_ + cc] = make_float2(pacc[fn][2]*zb, pacc[fn][3]*zb);
        }
    }

    // ---- colsum sweep over cached e (fp64, deterministic) ----
    double cs[4] = {0.0, 0.0, 0.0, 0.0};
    for (int i = 0; i < 64; i++) {
        double zi = (double)zs[i];
        const float* row = ec + (size_t)i*T_;
        #pragma unroll
        for (int g = 0; g < 4; g++)
            cs[g] += (double)row[tid + g*256] * zi;
    }
    float* pr = part + ((size_t)((b*H_ + h)*16 + qt))*T_;
    #pragma unroll
    for (int g = 0; g < 4; g++) pr[tid + g*256] = (float)cs[g];
}

// ---------------- layer-2 masked attention (two-pass, tile skip) ------------
#define SMEM_AM ((3*64*AS + 64*VS2 + 128)*4 + 512)
__global__ __launch_bounds__(256)
void attn_masked_kernel(const float* __restrict__ qkv, const int* __restrict__ ids,
                        float* __restrict__ ctx, float* __restrict__ part)
{
    extern __shared__ float smf[];
    float* Qh = smf;
    float* Kh = Qh + 64*AS;
    float* Ps = Kh + 64*AS;
    float* Vs = Ps + 64*AS;           // [64][VS2] natural
    float* ms = Vs + 64*VS2;
    float* ls = ms + 64;
    int*   qid = (int*)(ls + 64);
    int*   kid = qid + 64;

    int qt = blockIdx.x, h = blockIdx.y, b = blockIdx.z;
    int tid = threadIdx.x, lane = tid & 31, w = tid >> 5;
    int q0 = qt * 64;
    const float scale = 0.125f;

    const float* Qp = qkv;
    const float* Kp = qkv + (size_t)BT_*D_;
    const float* Vp = qkv + (size_t)2*BT_*D_;

    int lrow = tid >> 2, le0 = (tid & 3) * 16;
    int m0 = (w >> 1) * 16, n0 = (w & 1) * 32;
    int rq = lane >> 2, cq = lane & 3;
    int sr = tid >> 2, seg = tid & 3;

    {
        const float* src = Qp + (size_t)(b*T_ + q0 + lrow) * D_ + h*DH_ + le0;
        #pragma unroll
        for (int u = 0; u < 4; u++)
            *(float4*)&Qh[lrow*AS + le0 + u*4] = *(const float4*)(src + u*4);
        if (tid < 64) qid[tid] = ids[b*T_ + q0 + tid];
    }
    __syncthreads();
    int qid0 = qid[0], qidL = qid[63];

    float m = -1e30f, l = 0.f;

    for (int kt = 0; kt < 16; kt++) {
        int k0 = kt * 64;
        if (tid < 64) kid[tid] = ids[b*T_ + k0 + tid];
        __syncthreads();
        if (kid[63] < qid0 || qidL < kid[0]) continue;
        {
            const float* src = Kp + (size_t)(b*T_ + k0 + lrow) * D_ + h*DH_ + le0;
            #pragma unroll
            for (int u = 0; u < 4; u++)
                *(float4*)&Kh[lrow*AS + le0 + u*4] = *(const float4*)(src + u*4);
        }
        __syncthreads();
        float dq[4][4];
        #pragma unroll
        for (int fn = 0; fn < 4; fn++)
            #pragma unroll
            for (int u = 0; u < 4; u++) dq[fn][u] = 0.f;
        #pragma unroll
        for (int ks = 0; ks < 8; ks++) {
            int kk = ks*8 + cq;
            int arr = m0 + rq;
            uint32_t ah[4] = { __float_as_uint(Qh[ arr   *AS + kk]),
                               __float_as_uint(Qh[(arr+8)*AS + kk]),
                               __float_as_uint(Qh[ arr   *AS + kk + 4]),
                               __float_as_uint(Qh[(arr+8)*AS + kk + 4]) };
            #pragma unroll
            for (int fn = 0; fn < 4; fn++) {
                int bnr = n0 + fn*8 + rq;
                uint32_t bh[2] = { __float_as_uint(Kh[bnr*AS + kk]),
                                   __float_as_uint(Kh[bnr*AS + kk + 4]) };
                MMA_TF32(dq[fn], ah, bh);
            }
        }
        #pragma unroll
        for (int fn = 0; fn < 4; fn++) {
            int i0 = m0 + rq, j0 = n0 + fn*8 + 2*cq;
            float s0 = dq[fn][0]*scale, s1 = dq[fn][1]*scale;
            float s2 = dq[fn][2]*scale, s3 = dq[fn][3]*scale;
            int qa = qid[i0], qb = qid[i0+8], ka = kid[j0], kb = kid[j0+1];
            if (qa != ka) s0 = -1e30f;
            if (qa != kb) s1 = -1e30f;
            if (qb != ka) s2 = -1e30f;
            if (qb != kb) s3 = -1e30f;
            *(float2*)&Ps[ i0   *AS + j0] = make_float2(s0, s1);
            *(float2*)&Ps[(i0+8)*AS + j0] = make_float2(s2, s3);
        }
        __syncthreads();
        {
            float sv[16]; float tm = -1e30f;
            #pragma unroll
            for (int u = 0; u < 4; u++) {
                float4 v = *(const float4*)&Ps[sr*AS + seg*16 + u*4];
                sv[u*4+0] = v.x; sv[u*4+1] = v.y; sv[u*4+2] = v.z; sv[u*4+3] = v.w;
                tm = fmaxf(tm, fmaxf(fmaxf(v.x, v.y), fmaxf(v.z, v.w)));
            }
            tm = fmaxf(tm, __shfl_xor_sync(0xffffffffu, tm, 1));
            tm = fmaxf(tm, __shfl_xor_sync(0xffffffffu, tm, 2));
            float nm = fmaxf(m, tm);
            float es = 0.f;
            #pragma unroll
            for (int it = 0; it < 16; it++) es += __expf(sv[it] - nm);
            es += __shfl_xor_sync(0xffffffffu, es, 1);
            es += __shfl_xor_sync(0xffffffffu, es, 2);
            l = l * __expf(m - nm) + es;
            m = nm;
        }
    }
    __syncthreads();
    if (seg == 0) { ms[sr] = m; ls[sr] = 1.f / l; }
    __syncthreads();

    float pacc[4][4];
    #pragma unroll
    for (int fn = 0; fn < 4; fn++)
        #pragma unroll
        for (int u = 0; u < 4; u++) pacc[fn][u] = 0.f;

    for (int kt = 0; kt < 16; kt++) {
        int k0 = kt * 64;
        if (tid < 64) kid[tid] = ids[b*T_ + k0 + tid];
        __syncthreads();
        if (kid[63] < qid0 || qidL < kid[0]) {
            if (tid < 64)
                part[((size_t)((b*H_ + h)*16 + qt))*T_ + k0 + tid] = 0.f;
            continue;
        }
        {
            const float* ksrc = Kp + (size_t)(b*T_ + k0 + lrow) * D_ + h*DH_ + le0;
            #pragma unroll
            for (int u = 0; u < 4; u++)
                *(float4*)&Kh[lrow*AS + le0 + u*4] = *(const float4*)(ksrc + u*4);
            const float* vsrc = Vp + (size_t)(b*T_ + k0 + lrow) * D_ + h*DH_ + le0;
            #pragma unroll
            for (int u = 0; u < 4; u++)
                *(float4*)&Vs[lrow*VS2 + le0 + u*4] = *(const float4*)(vsrc + u*4);
        }
        __syncthreads();
        float dq[4][4];
        #pragma unroll
        for (int fn = 0; fn < 4; fn++)
            #pragma unroll
            for (int u = 0; u < 4; u++) dq[fn][u] = 0.f;
        #pragma unroll
        for (int ks = 0; ks < 8; ks++) {
            int kk = ks*8 + cq;
            int arr = m0 + rq;
            uint32_t ah[4] = { __float_as_uint(Qh[ arr   *AS + kk]),
                               __float_as_uint(Qh[(arr+8)*AS + kk]),
                               __float_as_uint(Qh[ arr   *AS + kk + 4]),
                               __float_as_uint(Qh[(arr+8)*AS + kk + 4]) };
            #pragma unroll
            for (int fn = 0; fn < 4; fn++) {
                int bnr = n0 + fn*8 + rq;
                uint32_t bh[2] = { __float_as_uint(Kh[bnr*AS + kk]),
                                   __float_as_uint(Kh[bnr*AS + kk + 4]) };
                MMA_TF32(dq[fn], ah, bh);
            }
        }
        #pragma unroll
        for (int fn = 0; fn < 4; fn++) {
            int i0 = m0 + rq, j0 = n0 + fn*8 + 2*cq;
            float ma = ms[i0], la = ls[i0];
            float mb = ms[i0+8], lb = ls[i0+8];
            float p0 = __expf(dq[fn][0]*scale - ma) * la;
            float p1 = __expf(dq[fn][1]*scale - ma) * la;
            float p2 = __expf(dq[fn][2]*scale - mb) * lb;
            float p3 = __expf(dq[fn][3]*scale - mb) * lb;
            int qa = qid[i0], qb = qid[i0+8], ka = kid[j0], kb = kid[j0+1];
            if (qa != ka) p0 = 0.f;
            if (qa != kb) p1 = 0.f;
            if (qb != ka) p2 = 0.f;
            if (qb != kb) p3 = 0.f;
            *(float2*)&Ps[ i0   *AS + j0] = make_float2(p0, p1);
            *(float2*)&Ps[(i0+8)*AS + j0] = make_float2(p2, p3);
        }
        __syncthreads();
        if (tid < 64) {
            double cs = 0.0;
            #pragma unroll
            for (int i = 0; i < 64; i++) cs += (double)Ps[i*AS + tid];
            part[((size_t)((b*H_ + h)*16 + qt))*T_ + k0 + tid] = (float)cs;
        }
        #pragma unroll
        for (int ks = 0; ks < 8; ks++) {
            int kk = ks*8 + cq;
            int arr = m0 + rq;
            uint32_t ap[4] = { __float_as_uint(f2tf32(Ps[ arr   *AS + kk])),
                               __float_as_uint(f2tf32(Ps[(arr+8)*AS + kk])),
                               __float_as_uint(f2tf32(Ps[ arr   *AS + kk + 4])),
                               __float_as_uint(f2tf32(Ps[(arr+8)*AS + kk + 4])) };
            #pragma unroll
            for (int fn = 0; fn < 4; fn++) {
                int bnr = n0 + fn*8 + rq;
                uint32_t bv[2] = { __float_as_uint(f2tf32(Vs[ kk   *VS2 + bnr])),
                                   __float_as_uint(f2tf32(Vs[(kk+4)*VS2 + bnr])) };
                MMA_TF32(pacc[fn], ap, bv);
            }
        }
    }
    #pragma unroll
    for (int fn = 0; fn < 4; fn++) {
        int r  = b*T_ + q0 + m0 + rq;
        int cc = h*DH_ + n0 + fn*8 + 2*cq;
        *(float2*)&ctx[(size_t)r*D_ + cc]       = make_float2(pacc[fn][0], pacc[fn][1]);
        *(float2*)&ctx[(size_t)(r+8)*D_ + cc]   = make_float2(pacc[fn][2], pacc[fn][3]);
    }
}

// ---------------- deterministic fp64 reduction of prob column sums ---------
__global__ void reduce_part_kernel(const float* __restrict__ part, double* __restrict__ wsum)
{
    int idx = blockIdx.x * 256 + threadIdx.x;
    int b = idx >> 10, j = idx & 1023;
    double s = 0.0;
    for (int g = 0; g < H_*16; g++)
        s += (double)part[((size_t)(b*H_*16 + g)) * T_ + j];
    wsum[idx] = s;
}

// ---------------- y = LayerNorm(x + r), row = 512 ---------------------------
__global__ void add_ln_kernel(const float* __restrict__ x, const float* __restrict__ r,
                              float* __restrict__ y)
{
    __shared__ float sm[256];
    int row = blockIdx.x, tid = threadIdx.x;
    size_t base = (size_t)row * D_;
    float v0 = x[base + tid]        + r[base + tid];
    float v1 = x[base + 256 + tid]  + r[base + 256 + tid];
    sm[tid] = v0 + v1; __syncthreads();
    for (int s = 128; s > 0; s >>= 1) { if (tid < s) sm[tid] += sm[tid + s]; __syncthreads(); }
    float mean = sm[0] * (1.f / D_); __syncthreads();
    float d0 = v0 - mean, d1 = v1 - mean;
    sm[tid] = d0*d0 + d1*d1; __syncthreads();
    for (int s = 128; s > 0; s >>= 1) { if (tid < s) sm[tid] += sm[tid + s]; __syncthreads(); }
    float var = sm[0] * (1.f / D_);
    float inv = 1.f / sqrtf(var + 1e-5f);
    y[base + tid]       = d0 * inv;
    y[base + 256 + tid] = d1 * inv;
}

// ---------------- window-id scan (exact replica of reference scan, fp64) ----
__global__ void scan_kernel(const double* __restrict__ wsum, int* __restrict__ ids,
                            int* __restrict__ ws, int* __restrict__ we)
{
    __shared__ double smn[256], smx[256];
    int b = blockIdx.x, tid = threadIdx.x;
    double mn = 1e300, mx = -1e300;
    for (int t = tid; t < T_; t += 256) {
        double v = wsum[b*T_ + t] * (1.0 / H_);
        mn = fmin(mn, v); mx = fmax(mx, v);
    }
    smn[tid] = mn; smx[tid] = mx; __syncthreads();
    for (int s = 128; s > 0; s >>= 1) {
        if (tid < s) { smn[tid] = fmin(smn[tid], smn[tid+s]); smx[tid] = fmax(smx[tid], smx[tid+s]); }
        __syncthreads();
    }
    for (int t = tid; t < T_; t += 256) { ws[b*T_ + t] = 0; we[b*T_ + t] = 0; }
    __syncthreads();
    if (tid == 0) {
        double MN = smn[0], MX = smx[0];
        double denom = MX - MN + 1e-8;
        double thr = MN + 0.5 * denom;
        int cur = (wsum[b*T_ + 0] * (1.0 / H_)) >= thr ? 1 : 0;
        int start = 0, wid = 0;
        ids[b*T_ + 0] = 0;
        for (int t = 1; t < T_; t++) {
            int wt = (wsum[b*T_ + t] * (1.0 / H_)) >= thr ? 1 : 0;
            if (wt == cur) {
            } else if (start + 1 == t) {
                cur = wt;
            } else {
                cur = wt; start = t; wid++;
            }
            ids[b*T_ + t] = wid;
        }
        int prev = -1;
        for (int t = 0; t < T_; t++) {
            int w = ids[b*T_ + t];
            if (w != prev) { ws[b*T_ + w] = t; prev = w; }
            we[b*T_ + w] = t + 1;
        }
    }
}

// ---------------- wl = softmax_j(wsum/H) ------------------------------------
__global__ void wl_softmax_kernel(const double* __restrict__ wsum, float* __restrict__ wl)
{
    __shared__ float sm[256];
    int b = blockIdx.x, tid = threadIdx.x;
    float vals[4];
    float mx = -1e30f;
    #pragma unroll
    for (int i = 0; i < 4; i++) {
        vals[i] = (float)(wsum[b*T_ + tid + i*256] * (1.0 / H_));
        mx = fmaxf(mx, vals[i]);
    }
    sm[tid] = mx; __syncthreads();
    for (int s = 128; s > 0; s >>= 1) { if (tid < s) sm[tid] = fmaxf(sm[tid], sm[tid+s]); __syncthreads(); }
    float M = sm[0]; __syncthreads();
    float e[4], acc = 0.f;
    #pragma unroll
    for (int i = 0; i < 4; i++) { e[i] = expf(vals[i] - M); acc += e[i]; }
    sm[tid] = acc; __syncthreads();
    for (int s = 128; s > 0; s >>= 1) { if (tid < s) sm[tid] += sm[tid+s]; __syncthreads(); }
    float inv = 1.f / sm[0];
    #pragma unroll
    for (int i = 0; i < 4; i++) wl[b*T_ + tid + i*256] = e[i] * inv;
}

// ---------------- window-weighted pooling (deterministic gather) ------------
__global__ void word_tokens_kernel(const float* __restrict__ outl, const float* __restrict__ wl,
                                   const int* __restrict__ ws, const int* __restrict__ we,
                                   float* __restrict__ out)
{
    int w = blockIdx.x, b = blockIdx.y, tid = threadIdx.x;
    int s = ws[b*T_ + w], e = we[b*T_ + w];
    float acc[4] = {0.f, 0.f, 0.f, 0.f};
    for (int t = s; t < e; t++) {
        float g = wl[b*T_ + t];
        const float* row = outl + (size_t)(b*T_ + t) * D_;
        #pragma unroll
        for (int u = 0; u < 4; u++) acc[u] += g * row[tid + u*128];
    }
    float* dst = out + ((size_t)(b*2*T_ + w)) * D_;
    #pragma unroll
    for (int u = 0; u < 4; u++) dst[tid + u*128] = acc[u];
}

// ---------------- copy x into second half of concat output ------------------
__global__ void copy_x_kernel(const float* __restrict__ x, float* __restrict__ out)
{
    int idx = blockIdx.x * 256 + threadIdx.x;
    int b = (idx * 4) / (T_*D_);
    float4 v = *(const float4*)&x[(size_t)idx * 4];
    *(float4*)&out[(size_t)idx * 4 + (size_t)(b + 1) * T_ * D_] = v;
}

// ---------------- window_mapping output -------------------------------------
__global__ void winmap_kernel(const int* __restrict__ ids, float* __restrict__ out2)
{
    int idx = blockIdx.x * 256 + threadIdx.x;
    int e0 = idx * 4;
    int b = e0 >> 20;
    int k = (e0 >> 10) & 1023;
    int j = e0 & 1023;
    const int* idr = ids + b*T_;
    float4 v;
    v.x = (idr[j+0] == k) ? 1.f : 0.f;
    v.y = (idr[j+1] == k) ? 1.f : 0.f;
    v.z = (idr[j+2] == k) ? 1.f : 0.f;
    v.w = (idr[j+3] == k) ? 1.f : 0.f;
    *(float4*)&out2[(size_t)e0] = v;
}

// ---------------- host launcher ---------------------------------------------
extern "C" void kernel_launch(void* const* d_in, const int* in_sizes, int n_in,
                              void* d_out, int out_size)
{
    const float* x       = (const float*)d_in[0];
    const float* v_qkv_w = (const float*)d_in[1];
    const float* v_out_w = (const float*)d_in[2];
    const float* v_w1    = (const float*)d_in[3];
    const float* v_w2    = (const float*)d_in[4];
    const float* l_qkv_w = (const float*)d_in[5];
    const float* l_out_w = (const float*)d_in[6];
    const float* l_w1    = (const float*)d_in[7];
    const float* l_w2    = (const float*)d_in[8];
    float* out = (float*)d_out;

    float *qkv, *ctx, *tmp, *h1, *ffn, *outv, *outl, *part, *wl, *wT, *scores;
    double *wsum;
    int *ids, *ws, *we;
    cudaGetSymbolAddress((void**)&qkv,  g_qkv);
    cudaGetSymbolAddress((void**)&ctx,  g_ctx);
    cudaGetSymbolAddress((void**)&tmp,  g_tmp);
    cudaGetSymbolAddress((void**)&h1,   g_h1);
    cudaGetSymbolAddress((void**)&ffn,  g_ffn);
    cudaGetSymbolAddress((void**)&outv, g_outv);
    cudaGetSymbolAddress((void**)&outl, g_outl);
    cudaGetSymbolAddress((void**)&part, g_part);
    cudaGetSymbolAddress((void**)&wsum, g_wsum);
    cudaGetSymbolAddress((void**)&wl,   g_wl);
    cudaGetSymbolAddress((void**)&ids,  g_ids);
    cudaGetSymbolAddress((void**)&ws,   g_ws);
    cudaGetSymbolAddress((void**)&we,   g_we);
    cudaGetSymbolAddress((void**)&wT,   g_wT);
    cudaGetSymbolAddress((void**)&scores, g_scores);

    cudaFuncSetAttribute(gemm_bf16_kernel, cudaFuncAttributeMaxDynamicSharedMemorySize, GB_SMEM);
    cudaFuncSetAttribute(gemm_mma3_kernel, cudaFuncAttributeMaxDynamicSharedMemorySize, G3_SMEM);
    cudaFuncSetAttribute(attn4_kernel, cudaFuncAttributeMaxDynamicSharedMemorySize, SMEM_A4);
    cudaFuncSetAttribute(attn_masked_kernel, cudaFuncAttributeMaxDynamicSharedMemorySize, SMEM_AM);

    // ===== transpose all weights (one batched launch) ====
    transpose_all_kernel<<<6144, dim3(32,8)>>>(v_qkv_w, l_qkv_w, v_out_w, l_out_w,
                                               v_w1, l_w1, v_w2, l_w2, wT);

    dim3 gAttn(T_/64, H_, B_);
    dim3 gtD(D_/128, BT_/128, 1);
    dim3 gtF1(FF_/128, BT_/128, 1);
    dim3 gtQK(D_/128, BT_/128, 2);
    dim3 gtQKV(D_/128, BT_/128, 3);

    // ===== layer 1 (vanilla) =====
    gemm_mma3_kernel<<<gtQK, 256, G3_SMEM>>>(x, wT + WT_VQKV, qkv, D_, D_,
                                             (long long)D_*D_, (long long)BT_*D_);
    gemm_bf16_kernel<<<gtD, 128, GB_SMEM>>>(x, wT + WT_VQKV + 2*D_*D_, qkv + (size_t)2*BT_*D_,
                                            D_, D_, 0, 0, 0);
    attn4_kernel<<<gAttn, 256, SMEM_A4>>>(qkv, ctx, part, scores);
    reduce_part_kernel<<<(B_*T_)/256, 256>>>(part, wsum);
    gemm_bf16_kernel<<<gtD, 128, GB_SMEM>>>(ctx, wT + WT_VOUT, tmp, D_, D_, 0, 0, 0);
    add_ln_kernel<<<BT_, 256>>>(x, tmp, h1);
    gemm_bf16_kernel<<<gtF1, 128, GB_SMEM>>>(h1, wT + WT_VW1, ffn, FF_, D_, 0, 0, 1);
    gemm_bf16_kernel<<<gtD, 128, GB_SMEM>>>(ffn, wT + WT_VW2, tmp, D_, FF_, 0, 0, 0);
    add_ln_kernel<<<BT_, 256>>>(h1, tmp, outv);

    // ===== dynamic window mask =====
    scan_kernel<<<B_, 256>>>(wsum, ids, ws, we);

    // ===== layer 2 (masked) =====
    gemm_bf16_kernel<<<gtQKV, 128, GB_SMEM>>>(outv, wT + WT_LQKV, qkv, D_, D_,
                                              (long long)D_*D_, (long long)BT_*D_, 0);
    attn_masked_kernel<<<gAttn, 256, SMEM_AM>>>(qkv, ids, ctx, part);
    reduce_part_kernel<<<(B_*T_)/256, 256>>>(part, wsum);
    gemm_bf16_kernel<<<gtD, 128, GB_SMEM>>>(ctx, wT + WT_LOUT, tmp, D_, D_, 0, 0, 0);
    add_ln_kernel<<<BT_, 256>>>(outv, tmp, h1);
    gemm_bf16_kernel<<<gtF1, 128, GB_SMEM>>>(h1, wT + WT_LW1, ffn, FF_, D_, 0, 0, 1);
    gemm_bf16_kernel<<<gtD, 128, GB_SMEM>>>(ffn, wT + WT_LW2, tmp, D_, FF_, 0, 0, 0);
    add_ln_kernel<<<BT_, 256>>>(h1, tmp, outl);

    // ===== outputs =====
    wl_softmax_kernel<<<B_, 256>>>(wsum, wl);
    word_tokens_kernel<<<dim3(T_, B_), 128>>>(outl, wl, ws, we, out);
    copy_x_kernel<<<(B_*T_*D_/4)/256, 256>>>(x, out);
    winmap_kernel<<<(B_*T_*T_/4)/256, 256>>>(ids, out + (size_t)B_*2*T_*D_);
}

// round 15
// speedup vs baseline: 5.5055x; 1.0284x over previous
#include <cuda_runtime.h>
#include <cuda_bf16.h>
#include <math.h>
#include <stdint.h>

// Problem constants
#define B_  8
#define T_  1024
#define D_  512
#define FF_ 2048
#define H_  8
#define DH_ 64
#define BT_ (B_*T_)          // 8192 rows

// ---------------- scratch (device globals; no allocation allowed) ----------
__device__ float  g_qkv [3*BT_*D_];
__device__ float  g_ctx [BT_*D_];
__device__ float  g_tmp [BT_*D_];
__device__ float  g_h1  [BT_*D_];
__device__ float  g_ffn [BT_*FF_];
__device__ float  g_outv[BT_*D_];
__device__ float  g_outl[BT_*D_];
__device__ float  g_part[B_*H_*16*T_];
__device__ double g_wsum[B_*T_];
__device__ float  g_wl  [B_*T_];
__device__ int    g_ids [B_*T_];
__device__ int    g_ws  [B_*T_];
__device__ int    g_we  [B_*T_];
__device__ float  g_wT  [6291456];      // transposed weights
__device__ float  g_scores[(size_t)B_*H_*T_*T_];  // layer-1 exp(score) cache

// transposed-weight offsets (floats)
#define WT_LQKV 0
#define WT_VOUT 786432
#define WT_LOUT 1048576
#define WT_VW1  1310720
#define WT_LW1  2359296
#define WT_VW2  3407872
#define WT_LW2  4456448
#define WT_VQKV 5505024

// ---------------- tf32 helpers ----------------------------------------------
__device__ __forceinline__ float f2tf32(float x) {
    uint32_t u;
    asm("cvt.rna.tf32.f32 %0, %1;" : "=r"(u) : "f"(x));
    return __uint_as_float(u);
}
__device__ __forceinline__ void split_tf32(float x, uint32_t& hi, uint32_t& lo) {
    float h = f2tf32(x);
    float l = f2tf32(x - h);
    hi = __float_as_uint(h);
    lo = __float_as_uint(l);
}
#define MMA_TF32(d, a, b) \
    asm volatile("mma.sync.aligned.m16n8k8.row.col.f32.tf32.tf32.f32 " \
        "{%0,%1,%2,%3}, {%4,%5,%6,%7}, {%8,%9}, {%0,%1,%2,%3};" \
        : "+f"((d)[0]), "+f"((d)[1]), "+f"((d)[2]), "+f"((d)[3]) \
        : "r"((a)[0]), "r"((a)[1]), "r"((a)[2]), "r"((a)[3]), \
          "r"((b)[0]), "r"((b)[1]))
#define MMA_BF16(d, a, b) \
    asm volatile("mma.sync.aligned.m16n8k16.row.col.f32.bf16.bf16.f32 " \
        "{%0,%1,%2,%3}, {%4,%5,%6,%7}, {%8,%9}, {%0,%1,%2,%3};" \
        : "+f"((d)[0]), "+f"((d)[1]), "+f"((d)[2]), "+f"((d)[3]) \
        : "r"((a)[0]), "r"((a)[1]), "r"((a)[2]), "r"((a)[3]), \
          "r"((b)[0]), "r"((b)[1]))

__device__ __forceinline__ uint32_t pack_bf16x2(float lo, float hi) {
    __nv_bfloat162 h = __float22bfloat162_rn(make_float2(lo, hi));
    return *(uint32_t*)&h;
}
__device__ __forceinline__ float2 unpack_bf16x2(uint32_t v) {
    return __bfloat1622float2(*(__nv_bfloat162*)&v);
}

// ---------------- batched weight transpose ----------------------------------
__global__ void transpose_all_kernel(
    const float* __restrict__ vqkv, const float* __restrict__ lqkv,
    const float* __restrict__ vout, const float* __restrict__ lout,
    const float* __restrict__ vw1,  const float* __restrict__ lw1,
    const float* __restrict__ vw2,  const float* __restrict__ lw2,
    float* __restrict__ wT)
{
    __shared__ float t[32][33];
    int bid = blockIdx.x;
    int task, local;
    if (bid < 2048) { task = bid >> 8; local = bid & 255; }
    else { int r = bid - 2048; task = 8 + (r >> 10); local = r & 1023; }
    const float* src; float* dst; int R, C;
    switch (task) {
        case 0:  src = vqkv;           dst = wT + WT_VQKV;           R = 512;  C = 512;  break;
        case 1:  src = vqkv + 262144;  dst = wT + WT_VQKV + 262144;  R = 512;  C = 512;  break;
        case 2:  src = vqkv + 524288;  dst = wT + WT_VQKV + 524288;  R = 512;  C = 512;  break;
        case 3:  src = lqkv;           dst = wT + WT_LQKV;           R = 512;  C = 512;  break;
        case 4:  src = lqkv + 262144;  dst = wT + WT_LQKV + 262144;  R = 512;  C = 512;  break;
        case 5:  src = lqkv + 524288;  dst = wT + WT_LQKV + 524288;  R = 512;  C = 512;  break;
        case 6:  src = vout;           dst = wT + WT_VOUT;           R = 512;  C = 512;  break;
        case 7:  src = lout;           dst = wT + WT_LOUT;           R = 512;  C = 512;  break;
        case 8:  src = vw1;            dst = wT + WT_VW1;            R = 512;  C = 2048; break;
        case 9:  src = lw1;            dst = wT + WT_LW1;            R = 512;  C = 2048; break;
        case 10: src = vw2;            dst = wT + WT_VW2;            R = 2048; C = 512;  break;
        default: src = lw2;            dst = wT + WT_LW2;            R = 2048; C = 512;  break;
    }
    int nbx = C >> 5;
    int c0 = (local % nbx) * 32, r0 = (local / nbx) * 32;
    int tx = threadIdx.x, ty = threadIdx.y;
    #pragma unroll
    for (int i = 0; i < 32; i += 8)
        t[ty+i][tx] = src[(size_t)(r0+ty+i)*C + c0+tx];
    __syncthreads();
    #pragma unroll
    for (int i = 0; i < 32; i += 8)
        dst[(size_t)(c0+ty+i)*R + r0+tx] = t[tx][ty+i];
}

// ---------------- bf16 tensor GEMM (continuous path) ------------------------
#define MSB 40
#define GB_SMEM (4 * 128 * MSB * 2)
__global__ __launch_bounds__(128)
void gemm_bf16_kernel(const float* __restrict__ A, const float* __restrict__ BTs,
                      float* __restrict__ Cs, int N, int K,
                      long long bt_z, long long c_z, int relu)
{
    extern __shared__ char smraw[];
    __nv_bfloat16* sb = (__nv_bfloat16*)smraw;
    __nv_bfloat16* Asm[2] = { sb,            sb + 128*MSB };
    __nv_bfloat16* Bsm[2] = { sb + 2*128*MSB, sb + 3*128*MSB };

    const float* BT = BTs + (long long)blockIdx.z * bt_z;
    float*       C  = Cs  + (long long)blockIdx.z * c_z;

    int tid = threadIdx.x, lane = tid & 31, wid = tid >> 5;
    int wm = (wid >> 1) * 64, wn = (wid & 1) * 64;
    int bm = blockIdx.y * 128, bn = blockIdx.x * 128;
    int col4 = tid & 7, rbase = tid >> 3;
    int rq = lane >> 2, cq = lane & 3;

    float d[4][8][4];
    #pragma unroll
    for (int i = 0; i < 4; i++)
        #pragma unroll
        for (int j = 0; j < 8; j++)
            #pragma unroll
            for (int u = 0; u < 4; u++) d[i][j][u] = 0.f;

    float4 ar[8], br[8];
    #pragma unroll
    for (int j = 0; j < 8; j++) {
        ar[j] = *(const float4*)&A [(size_t)(bm + rbase + j*16) * K + col4*4];
        br[j] = *(const float4*)&BT[(size_t)(bn + rbase + j*16) * K + col4*4];
    }
    #pragma unroll
    for (int j = 0; j < 8; j++) {
        int r = rbase + j*16;
        uint2 pa = make_uint2(pack_bf16x2(ar[j].x, ar[j].y), pack_bf16x2(ar[j].z, ar[j].w));
        uint2 pb = make_uint2(pack_bf16x2(br[j].x, br[j].y), pack_bf16x2(br[j].z, br[j].w));
        *(uint2*)&Asm[0][r*MSB + col4*4] = pa;
        *(uint2*)&Bsm[0][r*MSB + col4*4] = pb;
    }
    __syncthreads();

    int nc = K / 32;
    for (int c = 0; c < nc; c++) {
        int buf = c & 1;
        if (c + 1 < nc) {
            int k0 = (c + 1) * 32;
            #pragma unroll
            for (int j = 0; j < 8; j++) {
                ar[j] = *(const float4*)&A [(size_t)(bm + rbase + j*16) * K + k0 + col4*4];
                br[j] = *(const float4*)&BT[(size_t)(bn + rbase + j*16) * K + k0 + col4*4];
            }
        }
        const __nv_bfloat16* a_s = Asm[buf];
        const __nv_bfloat16* b_s = Bsm[buf];
        #pragma unroll
        for (int ks = 0; ks < 2; ks++) {
            int k2 = ks*16 + cq*2;
            uint32_t af[4][4];
            #pragma unroll
            for (int fm = 0; fm < 4; fm++) {
                int r0 = wm + fm*16 + rq;
                af[fm][0] = *(const uint32_t*)&a_s[ r0     *MSB + k2];
                af[fm][1] = *(const uint32_t*)&a_s[(r0 + 8)*MSB + k2];
                af[fm][2] = *(const uint32_t*)&a_s[ r0     *MSB + k2 + 8];
                af[fm][3] = *(const uint32_t*)&a_s[(r0 + 8)*MSB + k2 + 8];
            }
            #pragma unroll
            for (int fn = 0; fn < 8; fn++) {
                int n0 = wn + fn*8 + rq;
                uint32_t bf[2] = { *(const uint32_t*)&b_s[n0*MSB + k2],
                                   *(const uint32_t*)&b_s[n0*MSB + k2 + 8] };
                #pragma unroll
                for (int fm = 0; fm < 4; fm++)
                    MMA_BF16(d[fm][fn], af[fm], bf);
            }
        }
        if (c + 1 < nc) {
            int nb = (c + 1) & 1;
            #pragma unroll
            for (int j = 0; j < 8; j++) {
                int r = rbase + j*16;
                uint2 pa = make_uint2(pack_bf16x2(ar[j].x, ar[j].y), pack_bf16x2(ar[j].z, ar[j].w));
                uint2 pb = make_uint2(pack_bf16x2(br[j].x, br[j].y), pack_bf16x2(br[j].z, br[j].w));
                *(uint2*)&Asm[nb][r*MSB + col4*4] = pa;
                *(uint2*)&Bsm[nb][r*MSB + col4*4] = pb;
            }
        }
        __syncthreads();
    }

    #pragma unroll
    for (int fm = 0; fm < 4; fm++) {
        #pragma unroll
        for (int fn = 0; fn < 8; fn++) {
            int r  = bm + wm + fm*16 + rq;
            int cc = bn + wn + fn*8 + 2*cq;
            float2 v0 = make_float2(d[fm][fn][0], d[fm][fn][1]);
            float2 v1 = make_float2(d[fm][fn][2], d[fm][fn][3]);
            if (relu) {
                v0.x = fmaxf(v0.x, 0.f); v0.y = fmaxf(v0.y, 0.f);
                v1.x = fmaxf(v1.x, 0.f); v1.y = fmaxf(v1.y, 0.f);
            }
            *(float2*)&C[(size_t)r*N + cc]       = v0;
            *(float2*)&C[(size_t)(r + 8)*N + cc] = v1;
        }
    }
}

// ---------------- 3xTF32 GEMM (decision path), fp32 smem + reg split --------
#define MS 36
#define G3_SMEM (4 * 128 * MS * 4)
__global__ __launch_bounds__(256)
void gemm_mma3_kernel(const float* __restrict__ A, const float* __restrict__ BTs,
                      float* __restrict__ Cs, int N, int K,
                      long long bt_z, long long c_z)
{
    extern __shared__ float smf[];
    float* As[2] = { smf,            smf + 128*MS };
    float* Bs[2] = { smf + 2*128*MS, smf + 3*128*MS };

    const float* BT = BTs + (long long)blockIdx.z * bt_z;
    float*       C  = Cs  + (long long)blockIdx.z * c_z;

    int tid = threadIdx.x, lane = tid & 31, wid = tid >> 5;
    int wm = (wid >> 1) * 32, wn = (wid & 1) * 64;
    int bm = blockIdx.y * 128, bn = blockIdx.x * 128;
    int rbase = tid >> 1, cb = (tid & 1) * 16;

    float d[2][8][4];
    #pragma unroll
    for (int i = 0; i < 2; i++)
        #pragma unroll
        for (int j = 0; j < 8; j++)
            #pragma unroll
            for (int u = 0; u < 4; u++) d[i][j][u] = 0.f;

    float4 ar[4], br[4];
    #pragma unroll
    for (int j = 0; j < 4; j++) {
        ar[j] = *(const float4*)&A [(size_t)(bm + rbase) * K + cb + j*4];
        br[j] = *(const float4*)&BT[(size_t)(bn + rbase) * K + cb + j*4];
    }
    #pragma unroll
    for (int j = 0; j < 4; j++) {
        *(float4*)&As[0][rbase*MS + cb + j*4] = ar[j];
        *(float4*)&Bs[0][rbase*MS + cb + j*4] = br[j];
    }
    __syncthreads();

    int nc = K / 32;
    for (int c = 0; c < nc; c++) {
        int buf = c & 1;
        if (c + 1 < nc) {
            int k0 = (c + 1) * 32;
            #pragma unroll
            for (int j = 0; j < 4; j++) {
                ar[j] = *(const float4*)&A [(size_t)(bm + rbase) * K + k0 + cb + j*4];
                br[j] = *(const float4*)&BT[(size_t)(bn + rbase) * K + k0 + cb + j*4];
            }
        }
        const float* a_s = As[buf];
        const float* b_s = Bs[buf];
        #pragma unroll
        for (int ks = 0; ks < 4; ks++) {
            int kk = ks*8 + (lane & 3);
            int rq = lane >> 2;
            uint32_t afh[2][4], afl[2][4];
            #pragma unroll
            for (int fm = 0; fm < 2; fm++) {
                int r0 = wm + fm*16 + rq;
                split_tf32(a_s[ r0     *MS + kk    ], afh[fm][0], afl[fm][0]);
                split_tf32(a_s[(r0 + 8)*MS + kk    ], afh[fm][1], afl[fm][1]);
                split_tf32(a_s[ r0     *MS + kk + 4], afh[fm][2], afl[fm][2]);
                split_tf32(a_s[(r0 + 8)*MS + kk + 4], afh[fm][3], afl[fm][3]);
            }
            #pragma unroll
            for (int fn = 0; fn < 8; fn++) {
                int n0 = wn + fn*8 + rq;
                uint32_t bfh[2], bfl[2];
                split_tf32(b_s[n0*MS + kk    ], bfh[0], bfl[0]);
                split_tf32(b_s[n0*MS + kk + 4], bfh[1], bfl[1]);
                #pragma unroll
                for (int fm = 0; fm < 2; fm++) {
                    MMA_TF32(d[fm][fn], afh[fm], bfh);
                    MMA_TF32(d[fm][fn], afl[fm], bfh);
                    MMA_TF32(d[fm][fn], afh[fm], bfl);
                }
            }
        }
        if (c + 1 < nc) {
            int nb = (c + 1) & 1;
            #pragma unroll
            for (int j = 0; j < 4; j++) {
                *(float4*)&As[nb][rbase*MS + cb + j*4] = ar[j];
                *(float4*)&Bs[nb][rbase*MS + cb + j*4] = br[j];
            }
        }
        __syncthreads();
    }

    #pragma unroll
    for (int fm = 0; fm < 2; fm++) {
        #pragma unroll
        for (int fn = 0; fn < 8; fn++) {
            int r  = bm + wm + fm*16 + (lane >> 2);
            int cc = bn + wn + fn*8 + 2*(lane & 3);
            *(float2*)&C[(size_t)r*N + cc]       = make_float2(d[fm][fn][0], d[fm][fn][1]);
            *(float2*)&C[(size_t)(r + 8)*N + cc] = make_float2(d[fm][fn][2], d[fm][fn][3]);
        }
    }
}

// ---------------- layer-1 attention v6 --------------------------------------
// fp32 Q/K + reg-split 3xTF32 QK; e computed once (fp32 -> gmem cache);
// bf16 P/V with m16n8k16 PV; register row sums.
#define AS 68
#define PSB 72   // bf16 row stride for P and V^T tiles
#define SMEM_A4 (2*64*AS*4 + 2*64*PSB*2 + 1280)
__global__ __launch_bounds__(256)
void attn4_kernel(const float* __restrict__ qkv, float* __restrict__ ctx,
                  float* __restrict__ part, float* __restrict__ ecache)
{
    extern __shared__ float smf[];
    float* Qf = smf;                              // [64][AS] fp32
    float* Kf = Qf + 64*AS;                       // [64][AS] fp32
    __nv_bfloat16* Psb = (__nv_bfloat16*)(Kf + 64*AS);  // [64][PSB] e bf16
    __nv_bfloat16* Vtb = Psb + 64*PSB;            // [64][PSB] V^T bf16: Vtb[c][j]
    float* rs = (float*)(Vtb + 64*PSB);           // [64][2] row-sum halves
    float* zs = rs + 128;                         // [64]

    int qt = blockIdx.x, h = blockIdx.y, b = blockIdx.z;
    int tid = threadIdx.x, lane = tid & 31, w = tid >> 5;
    int q0 = qt * 64;
    const float scale = 0.125f;

    const float* Qp = qkv;
    const float* Kp = qkv + (size_t)BT_*D_;
    const float* Vp = qkv + (size_t)2*BT_*D_;
    float* ec = ecache + ((size_t)(b*H_ + h)*T_ + q0)*T_;

    int lrow = tid >> 2, le0 = (tid & 3) * 16;
    int m0 = (w >> 1) * 16, n0 = (w & 1) * 32;
    int rq = lane >> 2, cq = lane & 3;

    // load Q fp32
    {
        const float* src = Qp + (size_t)(b*T_ + q0 + lrow) * D_ + h*DH_ + le0;
        #pragma unroll
        for (int u = 0; u < 4; u++)
            *(float4*)&Qf[lrow*AS + le0 + u*4] = *(const float4*)(src + u*4);
    }

    float lsum0 = 0.f, lsum1 = 0.f;
    float pacc[4][4];
    #pragma unroll
    for (int fn = 0; fn < 4; fn++)
        #pragma unroll
        for (int u = 0; u < 4; u++) pacc[fn][u] = 0.f;

    for (int kt = 0; kt < 16; kt++) {
        int k0 = kt * 64;
        __syncthreads();              // protect Kf/Vtb/Psb reuse
        {
            const float* src = Kp + (size_t)(b*T_ + k0 + lrow) * D_ + h*DH_ + le0;
            #pragma unroll
            for (int u = 0; u < 4; u++)
                *(float4*)&Kf[lrow*AS + le0 + u*4] = *(const float4*)(src + u*4);
            const float* vsrc = Vp + (size_t)(b*T_ + k0 + lrow) * D_ + h*DH_ + le0;
            #pragma unroll
            for (int u = 0; u < 4; u++) {
                float4 v = *(const float4*)(vsrc + u*4);
                Vtb[(le0 + u*4 + 0)*PSB + lrow] = __float2bfloat16(v.x);
                Vtb[(le0 + u*4 + 1)*PSB + lrow] = __float2bfloat16(v.y);
                Vtb[(le0 + u*4 + 2)*PSB + lrow] = __float2bfloat16(v.z);
                Vtb[(le0 + u*4 + 3)*PSB + lrow] = __float2bfloat16(v.w);
            }
        }
        __syncthreads();
        // QK 3xTF32 with register hi/lo split
        float dq[4][4];
        #pragma unroll
        for (int fn = 0; fn < 4; fn++)
            #pragma unroll
            for (int u = 0; u < 4; u++) dq[fn][u] = 0.f;
        #pragma unroll
        for (int ks = 0; ks < 8; ks++) {
            int kk = ks*8 + cq;
            int arr = m0 + rq;
            uint32_t ah[4], al[4];
            split_tf32(Qf[ arr   *AS + kk    ], ah[0], al[0]);
            split_tf32(Qf[(arr+8)*AS + kk    ], ah[1], al[1]);
            split_tf32(Qf[ arr   *AS + kk + 4], ah[2], al[2]);
            split_tf32(Qf[(arr+8)*AS + kk + 4], ah[3], al[3]);
            #pragma unroll
            for (int fn = 0; fn < 4; fn++) {
                int bnr = n0 + fn*8 + rq;
                uint32_t bh[2], bl[2];
                split_tf32(Kf[bnr*AS + kk    ], bh[0], bl[0]);
                split_tf32(Kf[bnr*AS + kk + 4], bh[1], bl[1]);
                MMA_TF32(dq[fn], ah, bh);
                MMA_TF32(dq[fn], al, bh);
                MMA_TF32(dq[fn], ah, bl);
            }
        }
        // e = exp(score) once: fp32 -> gmem cache (decision path), bf16 -> smem
        float p0 = 0.f, p1 = 0.f;
        #pragma unroll
        for (int fn = 0; fn < 4; fn++) {
            int i0 = m0 + rq, j0 = n0 + fn*8 + 2*cq;
            float e0 = __expf(dq[fn][0]*scale);
            float e1 = __expf(dq[fn][1]*scale);
            float e2 = __expf(dq[fn][2]*scale);
            float e3 = __expf(dq[fn][3]*scale);
            *(float2*)&ec[(size_t)i0*T_ + k0 + j0]     = make_float2(e0, e1);
            *(float2*)&ec[(size_t)(i0+8)*T_ + k0 + j0] = make_float2(e2, e3);
            *(uint32_t*)&Psb[ i0   *PSB + j0] = pack_bf16x2(e0, e1);
            *(uint32_t*)&Psb[(i0+8)*PSB + j0] = pack_bf16x2(e2, e3);
            p0 += e0 + e1;
            p1 += e2 + e3;
        }
        // register row-sum partials (reduce over cq)
        p0 += __shfl_xor_sync(0xffffffffu, p0, 1);
        p0 += __shfl_xor_sync(0xffffffffu, p0, 2);
        p1 += __shfl_xor_sync(0xffffffffu, p1, 1);
        p1 += __shfl_xor_sync(0xffffffffu, p1, 2);
        lsum0 += p0;
        lsum1 += p1;
        __syncthreads();
        // unnormalized PV mma (bf16 m16n8k16)
        #pragma unroll
        for (int ks = 0; ks < 4; ks++) {
            int k2 = ks*16 + cq*2;
            int arr = m0 + rq;
            uint32_t ap[4] = { *(const uint32_t*)&Psb[ arr   *PSB + k2],
                               *(const uint32_t*)&Psb[(arr+8)*PSB + k2],
                               *(const uint32_t*)&Psb[ arr   *PSB + k2 + 8],
                               *(const uint32_t*)&Psb[(arr+8)*PSB + k2 + 8] };
            #pragma unroll
            for (int fn = 0; fn < 4; fn++) {
                int bnr = n0 + fn*8 + rq;
                uint32_t bv[2] = { *(const uint32_t*)&Vtb[bnr*PSB + k2],
                                   *(const uint32_t*)&Vtb[bnr*PSB + k2 + 8] };
                MMA_BF16(pacc[fn], ap, bv);
            }
        }
    }
    __syncthreads();
    if (cq == 0) {
        rs[(m0 + rq)*2     + (w & 1)] = lsum0;
        rs[(m0 + rq + 8)*2 + (w & 1)] = lsum1;
    }
    __syncthreads();
    if (tid < 64) zs[tid] = 1.f / (rs[tid*2] + rs[tid*2 + 1]);
    __syncthreads();

    // write ctx (scale rows by z)
    {
        float za = zs[m0 + rq], zb = zs[m0 + rq + 8];
        #pragma unroll
        for (int fn = 0; fn < 4; fn++) {
            int r  = b*T_ + q0 + m0 + rq;
            int cc = h*DH_ + n0 + fn*8 + 2*cq;
            *(float2*)&ctx[(size_t)r*D_ + cc]     = make_float2(pacc[fn][0]*za, pacc[fn][1]*za);
            *(float2*)&ctx[(size_t)(r+8)*D_ + cc] = make_float2(pacc[fn][2]*zb, pacc[fn][3]*zb);
        }
    }

    // ---- colsum sweep over cached fp32 e (fp64, deterministic) ----
    double cs[4] = {0.0, 0.0, 0.0, 0.0};
    for (int i = 0; i < 64; i++) {
        double zi = (double)zs[i];
        const float* row = ec + (size_t)i*T_;
        #pragma unroll
        for (int g = 0; g < 4; g++)
            cs[g] += (double)row[tid + g*256] * zi;
    }
    float* pr = part + ((size_t)((b*H_ + h)*16 + qt))*T_;
    #pragma unroll
    for (int g = 0; g < 4; g++) pr[tid + g*256] = (float)cs[g];
}

// ---------------- layer-2 masked attention (two-pass, tile skip, bf16 PV) ---
// RACE FIX: skip decision reads ids from gmem into registers (uniform, no smem
// hazard); smem kid fill happens only after the loop-top __syncthreads().
#define SMEM_AM (2*64*AS*4 + 2*64*PSB*2 + 1280)
__global__ __launch_bounds__(256)
void attn_masked_kernel(const float* __restrict__ qkv, const int* __restrict__ ids,
                        float* __restrict__ ctx, float* __restrict__ part)
{
    extern __shared__ float smf[];
    float* Qh = smf;
    float* Kh = Qh + 64*AS;
    __nv_bfloat16* Psb = (__nv_bfloat16*)(Kh + 64*AS);  // [64][PSB] scores/probs bf16
    __nv_bfloat16* Vtb = Psb + 64*PSB;                  // [64][PSB] V^T bf16
    float* ms = (float*)(Vtb + 64*PSB);
    float* ls = ms + 64;
    int*   qid = (int*)(ls + 64);
    int*   kid = qid + 64;

    int qt = blockIdx.x, h = blockIdx.y, b = blockIdx.z;
    int tid = threadIdx.x, lane = tid & 31, w = tid >> 5;
    int q0 = qt * 64;
    const float scale = 0.125f;

    const float* Qp = qkv;
    const float* Kp = qkv + (size_t)BT_*D_;
    const float* Vp = qkv + (size_t)2*BT_*D_;
    const int* idb = ids + b*T_;

    int lrow = tid >> 2, le0 = (tid & 3) * 16;
    int m0 = (w >> 1) * 16, n0 = (w & 1) * 32;
    int rq = lane >> 2, cq = lane & 3;
    int sr = tid >> 2, seg = tid & 3;

    {
        const float* src = Qp + (size_t)(b*T_ + q0 + lrow) * D_ + h*DH_ + le0;
        #pragma unroll
        for (int u = 0; u < 4; u++)
            *(float4*)&Qh[lrow*AS + le0 + u*4] = *(const float4*)(src + u*4);
        if (tid < 64) qid[tid] = idb[q0 + tid];
    }
    __syncthreads();
    int qid0 = qid[0], qidL = qid[63];

    float m = -1e30f, l = 0.f;

    for (int kt = 0; kt < 16; kt++) {
        int k0 = kt * 64;
        // uniform skip decision from gmem (ids immutable during kernel)
        int kmin = idb[k0], kmax = idb[k0 + 63];
        if (kmax < qid0 || qidL < kmin) continue;
        __syncthreads();              // protect Kh/Psb/kid reuse
        {
            if (tid < 64) kid[tid] = idb[k0 + tid];
            const float* src = Kp + (size_t)(b*T_ + k0 + lrow) * D_ + h*DH_ + le0;
            #pragma unroll
            for (int u = 0; u < 4; u++)
                *(float4*)&Kh[lrow*AS + le0 + u*4] = *(const float4*)(src + u*4);
        }
        __syncthreads();
        float dq[4][4];
        #pragma unroll
        for (int fn = 0; fn < 4; fn++)
            #pragma unroll
            for (int u = 0; u < 4; u++) dq[fn][u] = 0.f;
        #pragma unroll
        for (int ks = 0; ks < 8; ks++) {
            int kk = ks*8 + cq;
            int arr = m0 + rq;
            uint32_t ah[4] = { __float_as_uint(Qh[ arr   *AS + kk]),
                               __float_as_uint(Qh[(arr+8)*AS + kk]),
                               __float_as_uint(Qh[ arr   *AS + kk + 4]),
                               __float_as_uint(Qh[(arr+8)*AS + kk + 4]) };
            #pragma unroll
            for (int fn = 0; fn < 4; fn++) {
                int bnr = n0 + fn*8 + rq;
                uint32_t bh[2] = { __float_as_uint(Kh[bnr*AS + kk]),
                                   __float_as_uint(Kh[bnr*AS + kk + 4]) };
                MMA_TF32(dq[fn], ah, bh);
            }
        }
        #pragma unroll
        for (int fn = 0; fn < 4; fn++) {
            int i0 = m0 + rq, j0 = n0 + fn*8 + 2*cq;
            float s0 = dq[fn][0]*scale, s1 = dq[fn][1]*scale;
            float s2 = dq[fn][2]*scale, s3 = dq[fn][3]*scale;
            int qa = qid[i0], qb = qid[i0+8], ka = kid[j0], kb = kid[j0+1];
            if (qa != ka) s0 = -1e30f;
            if (qa != kb) s1 = -1e30f;
            if (qb != ka) s2 = -1e30f;
            if (qb != kb) s3 = -1e30f;
            *(uint32_t*)&Psb[ i0   *PSB + j0] = pack_bf16x2(s0, s1);
            *(uint32_t*)&Psb[(i0+8)*PSB + j0] = pack_bf16x2(s2, s3);
        }
        __syncthreads();
        {
            float sv[16]; float tm = -1e30f;
            #pragma unroll
            for (int u = 0; u < 4; u++) {
                uint2 q = *(const uint2*)&Psb[sr*PSB + seg*16 + u*4];
                float2 a = unpack_bf16x2(q.x);
                float2 bq = unpack_bf16x2(q.y);
                sv[u*4+0] = a.x; sv[u*4+1] = a.y; sv[u*4+2] = bq.x; sv[u*4+3] = bq.y;
                tm = fmaxf(tm, fmaxf(fmaxf(a.x, a.y), fmaxf(bq.x, bq.y)));
            }
            tm = fmaxf(tm, __shfl_xor_sync(0xffffffffu, tm, 1));
            tm = fmaxf(tm, __shfl_xor_sync(0xffffffffu, tm, 2));
            float nm = fmaxf(m, tm);
            float es = 0.f;
            #pragma unroll
            for (int it = 0; it < 16; it++) es += __expf(sv[it] - nm);
            es += __shfl_xor_sync(0xffffffffu, es, 1);
            es += __shfl_xor_sync(0xffffffffu, es, 2);
            l = l * __expf(m - nm) + es;
            m = nm;
        }
    }
    __syncthreads();
    if (seg == 0) { ms[sr] = m; ls[sr] = 1.f / l; }
    __syncthreads();

    float pacc[4][4];
    #pragma unroll
    for (int fn = 0; fn < 4; fn++)
        #pragma unroll
        for (int u = 0; u < 4; u++) pacc[fn][u] = 0.f;

    for (int kt = 0; kt < 16; kt++) {
        int k0 = kt * 64;
        int kmin = idb[k0], kmax = idb[k0 + 63];
        if (kmax < qid0 || qidL < kmin) {
            if (tid < 64)
                part[((size_t)((b*H_ + h)*16 + qt))*T_ + k0 + tid] = 0.f;
            continue;
        }
        __syncthreads();              // protect Kh/Vtb/Psb/kid reuse
        {
            if (tid < 64) kid[tid] = idb[k0 + tid];
            const float* ksrc = Kp + (size_t)(b*T_ + k0 + lrow) * D_ + h*DH_ + le0;
            #pragma unroll
            for (int u = 0; u < 4; u++)
                *(float4*)&Kh[lrow*AS + le0 + u*4] = *(const float4*)(ksrc + u*4);
            const float* vsrc = Vp + (size_t)(b*T_ + k0 + lrow) * D_ + h*DH_ + le0;
            #pragma unroll
            for (int u = 0; u < 4; u++) {
                float4 v = *(const float4*)(vsrc + u*4);
                Vtb[(le0 + u*4 + 0)*PSB + lrow] = __float2bfloat16(v.x);
                Vtb[(le0 + u*4 + 1)*PSB + lrow] = __float2bfloat16(v.y);
                Vtb[(le0 + u*4 + 2)*PSB + lrow] = __float2bfloat16(v.z);
                Vtb[(le0 + u*4 + 3)*PSB + lrow] = __float2bfloat16(v.w);
            }
        }
        __syncthreads();
        float dq[4][4];
        #pragma unroll
        for (int fn = 0; fn < 4; fn++)
            #pragma unroll
            for (int u = 0; u < 4; u++) dq[fn][u] = 0.f;
        #pragma unroll
        for (int ks = 0; ks < 8; ks++) {
            int kk = ks*8 + cq;
            int arr = m0 + rq;
            uint32_t ah[4] = { __float_as_uint(Qh[ arr   *AS + kk]),
                               __float_as_uint(Qh[(arr+8)*AS + kk]),
                               __float_as_uint(Qh[ arr   *AS + kk + 4]),
                               __float_as_uint(Qh[(arr+8)*AS + kk + 4]) };
            #pragma unroll
            for (int fn = 0; fn < 4; fn++) {
                int bnr = n0 + fn*8 + rq;
                uint32_t bh[2] = { __float_as_uint(Kh[bnr*AS + kk]),
                                   __float_as_uint(Kh[bnr*AS + kk + 4]) };
                MMA_TF32(dq[fn], ah, bh);
            }
        }
        #pragma unroll
        for (int fn = 0; fn < 4; fn++) {
            int i0 = m0 + rq, j0 = n0 + fn*8 + 2*cq;
            float ma = ms[i0], la = ls[i0];
            float mb = ms[i0+8], lb = ls[i0+8];
            float p0 = __expf(dq[fn][0]*scale - ma) * la;
            float p1 = __expf(dq[fn][1]*scale - ma) * la;
            float p2 = __expf(dq[fn][2]*scale - mb) * lb;
            float p3 = __expf(dq[fn][3]*scale - mb) * lb;
            int qa = qid[i0], qb = qid[i0+8], ka = kid[j0], kb = kid[j0+1];
            if (qa != ka) p0 = 0.f;
            if (qa != kb) p1 = 0.f;
            if (qb != ka) p2 = 0.f;
            if (qb != kb) p3 = 0.f;
            *(uint32_t*)&Psb[ i0   *PSB + j0] = pack_bf16x2(p0, p1);
            *(uint32_t*)&Psb[(i0+8)*PSB + j0] = pack_bf16x2(p2, p3);
        }
        __syncthreads();
        if (tid < 64) {
            double cs = 0.0;
            #pragma unroll
            for (int i = 0; i < 64; i++)
                cs += (double)__bfloat162float(Psb[i*PSB + tid]);
            part[((size_t)((b*H_ + h)*16 + qt))*T_ + k0 + tid] = (float)cs;
        }
        #pragma unroll
        for (int ks = 0; ks < 4; ks++) {
            int k2 = ks*16 + cq*2;
            int arr = m0 + rq;
            uint32_t ap[4] = { *(const uint32_t*)&Psb[ arr   *PSB + k2],
                               *(const uint32_t*)&Psb[(arr+8)*PSB + k2],
                               *(const uint32_t*)&Psb[ arr   *PSB + k2 + 8],
                               *(const uint32_t*)&Psb[(arr+8)*PSB + k2 + 8] };
            #pragma unroll
            for (int fn = 0; fn < 4; fn++) {
                int bnr = n0 + fn*8 + rq;
                uint32_t bv[2] = { *(const uint32_t*)&Vtb[bnr*PSB + k2],
                                   *(const uint32_t*)&Vtb[bnr*PSB + k2 + 8] };
                MMA_BF16(pacc[fn], ap, bv);
            }
        }
    }
    #pragma unroll
    for (int fn = 0; fn < 4; fn++) {
        int r  = b*T_ + q0 + m0 + rq;
        int cc = h*DH_ + n0 + fn*8 + 2*cq;
        *(float2*)&ctx[(size_t)r*D_ + cc]       = make_float2(pacc[fn][0], pacc[fn][1]);
        *(float2*)&ctx[(size_t)(r+8)*D_ + cc]   = make_float2(pacc[fn][2], pacc[fn][3]);
    }
}

// ---------------- deterministic fp64 reduction of prob column sums ---------
__global__ void reduce_part_kernel(const float* __restrict__ part, double* __restrict__ wsum)
{
    int idx = blockIdx.x * 256 + threadIdx.x;
    int b = idx >> 10, j = idx & 1023;
    double s = 0.0;
    for (int g = 0; g < H_*16; g++)
        s += (double)part[((size_t)(b*H_*16 + g)) * T_ + j];
    wsum[idx] = s;
}

// ---------------- y = LayerNorm(x + r), row = 512 ---------------------------
__global__ void add_ln_kernel(const float* __restrict__ x, const float* __restrict__ r,
                              float* __restrict__ y)
{
    __shared__ float sm[256];
    int row = blockIdx.x, tid = threadIdx.x;
    size_t base = (size_t)row * D_;
    float v0 = x[base + tid]        + r[base + tid];
    float v1 = x[base + 256 + tid]  + r[base + 256 + tid];
    sm[tid] = v0 + v1; __syncthreads();
    for (int s = 128; s > 0; s >>= 1) { if (tid < s) sm[tid] += sm[tid + s]; __syncthreads(); }
    float mean = sm[0] * (1.f / D_); __syncthreads();
    float d0 = v0 - mean, d1 = v1 - mean;
    sm[tid] = d0*d0 + d1*d1; __syncthreads();
    for (int s = 128; s > 0; s >>= 1) { if (tid < s) sm[tid] += sm[tid + s]; __syncthreads(); }
    float var = sm[0] * (1.f / D_);
    float inv = 1.f / sqrtf(var + 1e-5f);
    y[base + tid]       = d0 * inv;
    y[base + 256 + tid] = d1 * inv;
}

// ---------------- window-id scan (exact replica of reference scan, fp64) ----
__global__ void scan_kernel(const double* __restrict__ wsum, int* __restrict__ ids,
                            int* __restrict__ ws, int* __restrict__ we)
{
    __shared__ double smn[256], smx[256];
    int b = blockIdx.x, tid = threadIdx.x;
    double mn = 1e300, mx = -1e300;
    for (int t = tid; t < T_; t += 256) {
        double v = wsum[b*T_ + t] * (1.0 / H_);
        mn = fmin(mn, v); mx = fmax(mx, v);
    }
    smn[tid] = mn; smx[tid] = mx; __syncthreads();
    for (int s = 128; s > 0; s >>= 1) {
        if (tid < s) { smn[tid] = fmin(smn[tid], smn[tid+s]); smx[tid] = fmax(smx[tid], smx[tid+s]); }
        __syncthreads();
    }
    for (int t = tid; t < T_; t += 256) { ws[b*T_ + t] = 0; we[b*T_ + t] = 0; }
    __syncthreads();
    if (tid == 0) {
        double MN = smn[0], MX = smx[0];
        double denom = MX - MN + 1e-8;
        double thr = MN + 0.5 * denom;
        int cur = (wsum[b*T_ + 0] * (1.0 / H_)) >= thr ? 1 : 0;
        int start = 0, wid = 0;
        ids[b*T_ + 0] = 0;
        for (int t = 1; t < T_; t++) {
            int wt = (wsum[b*T_ + t] * (1.0 / H_)) >= thr ? 1 : 0;
            if (wt == cur) {
            } else if (start + 1 == t) {
                cur = wt;
            } else {
                cur = wt; start = t; wid++;
            }
            ids[b*T_ + t] = wid;
        }
        int prev = -1;
        for (int t = 0; t < T_; t++) {
            int w = ids[b*T_ + t];
            if (w != prev) { ws[b*T_ + w] = t; prev = w; }
            we[b*T_ + w] = t + 1;
        }
    }
}

// ---------------- wl = softmax_j(wsum/H) ------------------------------------
__global__ void wl_softmax_kernel(const double* __restrict__ wsum, float* __restrict__ wl)
{
    __shared__ float sm[256];
    int b = blockIdx.x, tid = threadIdx.x;
    float vals[4];
    float mx = -1e30f;
    #pragma unroll
    for (int i = 0; i < 4; i++) {
        vals[i] = (float)(wsum[b*T_ + tid + i*256] * (1.0 / H_));
        mx = fmaxf(mx, vals[i]);
    }
    sm[tid] = mx; __syncthreads();
    for (int s = 128; s > 0; s >>= 1) { if (tid < s) sm[tid] = fmaxf(sm[tid], sm[tid+s]); __syncthreads(); }
    float M = sm[0]; __syncthreads();
    float e[4], acc = 0.f;
    #pragma unroll
    for (int i = 0; i < 4; i++) { e[i] = expf(vals[i] - M); acc += e[i]; }
    sm[tid] = acc; __syncthreads();
    for (int s = 128; s > 0; s >>= 1) { if (tid < s) sm[tid] += sm[tid+s]; __syncthreads(); }
    float inv = 1.f / sm[0];
    #pragma unroll
    for (int i = 0; i < 4; i++) wl[b*T_ + tid + i*256] = e[i] * inv;
}

// ---------------- window-weighted pooling (deterministic gather) ------------
__global__ void word_tokens_kernel(const float* __restrict__ outl, const float* __restrict__ wl,
                                   const int* __restrict__ ws, const int* __restrict__ we,
                                   float* __restrict__ out)
{
    int w = blockIdx.x, b = blockIdx.y, tid = threadIdx.x;
    int s = ws[b*T_ + w], e = we[b*T_ + w];
    float acc[4] = {0.f, 0.f, 0.f, 0.f};
    for (int t = s; t < e; t++) {
        float g = wl[b*T_ + t];
        const float* row = outl + (size_t)(b*T_ + t) * D_;
        #pragma unroll
        for (int u = 0; u < 4; u++) acc[u] += g * row[tid + u*128];
    }
    float* dst = out + ((size_t)(b*2*T_ + w)) * D_;
    #pragma unroll
    for (int u = 0; u < 4; u++) dst[tid + u*128] = acc[u];
}

// ---------------- copy x into second half of concat output ------------------
__global__ void copy_x_kernel(const float* __restrict__ x, float* __restrict__ out)
{
    int idx = blockIdx.x * 256 + threadIdx.x;
    int b = (idx * 4) / (T_*D_);
    float4 v = *(const float4*)&x[(size_t)idx * 4];
    *(float4*)&out[(size_t)idx * 4 + (size_t)(b + 1) * T_ * D_] = v;
}

// ---------------- window_mapping output -------------------------------------
__global__ void winmap_kernel(const int* __restrict__ ids, float* __restrict__ out2)
{
    int idx = blockIdx.x * 256 + threadIdx.x;
    int e0 = idx * 4;
    int b = e0 >> 20;
    int k = (e0 >> 10) & 1023;
    int j = e0 & 1023;
    const int* idr = ids + b*T_;
    float4 v;
    v.x = (idr[j+0] == k) ? 1.f : 0.f;
    v.y = (idr[j+1] == k) ? 1.f : 0.f;
    v.z = (idr[j+2] == k) ? 1.f : 0.f;
    v.w = (idr[j+3] == k) ? 1.f : 0.f;
    *(float4*)&out2[(size_t)e0] = v;
}

// ---------------- host launcher ---------------------------------------------
extern "C" void kernel_launch(void* const* d_in, const int* in_sizes, int n_in,
                              void* d_out, int out_size)
{
    const float* x       = (const float*)d_in[0];
    const float* v_qkv_w = (const float*)d_in[1];
    const float* v_out_w = (const float*)d_in[2];
    const float* v_w1    = (const float*)d_in[3];
    const float* v_w2    = (const float*)d_in[4];
    const float* l_qkv_w = (const float*)d_in[5];
    const float* l_out_w = (const float*)d_in[6];
    const float* l_w1    = (const float*)d_in[7];
    const float* l_w2    = (const float*)d_in[8];
    float* out = (float*)d_out;

    float *qkv, *ctx, *tmp, *h1, *ffn, *outv, *outl, *part, *wl, *wT, *scores;
    double *wsum;
    int *ids, *ws, *we;
    cudaGetSymbolAddress((void**)&qkv,  g_qkv);
    cudaGetSymbolAddress((void**)&ctx,  g_ctx);
    cudaGetSymbolAddress((void**)&tmp,  g_tmp);
    cudaGetSymbolAddress((void**)&h1,   g_h1);
    cudaGetSymbolAddress((void**)&ffn,  g_ffn);
    cudaGetSymbolAddress((void**)&outv, g_outv);
    cudaGetSymbolAddress((void**)&outl, g_outl);
    cudaGetSymbolAddress((void**)&part, g_part);
    cudaGetSymbolAddress((void**)&wsum, g_wsum);
    cudaGetSymbolAddress((void**)&wl,   g_wl);
    cudaGetSymbolAddress((void**)&ids,  g_ids);
    cudaGetSymbolAddress((void**)&ws,   g_ws);
    cudaGetSymbolAddress((void**)&we,   g_we);
    cudaGetSymbolAddress((void**)&wT,   g_wT);
    cudaGetSymbolAddress((void**)&scores, g_scores);

    cudaFuncSetAttribute(gemm_bf16_kernel, cudaFuncAttributeMaxDynamicSharedMemorySize, GB_SMEM);
    cudaFuncSetAttribute(gemm_mma3_kernel, cudaFuncAttributeMaxDynamicSharedMemorySize, G3_SMEM);
    cudaFuncSetAttribute(attn4_kernel, cudaFuncAttributeMaxDynamicSharedMemorySize, SMEM_A4);
    cudaFuncSetAttribute(attn_masked_kernel, cudaFuncAttributeMaxDynamicSharedMemorySize, SMEM_AM);

    // ===== transpose all weights (one batched launch) ====
    transpose_all_kernel<<<6144, dim3(32,8)>>>(v_qkv_w, l_qkv_w, v_out_w, l_out_w,
                                               v_w1, l_w1, v_w2, l_w2, wT);

    dim3 gAttn(T_/64, H_, B_);
    dim3 gtD(D_/128, BT_/128, 1);
    dim3 gtF1(FF_/128, BT_/128, 1);
    dim3 gtQK(D_/128, BT_/128, 2);
    dim3 gtQKV(D_/128, BT_/128, 3);

    // ===== layer 1 (vanilla) =====
    gemm_mma3_kernel<<<gtQK, 256, G3_SMEM>>>(x, wT + WT_VQKV, qkv, D_, D_,
                                             (long long)D_*D_, (long long)BT_*D_);
    gemm_bf16_kernel<<<gtD, 128, GB_SMEM>>>(x, wT + WT_VQKV + 2*D_*D_, qkv + (size_t)2*BT_*D_,
                                            D_, D_, 0, 0, 0);
    attn4_kernel<<<gAttn, 256, SMEM_A4>>>(qkv, ctx, part, scores);
    reduce_part_kernel<<<(B_*T_)/256, 256>>>(part, wsum);
    gemm_bf16_kernel<<<gtD, 128, GB_SMEM>>>(ctx, wT + WT_VOUT, tmp, D_, D_, 0, 0, 0);
    add_ln_kernel<<<BT_, 256>>>(x, tmp, h1);
    gemm_bf16_kernel<<<gtF1, 128, GB_SMEM>>>(h1, wT + WT_VW1, ffn, FF_, D_, 0, 0, 1);
    gemm_bf16_kernel<<<gtD, 128, GB_SMEM>>>(ffn, wT + WT_VW2, tmp, D_, FF_, 0, 0, 0);
    add_ln_kernel<<<BT_, 256>>>(h1, tmp, outv);

    // ===== dynamic window mask =====
    scan_kernel<<<B_, 256>>>(wsum, ids, ws, we);

    // ===== layer 2 (masked) =====
    gemm_bf16_kernel<<<gtQKV, 128, GB_SMEM>>>(outv, wT + WT_LQKV, qkv, D_, D_,
                                              (long long)D_*D_, (long long)BT_*D_, 0);
    attn_masked_kernel<<<gAttn, 256, SMEM_AM>>>(qkv, ids, ctx, part);
    reduce_part_kernel<<<(B_*T_)/256, 256>>>(part, wsum);
    gemm_bf16_kernel<<<gtD, 128, GB_SMEM>>>(ctx, wT + WT_LOUT, tmp, D_, D_, 0, 0, 0);
    add_ln_kernel<<<BT_, 256>>>(outv, tmp, h1);
    gemm_bf16_kernel<<<gtF1, 128, GB_SMEM>>>(h1, wT + WT_LW1, ffn, FF_, D_, 0, 0, 1);
    gemm_bf16_kernel<<<gtD, 128, GB_SMEM>>>(ffn, wT + WT_LW2, tmp, D_, FF_, 0, 0, 0);
    add_ln_kernel<<<BT_, 256>>>(h1, tmp, outl);

    // ===== outputs =====
    wl_softmax_kernel<<<B_, 256>>>(wsum, wl);
    word_tokens_kernel<<<dim3(T_, B_), 128>>>(outl, wl, ws, we, out);
    copy_x_kernel<<<(B_*T_*D_/4)/256, 256>>>(x, out);
    winmap_kernel<<<(B_*T_*T_/4)/256, 256>>>(ids, out + (size_t)B_*2*T_*D_);
}